// round 9
// baseline (speedup 1.0000x reference)
#include <cuda_runtime.h>
#include <cuda_bf16.h>
#include <cstdint>

// ---------------- constants ----------------
namespace {
constexpr int Bb = 16;      // batch
constexpr int Cc = 256;     // channels
constexpr int Nn = 4096;    // H*W
constexpr int NH = 8;       // heads
constexpr int HD = 32;      // head dim
constexpr int AG = 49;      // agent tokens
constexpr float SCALE = 0.17677669529663689f;  // 32^-0.5
constexpr int AP = 264;                         // smem pitch (bf16), conflict-free ldmatrix
constexpr unsigned A_HALF = 128 * AP * 2;       // 67584 per A half (hi or lo)
constexpr unsigned B_HALF = 32 * AP * 2;        // 16896 per B half per stage
constexpr unsigned B_STAGE = 2 * B_HALF;        // 33792 (hi+lo)
constexpr unsigned STAG_OFF = 2 * A_HALF + 2 * B_STAGE;   // 202752
constexpr unsigned SMEM_DYN = STAG_OFF + 128 * 36 * 4;    // 221184
}

// ---------------- scratch (device globals; no allocation allowed) ----------------
__device__ float g_q[Bb * Nn * Cc];
__device__ float g_k[Bb * Nn * Cc];
__device__ float g_v[Bb * Nn * Cc];
__device__ float g_o[Bb * Nn * Cc];            // attention out (pre-dwconv, pre-proj)
__device__ float g_agent[Bb * AG * Cc];
__device__ float g_agentv[Bb * NH * AG * HD];
__device__ float g_bias1[NH * AG * Nn];        // stage-1 bias [h][a][n]
__device__ float g_bias2[NH * Nn * AG];        // stage-2 bias [h][n][a]

// bf16 hi/lo split operands for tensor-core GEMMs
__device__ __nv_bfloat16 g_xh[Bb * Nn * Cc];   // xt row-major [b][n][c]
__device__ __nv_bfloat16 g_xl[Bb * Nn * Cc];
__device__ __nv_bfloat16 g_oh[Bb * Nn * Cc];
__device__ __nv_bfloat16 g_ol[Bb * Nn * Cc];
__device__ __nv_bfloat16 g_wh[768 * Cc];       // qkv weights combined [q|k|v]
__device__ __nv_bfloat16 g_wl[768 * Cc];
__device__ __nv_bfloat16 g_pwh[Cc * Cc];       // proj weights
__device__ __nv_bfloat16 g_pwl[Cc * Cc];

// ---------------- PTX helpers (baseline sm_80+ features only) ----------------
__device__ __forceinline__ uint32_t smem_u32(const void* p) {
    uint32_t a;
    asm("{ .reg .u64 t; cvta.to.shared.u64 t, %1; cvt.u32.u64 %0, t; }" : "=r"(a) : "l"(p));
    return a;
}
__device__ __forceinline__ void ldm_x4(uint32_t* r, uint32_t addr) {
    asm volatile("ldmatrix.sync.aligned.m8n8.x4.shared.b16 {%0,%1,%2,%3}, [%4];"
                 : "=r"(r[0]), "=r"(r[1]), "=r"(r[2]), "=r"(r[3]) : "r"(addr));
}
__device__ __forceinline__ void mma_bf16(float* d, const uint32_t* a, uint32_t b0, uint32_t b1) {
    asm volatile(
        "mma.sync.aligned.m16n8k16.row.col.f32.bf16.bf16.f32 "
        "{%0,%1,%2,%3}, {%4,%5,%6,%7}, {%8,%9}, {%0,%1,%2,%3};"
        : "+f"(d[0]), "+f"(d[1]), "+f"(d[2]), "+f"(d[3])
        : "r"(a[0]), "r"(a[1]), "r"(a[2]), "r"(a[3]), "r"(b0), "r"(b1));
}
__device__ __forceinline__ void cp16(uint32_t dst, const void* src) {
    asm volatile("cp.async.ca.shared.global [%0], [%1], 16;" :: "r"(dst), "l"(src));
}
__device__ __forceinline__ void cp_commit() { asm volatile("cp.async.commit_group;" ::: "memory"); }
template <int N>
__device__ __forceinline__ void cp_wait() { asm volatile("cp.async.wait_group %0;" :: "n"(N) : "memory"); }

// ---------------- prep: bf16 hi/lo splits ----------------
__global__ void k_prep_w(const float* __restrict__ Wq, const float* __restrict__ Wkv,
                         const float* __restrict__ Wp) {
    int row = blockIdx.x, t = threadIdx.x;
    if (row < 768) {
        float v = (row < 256) ? Wq[row * 256 + t] : Wkv[(row - 256) * 256 + t];
        __nv_bfloat16 hi = __float2bfloat16(v);
        g_wh[row * 256 + t] = hi;
        g_wl[row * 256 + t] = __float2bfloat16(v - __bfloat162float(hi));
    } else {
        int r = row - 768;
        float v = Wp[r * 256 + t];
        __nv_bfloat16 hi = __float2bfloat16(v);
        g_pwh[r * 256 + t] = hi;
        g_pwl[r * 256 + t] = __float2bfloat16(v - __bfloat162float(hi));
    }
}

__global__ void k_xsplit(const float* __restrict__ x) {
    __shared__ float tile[32][33];
    int tx = threadIdx.x, ty = threadIdx.y;  // 32x8
    int n0 = blockIdx.x * 32, c0 = blockIdx.y * 32, b = blockIdx.z;
#pragma unroll
    for (int yy = 0; yy < 32; yy += 8)
        tile[ty + yy][tx] = x[((size_t)b * 256 + c0 + ty + yy) * 4096 + n0 + tx];
    __syncthreads();
#pragma unroll
    for (int yy = 0; yy < 32; yy += 8) {
        int nl = ty + yy;
        float v = tile[tx][nl];
        __nv_bfloat16 hi = __float2bfloat16(v);
        size_t o = ((size_t)b * 4096 + n0 + nl) * 256 + c0 + tx;
        g_xh[o] = hi;
        g_xl[o] = __float2bfloat16(v - __bfloat162float(hi));
    }
}

// ---------------- tensor-core GEMM: cp.async 2-stage pipelined B (32-col tiles) ----------------
// MODE 0 (JT=24): A = g_xh/g_xl, W = g_wh/g_wl -> g_q/g_k/g_v row-major [b][n][256]
// MODE 1 (JT=8):  A = g_oh/g_ol, W = g_pwh/g_pwl -> transposed out[b][j][n] + bias
template <int JT, int MODE>
__global__ __launch_bounds__(256, 1)
void k_gemm_mma(const float* __restrict__ bias, float* __restrict__ outp) {
    extern __shared__ __align__(16) char dsm[];
    __nv_bfloat16* sAh = (__nv_bfloat16*)dsm;
    __nv_bfloat16* sAl = (__nv_bfloat16*)(dsm + A_HALF);
    float* stag = (float*)(dsm + STAG_OFF);    // 128 x 36 fp32

    const int t = threadIdx.x;
    const int lane = t & 31, wid = t >> 5;
    const int wm = wid & 3, wn = wid >> 2;     // warp tile: 32(m) x 16(n)
    const int b = blockIdx.y, n0 = blockIdx.x * 128;

    const uint32_t uA = smem_u32(dsm);
    const uint32_t uB = uA + 2 * A_HALF;       // two stages of (hi|lo)

    const __nv_bfloat16* Wgh = (MODE == 0) ? g_wh : g_pwh;
    const __nv_bfloat16* Wgl = (MODE == 0) ? g_wl : g_pwl;

    // ---- prefetch B stage 0 (jt=0) ----
    {
#pragma unroll
        for (int it = 0; it < 4; it++) {
            int idx = t + it * 256;            // 1024 chunks: 32 rows x 32
            int r = idx >> 5, ch = idx & 31;
            uint32_t off = (uint32_t)((r * AP + ch * 8) * 2);
            cp16(uB + off, Wgh + (size_t)r * 256 + ch * 8);
            cp16(uB + B_HALF + off, Wgl + (size_t)r * 256 + ch * 8);
        }
        cp_commit();
    }

    // ---- load resident A tile (hi+lo) ----
    const __nv_bfloat16* Agh = (MODE == 0 ? g_xh : g_oh) + ((size_t)b * 4096 + n0) * 256;
    const __nv_bfloat16* Agl = (MODE == 0 ? g_xl : g_ol) + ((size_t)b * 4096 + n0) * 256;
#pragma unroll
    for (int it = 0; it < 16; it++) {
        int idx = t + it * 256;                // 4096 chunks of 8 bf16
        int r = idx >> 5, ch = idx & 31;
        *(uint4*)&sAh[r * AP + ch * 8] = *(const uint4*)(Agh + (size_t)r * 256 + ch * 8);
        *(uint4*)&sAl[r * AP + ch * 8] = *(const uint4*)(Agl + (size_t)r * 256 + ch * 8);
    }

    // ---- per-thread ldmatrix byte offsets ----
    const int q8 = lane >> 3, r8 = lane & 7;
    uint32_t aoff[2], boff;
#pragma unroll
    for (int mt = 0; mt < 2; mt++) {
        int row = wm * 32 + mt * 16 + (q8 & 1) * 8 + r8;
        aoff[mt] = (uint32_t)((row * AP + (q8 >> 1) * 8) * 2);
    }
    {
        int nrow = wn * 16 + (q8 >> 1) * 8 + r8;   // < 32
        boff = (uint32_t)((nrow * AP + (q8 & 1) * 8) * 2);
    }
    const uint32_t uAh = uA, uAl = uA + A_HALF;

    for (int jt = 0; jt < JT; jt++) {
        // ---- prefetch B for jt+1 into alternate stage ----
        if (jt + 1 < JT) {
            uint32_t dst = uB + ((jt + 1) & 1) * B_STAGE;
            const __nv_bfloat16* wh = Wgh + (size_t)(jt + 1) * 32 * 256;
            const __nv_bfloat16* wl = Wgl + (size_t)(jt + 1) * 32 * 256;
#pragma unroll
            for (int it = 0; it < 4; it++) {
                int idx = t + it * 256;
                int r = idx >> 5, ch = idx & 31;
                uint32_t off = (uint32_t)((r * AP + ch * 8) * 2);
                cp16(dst + off, wh + (size_t)r * 256 + ch * 8);
                cp16(dst + B_HALF + off, wl + (size_t)r * 256 + ch * 8);
            }
            cp_commit();
            cp_wait<1>();    // current stage (jt) complete
        } else {
            cp_wait<0>();
        }
        __syncthreads();

        const uint32_t sbh = uB + (jt & 1) * B_STAGE;
        const uint32_t sbl = sbh + B_HALF;

        float acc[2][2][4];
#pragma unroll
        for (int mt = 0; mt < 2; mt++)
#pragma unroll
            for (int nt = 0; nt < 2; nt++)
#pragma unroll
                for (int e = 0; e < 4; e++) acc[mt][nt][e] = 0.f;

#pragma unroll 4
        for (int ks = 0; ks < 16; ks++) {
            uint32_t ko = (uint32_t)(ks * 32);   // 16 k-elems = 32 bytes
            uint32_t A_h[2][4], A_l[2][4], B_h[4], B_l[4];
            ldm_x4(A_h[0], uAh + aoff[0] + ko);
            ldm_x4(A_h[1], uAh + aoff[1] + ko);
            ldm_x4(A_l[0], uAl + aoff[0] + ko);
            ldm_x4(A_l[1], uAl + aoff[1] + ko);
            ldm_x4(B_h, sbh + boff + ko);
            ldm_x4(B_l, sbl + boff + ko);
#pragma unroll
            for (int mt = 0; mt < 2; mt++) {
#pragma unroll
                for (int nt = 0; nt < 2; nt++) {
                    int hf = nt * 2;
                    mma_bf16(acc[mt][nt], A_h[mt], B_h[hf], B_h[hf + 1]);
                    mma_bf16(acc[mt][nt], A_h[mt], B_l[hf], B_l[hf + 1]);
                    mma_bf16(acc[mt][nt], A_l[mt], B_h[hf], B_h[hf + 1]);
                }
            }
        }

        // ---- stage fragments to smem [128][36] ----
        {
            int r0 = lane >> 2, c0 = (lane & 3) * 2;
#pragma unroll
            for (int mt = 0; mt < 2; mt++) {
#pragma unroll
                for (int nt = 0; nt < 2; nt++) {
                    int row = wm * 32 + mt * 16 + r0;
                    int col = wn * 16 + nt * 8 + c0;
                    stag[row * 36 + col]           = acc[mt][nt][0];
                    stag[row * 36 + col + 1]       = acc[mt][nt][1];
                    stag[(row + 8) * 36 + col]     = acc[mt][nt][2];
                    stag[(row + 8) * 36 + col + 1] = acc[mt][nt][3];
                }
            }
        }
        __syncthreads();

        // ---- coalesced stores ----
        if (MODE == 0) {
            float* dst = (jt < 8) ? g_q : (jt < 16) ? g_k : g_v;
            int jl = (jt & 7) * 32;
#pragma unroll
            for (int it = 0; it < 4; it++) {
                int idx = t + it * 256;          // 1024 float4
                int m = idx >> 3, j4 = (idx & 7) * 4;
                *(float4*)&dst[((size_t)b * 4096 + n0 + m) * 256 + jl + j4] =
                    *(float4*)&stag[m * 36 + j4];
            }
        } else {
            int m = t & 127, j0 = t >> 7;
#pragma unroll 8
            for (int j = j0; j < 32; j += 2) {
                float v = stag[m * 36 + j] + bias[jt * 32 + j];
                outp[((size_t)b * 256 + jt * 32 + j) * 4096 + n0 + m] = v;
            }
        }
        __syncthreads();   // staging reused next iteration
    }
}

// ---------------- bilinear coeffs for 7 -> 64 resize ----------------
__device__ __forceinline__ void lin7(int i, int& j0, int& j1, float& w) {
    float c = (i + 0.5f) * (7.0f / 64.0f) - 0.5f;
    float f = floorf(c);
    w = c - f;
    int j = (int)f;
    j0 = max(0, min(6, j));
    j1 = max(0, min(6, j + 1));
}

__device__ __forceinline__ float bil7(const float* img, int y0, int y1, float wy,
                                      int x0, int x1, float wx) {
    float v0 = img[y0 * 7 + x0] * (1.f - wx) + img[y0 * 7 + x1] * wx;
    float v1 = img[y1 * 7 + x0] * (1.f - wx) + img[y1 * 7 + x1] * wx;
    return v0 * (1.f - wy) + v1 * wy;
}

// ---------------- K1: position biases ----------------
__global__ void k_bias(const float* __restrict__ an, const float* __restrict__ na,
                       const float* __restrict__ ahb, const float* __restrict__ awb,
                       const float* __restrict__ hab, const float* __restrict__ wab) {
    int n = blockIdx.x * 256 + threadIdx.x;
    int a = blockIdx.y, h = blockIdx.z;
    int y = n >> 6, x = n & 63;
    int y0, y1, x0, x1; float wy, wx;
    lin7(y, y0, y1, wy);
    lin7(x, x0, x1, wx);
    const float* i1 = an + (h * AG + a) * 49;
    const float* i2 = na + (h * AG + a) * 49;
    float v1 = bil7(i1, y0, y1, wy, x0, x1, wx);
    float v2 = bil7(i2, y0, y1, wy, x0, x1, wx);
    g_bias1[(h * AG + a) * Nn + n] = v1 + ahb[(h * AG + a) * 64 + y] + awb[(h * AG + a) * 64 + x];
    g_bias2[(h * Nn + n) * AG + a] = v2 + hab[(h * 64 + y) * AG + a] + wab[(h * 64 + x) * AG + a];
}

// ---------------- K3: adaptive avg pool q -> agent ----------------
__global__ void k_pool() {
    int c = threadIdx.x;
    int a = blockIdx.x;
    int b = blockIdx.y;
    int p = a / 7, q = a % 7;
    int ys = (p * 64) / 7, ye = ((p + 1) * 64 + 6) / 7;
    int xs = (q * 64) / 7, xe = ((q + 1) * 64 + 6) / 7;
    float s = 0.f;
    for (int y = ys; y < ye; y++)
        for (int x = xs; x < xe; x++)
            s += g_q[(b * Nn + y * 64 + x) * Cc + c];
    g_agent[(b * AG + a) * Cc + c] = s * (1.0f / ((ye - ys) * (xe - xs)));
}

// ---------------- K4: fused stage-1 (flash: scores -> online softmax -> @V) ----------------
// One block per (h, b). agent_v[a][d] = softmax_n(ah.k + bias1) @ v
// k_s: flat pitch-32 with XOR chunk swizzle (16B-aligned, conflict-free LDS.128).
// v_s: pitch-33, scalar stores/loads (conflict-free).
__global__ __launch_bounds__(256) void k_fs1() {
    __shared__ __align__(16) float ah_s[AG * HD];
    __shared__ __align__(16) float k_s[64 * 32];
    __shared__ float v_s[64][33];
    __shared__ float s_s[AG][65];
    __shared__ float m_s[AG], r_s[AG], l_s[AG];

    int h = blockIdx.x, b = blockIdx.y;
    int bh = b * NH + h;
    int t = threadIdx.x;
    int ta = t >> 5, td = t & 31;   // warp ta owns agent rows {ta, ta+8, ..}, lane owns dim td

    for (int idx = t; idx < AG * HD; idx += 256)
        ah_s[idx] = g_agent[(b * AG + (idx >> 5)) * Cc + h * HD + (idx & 31)] * SCALE;
    if (t < AG) { m_s[t] = -1e30f; l_s[t] = 0.f; }
    __syncthreads();

    float acc[7];
#pragma unroll
    for (int i = 0; i < 7; i++) acc[i] = 0.f;

    const float* kb = g_k + (size_t)b * Nn * Cc + h * HD;
    const float* vb = g_v + (size_t)b * Nn * Cc + h * HD;
    const float* bias = g_bias1 + (size_t)h * AG * Nn;

    for (int n0 = 0; n0 < Nn; n0 += 64) {
#pragma unroll
        for (int i = 0; i < 2; i++) {
            int idx = t + i * 256;             // 512 float4 each
            int r = idx >> 3, cd = idx & 7;    // row r, chunk cd (4 floats)
            float4 kk = *(const float4*)(kb + (size_t)(n0 + r) * Cc + cd * 4);
            float4 vv = *(const float4*)(vb + (size_t)(n0 + r) * Cc + cd * 4);
            *(float4*)&k_s[r * 32 + ((cd ^ (r & 7)) << 2)] = kk;
            v_s[r][cd * 4 + 0] = vv.x;
            v_s[r][cd * 4 + 1] = vv.y;
            v_s[r][cd * 4 + 2] = vv.z;
            v_s[r][cd * 4 + 3] = vv.w;
        }
        __syncthreads();
        // scores 49x64
        for (int idx = t; idx < AG * 64; idx += 256) {
            int a = idx >> 6, n = idx & 63;
            int sw = n & 7;
            const float* ap = &ah_s[a * HD];
            const float* kp = &k_s[n * 32];
            float s = 0.f;
#pragma unroll
            for (int i = 0; i < 8; i++) {
                float4 w = *(const float4*)&ap[i * 4];
                float4 kk = *(const float4*)&kp[(i ^ sw) << 2];
                s += w.x * kk.x + w.y * kk.y + w.z * kk.z + w.w * kk.w;
            }
            s_s[a][n] = s + bias[a * Nn + n0 + n];
        }
        __syncthreads();
        if (t < AG) {
            float mo = m_s[t], mx = mo;
#pragma unroll 8
            for (int n = 0; n < 64; n++) mx = fmaxf(mx, s_s[t][n]);
            float r = __expf(mo - mx);
            float sum = 0.f;
#pragma unroll 8
            for (int n = 0; n < 64; n++) {
                float e = __expf(s_s[t][n] - mx);
                s_s[t][n] = e;
                sum += e;
            }
            l_s[t] = l_s[t] * r + sum;
            m_s[t] = mx;
            r_s[t] = r;
        }
        __syncthreads();
        // accumulate P@V: lane td reads v row once per n; scores broadcast per warp
        {
            float rs[7];
#pragma unroll
            for (int i = 0; i < 7; i++) {
                int a = ta + i * 8;
                rs[i] = (a < AG) ? r_s[a] : 0.f;
                acc[i] *= rs[i];
            }
#pragma unroll 4
            for (int n = 0; n < 64; n++) {
                float vv = v_s[n][td];
#pragma unroll
                for (int i = 0; i < 7; i++) {
                    int a = ta + i * 8;
                    if (a < AG) acc[i] += s_s[a][n] * vv;
                }
            }
        }
        __syncthreads();
    }
#pragma unroll
    for (int i = 0; i < 7; i++) {
        int a = ta + i * 8;
        if (a < AG)
            g_agentv[(bh * AG + a) * HD + td] = acc[i] / l_s[a];
    }
}

// ---------------- K7: fused stage-2 ----------------
__global__ __launch_bounds__(256) void k_st2() {
    __shared__ __align__(16) float ah_s[AG * HD];
    __shared__ __align__(16) float av_s[AG * HD];
    __shared__ __align__(16) float p_sm[AG][128];
    __shared__ float li_sm[128];
    int t = threadIdx.x;
    int n0 = blockIdx.x * 128, h = blockIdx.y, b = blockIdx.z;
    for (int idx = t; idx < AG * HD; idx += 256) {
        int a = idx >> 5, d = idx & 31;
        ah_s[idx] = g_agent[(b * AG + a) * Cc + h * HD + d];
        av_s[idx] = g_agentv[((b * NH + h) * AG + a) * HD + d];
    }
    __syncthreads();
    {
        int n_l = t & 127, a0 = t >> 7;
        float4 q4[8];
        const float4* qp = (const float4*)(g_q + ((size_t)b * Nn + n0 + n_l) * Cc + h * HD);
#pragma unroll
        for (int i = 0; i < 8; i++) q4[i] = qp[i];
        const float* b2 = g_bias2 + ((size_t)h * Nn + n0 + n_l) * AG;
        for (int a = a0; a < AG; a += 2) {
            float s = 0.f;
#pragma unroll
            for (int i = 0; i < 8; i++) {
                float4 w = *(const float4*)&ah_s[a * HD + i * 4];
                s += q4[i].x * w.x + q4[i].y * w.y + q4[i].z * w.z + q4[i].w * w.w;
            }
            p_sm[a][n_l] = s * SCALE + b2[a];
        }
    }
    __syncthreads();
    if (t < 128) {
        float mx = -1e30f;
        for (int a = 0; a < AG; a++) mx = fmaxf(mx, p_sm[a][t]);
        float sm = 0.f;
        for (int a = 0; a < AG; a++) {
            float e = __expf(p_sm[a][t] - mx);
            p_sm[a][t] = e;
            sm += e;
        }
        li_sm[t] = 1.0f / sm;
    }
    __syncthreads();
    {
        int d = t & 31, grp = t >> 5;
        int nb = grp * 16;
        float acc[16];
#pragma unroll
        for (int i = 0; i < 16; i++) acc[i] = 0.f;
        for (int a = 0; a < AG; a++) {
            float av = av_s[a * HD + d];
#pragma unroll
            for (int i4 = 0; i4 < 4; i4++) {
                float4 p4 = *(const float4*)&p_sm[a][nb + i4 * 4];
                acc[i4 * 4 + 0] += p4.x * av;
                acc[i4 * 4 + 1] += p4.y * av;
                acc[i4 * 4 + 2] += p4.z * av;
                acc[i4 * 4 + 3] += p4.w * av;
            }
        }
#pragma unroll
        for (int i = 0; i < 16; i++) {
            int n = nb + i;
            g_o[((size_t)b * Nn + n0 + n) * Cc + h * HD + d] = acc[i] * li_sm[n];
        }
    }
}

// ---------------- K8: depthwise 3x3 conv + bf16 hi/lo split of (o + dw) ----------------
__global__ void k_dw(const float* __restrict__ Wd, const float* __restrict__ bd) {
    int c = threadIdx.x;
    int n = blockIdx.x, b = blockIdx.y;
    int y = n >> 6, x = n & 63;
    float s = bd[c];
#pragma unroll
    for (int dy = -1; dy <= 1; dy++) {
        int yy = y + dy;
        if (yy < 0 || yy > 63) continue;
#pragma unroll
        for (int dx = -1; dx <= 1; dx++) {
            int xx = x + dx;
            if (xx < 0 || xx > 63) continue;
            s += g_v[((size_t)b * Nn + yy * 64 + xx) * Cc + c] * Wd[c * 9 + (dy + 1) * 3 + (dx + 1)];
        }
    }
    size_t idx = ((size_t)b * Nn + n) * Cc + c;
    float v = g_o[idx] + s;
    __nv_bfloat16 hi = __float2bfloat16(v);
    g_oh[idx] = hi;
    g_ol[idx] = __float2bfloat16(v - __bfloat162float(hi));
}

// ---------------- launch ----------------
extern "C" void kernel_launch(void* const* d_in, const int* in_sizes, int n_in,
                              void* d_out, int out_size) {
    const float* x     = (const float*)d_in[0];
    const float* Wq    = (const float*)d_in[1];
    const float* Wkv   = (const float*)d_in[2];
    const float* Wproj = (const float*)d_in[3];
    const float* bproj = (const float*)d_in[4];
    const float* Wdwc  = (const float*)d_in[5];
    const float* bdwc  = (const float*)d_in[6];
    const float* an    = (const float*)d_in[7];
    const float* na    = (const float*)d_in[8];
    const float* ahb   = (const float*)d_in[9];
    const float* awb   = (const float*)d_in[10];
    const float* hab   = (const float*)d_in[11];
    const float* wab   = (const float*)d_in[12];
    float* out = (float*)d_out;

    cudaFuncSetAttribute(k_gemm_mma<24, 0>, cudaFuncAttributeMaxDynamicSharedMemorySize, SMEM_DYN);
    cudaFuncSetAttribute(k_gemm_mma<8, 1>,  cudaFuncAttributeMaxDynamicSharedMemorySize, SMEM_DYN);

    k_bias   <<<dim3(Nn / 256, AG, NH), 256>>>(an, na, ahb, awb, hab, wab);
    k_prep_w <<<1024, 256>>>(Wq, Wkv, Wproj);
    k_xsplit <<<dim3(128, 8, Bb), dim3(32, 8)>>>(x);
    k_gemm_mma<24, 0><<<dim3(32, Bb), 256, SMEM_DYN>>>(nullptr, nullptr);
    k_pool   <<<dim3(AG, Bb), 256>>>();
    k_fs1    <<<dim3(NH, Bb), 256>>>();
    k_st2    <<<dim3(Nn / 128, NH, Bb), 256>>>();
    k_dw     <<<dim3(Nn, Bb), 256>>>(Wdwc, bdwc);
    k_gemm_mma<8, 1><<<dim3(32, Bb), 256, SMEM_DYN>>>(bproj, out);
}

// round 10
// speedup vs baseline: 1.4354x; 1.4354x over previous
#include <cuda_runtime.h>
#include <cuda_bf16.h>
#include <cstdint>

// ---------------- constants ----------------
namespace {
constexpr int Bb = 16;      // batch
constexpr int Cc = 256;     // channels
constexpr int Nn = 4096;    // H*W
constexpr int NH = 8;       // heads
constexpr int HD = 32;      // head dim
constexpr int AG = 49;      // agent tokens
constexpr int NSPLIT = 8;   // stage-1 n-splits
constexpr float SCALE = 0.17677669529663689f;  // 32^-0.5

// GEMM smem layout (bytes), per stage: A(hi|lo) 128x32k pitch40, B(hi|lo) 64x32k pitch40
constexpr int KP = 40;                          // k-pitch in bf16 (80B rows: conflict-free ldmatrix)
constexpr unsigned SA_SZ = 128 * KP * 2;        // 10240
constexpr unsigned SB_SZ = 64 * KP * 2;         // 5120
constexpr unsigned STAGE_SZ = 2 * SA_SZ + 2 * SB_SZ;  // 30720
constexpr unsigned STAG_OFF = 2 * STAGE_SZ;     // 61440
constexpr unsigned SMEM_DYN = STAG_OFF + 128 * 68 * 4; // 96256
}

// ---------------- scratch (device globals; no allocation allowed) ----------------
__device__ float g_q[Bb * Nn * Cc];
__device__ float g_k[Bb * Nn * Cc];
__device__ float g_v[Bb * Nn * Cc];
__device__ float g_o[Bb * Nn * Cc];            // attention out (pre-dwconv, pre-proj)
__device__ float g_agent[Bb * AG * Cc];
__device__ float g_agentv[Bb * NH * AG * HD];
__device__ float g_bias1[NH * AG * Nn];        // stage-1 bias [h][a][n]
__device__ float g_bias2[NH * Nn * AG];        // stage-2 bias [h][n][a]
__device__ float g_pacc[Bb * NH * NSPLIT * AG * HD];  // stage-1 partial acc
__device__ float g_pm[Bb * NH * NSPLIT * AG];
__device__ float g_pl[Bb * NH * NSPLIT * AG];

// bf16 hi/lo split operands for tensor-core GEMMs
__device__ __nv_bfloat16 g_xh[Bb * Nn * Cc];   // xt row-major [b][n][c]
__device__ __nv_bfloat16 g_xl[Bb * Nn * Cc];
__device__ __nv_bfloat16 g_oh[Bb * Nn * Cc];
__device__ __nv_bfloat16 g_ol[Bb * Nn * Cc];
__device__ __nv_bfloat16 g_wh[768 * Cc];       // qkv weights combined [q|k|v]
__device__ __nv_bfloat16 g_wl[768 * Cc];
__device__ __nv_bfloat16 g_pwh[Cc * Cc];       // proj weights
__device__ __nv_bfloat16 g_pwl[Cc * Cc];

// ---------------- PTX helpers (baseline sm_80+ features only) ----------------
__device__ __forceinline__ uint32_t smem_u32(const void* p) {
    uint32_t a;
    asm("{ .reg .u64 t; cvta.to.shared.u64 t, %1; cvt.u32.u64 %0, t; }" : "=r"(a) : "l"(p));
    return a;
}
__device__ __forceinline__ void ldm_x4(uint32_t* r, uint32_t addr) {
    asm volatile("ldmatrix.sync.aligned.m8n8.x4.shared.b16 {%0,%1,%2,%3}, [%4];"
                 : "=r"(r[0]), "=r"(r[1]), "=r"(r[2]), "=r"(r[3]) : "r"(addr));
}
__device__ __forceinline__ void mma_bf16(float* d, const uint32_t* a, uint32_t b0, uint32_t b1) {
    asm volatile(
        "mma.sync.aligned.m16n8k16.row.col.f32.bf16.bf16.f32 "
        "{%0,%1,%2,%3}, {%4,%5,%6,%7}, {%8,%9}, {%0,%1,%2,%3};"
        : "+f"(d[0]), "+f"(d[1]), "+f"(d[2]), "+f"(d[3])
        : "r"(a[0]), "r"(a[1]), "r"(a[2]), "r"(a[3]), "r"(b0), "r"(b1));
}
__device__ __forceinline__ void cp16(uint32_t dst, const void* src) {
    asm volatile("cp.async.ca.shared.global [%0], [%1], 16;" :: "r"(dst), "l"(src));
}
__device__ __forceinline__ void cp_commit() { asm volatile("cp.async.commit_group;" ::: "memory"); }
template <int N>
__device__ __forceinline__ void cp_wait() { asm volatile("cp.async.wait_group %0;" :: "n"(N) : "memory"); }

// ---------------- prep: bf16 hi/lo splits ----------------
__global__ void k_prep_w(const float* __restrict__ Wq, const float* __restrict__ Wkv,
                         const float* __restrict__ Wp) {
    int row = blockIdx.x, t = threadIdx.x;
    if (row < 768) {
        float v = (row < 256) ? Wq[row * 256 + t] : Wkv[(row - 256) * 256 + t];
        __nv_bfloat16 hi = __float2bfloat16(v);
        g_wh[row * 256 + t] = hi;
        g_wl[row * 256 + t] = __float2bfloat16(v - __bfloat162float(hi));
    } else {
        int r = row - 768;
        float v = Wp[r * 256 + t];
        __nv_bfloat16 hi = __float2bfloat16(v);
        g_pwh[r * 256 + t] = hi;
        g_pwl[r * 256 + t] = __float2bfloat16(v - __bfloat162float(hi));
    }
}

__global__ void k_xsplit(const float* __restrict__ x) {
    __shared__ float tile[32][33];
    int tx = threadIdx.x, ty = threadIdx.y;  // 32x8
    int n0 = blockIdx.x * 32, c0 = blockIdx.y * 32, b = blockIdx.z;
#pragma unroll
    for (int yy = 0; yy < 32; yy += 8)
        tile[ty + yy][tx] = x[((size_t)b * 256 + c0 + ty + yy) * 4096 + n0 + tx];
    __syncthreads();
#pragma unroll
    for (int yy = 0; yy < 32; yy += 8) {
        int nl = ty + yy;
        float v = tile[tx][nl];
        __nv_bfloat16 hi = __float2bfloat16(v);
        size_t o = ((size_t)b * 4096 + n0 + nl) * 256 + c0 + tx;
        g_xh[o] = hi;
        g_xl[o] = __float2bfloat16(v - __bfloat162float(hi));
    }
}

// ---------------- tensor-core GEMM: streaming double-buffered 128x64 tiles ----------------
// C[128 n-rows][64 j] = A[128][256] @ W[j0+0..63][256]^T
// MODE 0: A = g_xh/g_xl, W = g_wh/g_wl -> g_q/g_k/g_v row-major [b][n][256]
// MODE 1: A = g_oh/g_ol, W = g_pwh/g_pwl -> transposed out[b][j][n] + bias
template <int MODE>
__global__ __launch_bounds__(256, 2)
void k_gemm_mma(const float* __restrict__ bias, float* __restrict__ outp) {
    extern __shared__ __align__(16) char dsm[];
    float* stag = (float*)(dsm + STAG_OFF);    // 128 x 68 fp32

    const int t = threadIdx.x;
    const int lane = t & 31, wid = t >> 5;
    const int wm = wid & 3, wn = wid >> 2;     // warp tile: 32(m) x 32(n)
    const int b = blockIdx.z;
    const int n0 = blockIdx.x * 128;
    const int jt = blockIdx.y, j0 = jt * 64;

    const __nv_bfloat16* Agh = (MODE == 0 ? g_xh : g_oh) + ((size_t)b * 4096 + n0) * 256;
    const __nv_bfloat16* Agl = (MODE == 0 ? g_xl : g_ol) + ((size_t)b * 4096 + n0) * 256;
    const __nv_bfloat16* Wgh = ((MODE == 0) ? g_wh : g_pwh) + (size_t)j0 * 256;
    const __nv_bfloat16* Wgl = ((MODE == 0) ? g_wl : g_pwl) + (size_t)j0 * 256;

    const uint32_t uS = smem_u32(dsm);

    // stage loader: A 512 chunks/half (2 iters), B 256 chunks/half (1 iter)
    auto load_stage = [&](int st, int kt) {
        uint32_t base = uS + st * STAGE_SZ;
        int k0 = kt * 32;
#pragma unroll
        for (int it = 0; it < 2; it++) {
            int idx = t + it * 256;            // 512: r=idx>>2, ch=idx&3
            int r = idx >> 2, ch = idx & 3;
            uint32_t off = (uint32_t)((r * KP + ch * 8) * 2);
            const size_t g = (size_t)r * 256 + k0 + ch * 8;
            cp16(base + off, Agh + g);
            cp16(base + SA_SZ + off, Agl + g);
        }
        {
            int r = t >> 2, ch = t & 3;        // 256: r 0..63
            uint32_t off = (uint32_t)((r * KP + ch * 8) * 2);
            const size_t g = (size_t)r * 256 + k0 + ch * 8;
            cp16(base + 2 * SA_SZ + off, Wgh + g);
            cp16(base + 2 * SA_SZ + SB_SZ + off, Wgl + g);
        }
    };

    // per-thread ldmatrix byte offsets (within stage)
    const int q8 = lane >> 3, r8 = lane & 7;
    uint32_t aoff[2], boff[2];
#pragma unroll
    for (int mt = 0; mt < 2; mt++) {
        int row = wm * 32 + mt * 16 + (q8 & 1) * 8 + r8;
        aoff[mt] = (uint32_t)((row * KP + (q8 >> 1) * 8) * 2);
    }
#pragma unroll
    for (int p = 0; p < 2; p++) {
        int nrow = wn * 32 + p * 16 + (q8 >> 1) * 8 + r8;
        boff[p] = (uint32_t)((nrow * KP + (q8 & 1) * 8) * 2);
    }

    float acc[2][4][4];
#pragma unroll
    for (int mt = 0; mt < 2; mt++)
#pragma unroll
        for (int nt = 0; nt < 4; nt++)
#pragma unroll
            for (int e = 0; e < 4; e++) acc[mt][nt][e] = 0.f;

    load_stage(0, 0);
    cp_commit();

    for (int kt = 0; kt < 8; kt++) {
        cp_wait<0>();
        __syncthreads();
        if (kt < 7) {
            load_stage((kt + 1) & 1, kt + 1);
            cp_commit();
        }
        const uint32_t base = uS + (kt & 1) * STAGE_SZ;
        const uint32_t uAh = base, uAl = base + SA_SZ;
        const uint32_t uBh = base + 2 * SA_SZ, uBl = uBh + SB_SZ;
#pragma unroll
        for (int kh = 0; kh < 2; kh++) {
            uint32_t ko = (uint32_t)(kh * 32);   // 16 k-elems = 32 bytes
            uint32_t A_h[2][4], A_l[2][4], B_h[2][4], B_l[2][4];
            ldm_x4(A_h[0], uAh + aoff[0] + ko);
            ldm_x4(A_h[1], uAh + aoff[1] + ko);
            ldm_x4(A_l[0], uAl + aoff[0] + ko);
            ldm_x4(A_l[1], uAl + aoff[1] + ko);
            ldm_x4(B_h[0], uBh + boff[0] + ko);
            ldm_x4(B_h[1], uBh + boff[1] + ko);
            ldm_x4(B_l[0], uBl + boff[0] + ko);
            ldm_x4(B_l[1], uBl + boff[1] + ko);
#pragma unroll
            for (int mt = 0; mt < 2; mt++) {
#pragma unroll
                for (int nt = 0; nt < 4; nt++) {
                    int p = nt >> 1, hf = (nt & 1) * 2;
                    mma_bf16(acc[mt][nt], A_h[mt], B_h[p][hf], B_h[p][hf + 1]);
                    mma_bf16(acc[mt][nt], A_h[mt], B_l[p][hf], B_l[p][hf + 1]);
                    mma_bf16(acc[mt][nt], A_l[mt], B_h[p][hf], B_h[p][hf + 1]);
                }
            }
        }
        __syncthreads();
    }

    // ---- stage fragments to smem [128][68] ----
    {
        int r0 = lane >> 2, c0 = (lane & 3) * 2;
#pragma unroll
        for (int mt = 0; mt < 2; mt++) {
#pragma unroll
            for (int nt = 0; nt < 4; nt++) {
                int row = wm * 32 + mt * 16 + r0;
                int col = wn * 32 + nt * 8 + c0;
                stag[row * 68 + col]           = acc[mt][nt][0];
                stag[row * 68 + col + 1]       = acc[mt][nt][1];
                stag[(row + 8) * 68 + col]     = acc[mt][nt][2];
                stag[(row + 8) * 68 + col + 1] = acc[mt][nt][3];
            }
        }
    }
    __syncthreads();

    // ---- coalesced stores ----
    if (MODE == 0) {
        float* dst = (jt < 4) ? g_q : (jt < 8) ? g_k : g_v;
        int jl = (jt & 3) * 64;
#pragma unroll
        for (int it = 0; it < 8; it++) {
            int idx = t + it * 256;          // 2048 float4
            int m = idx >> 4, j4 = (idx & 15) * 4;
            *(float4*)&dst[((size_t)b * 4096 + n0 + m) * 256 + jl + j4] =
                *(float4*)&stag[m * 68 + j4];
        }
    } else {
        int m = t & 127, js = t >> 7;
#pragma unroll 8
        for (int j = js; j < 64; j += 2) {
            float v = stag[m * 68 + j] + bias[j0 + j];
            outp[((size_t)b * 256 + j0 + j) * 4096 + n0 + m] = v;
        }
    }
}

// ---------------- bilinear coeffs for 7 -> 64 resize ----------------
__device__ __forceinline__ void lin7(int i, int& j0, int& j1, float& w) {
    float c = (i + 0.5f) * (7.0f / 64.0f) - 0.5f;
    float f = floorf(c);
    w = c - f;
    int j = (int)f;
    j0 = max(0, min(6, j));
    j1 = max(0, min(6, j + 1));
}

__device__ __forceinline__ float bil7(const float* img, int y0, int y1, float wy,
                                      int x0, int x1, float wx) {
    float v0 = img[y0 * 7 + x0] * (1.f - wx) + img[y0 * 7 + x1] * wx;
    float v1 = img[y1 * 7 + x0] * (1.f - wx) + img[y1 * 7 + x1] * wx;
    return v0 * (1.f - wy) + v1 * wy;
}

// ---------------- K1: position biases ----------------
__global__ void k_bias(const float* __restrict__ an, const float* __restrict__ na,
                       const float* __restrict__ ahb, const float* __restrict__ awb,
                       const float* __restrict__ hab, const float* __restrict__ wab) {
    int n = blockIdx.x * 256 + threadIdx.x;
    int a = blockIdx.y, h = blockIdx.z;
    int y = n >> 6, x = n & 63;
    int y0, y1, x0, x1; float wy, wx;
    lin7(y, y0, y1, wy);
    lin7(x, x0, x1, wx);
    const float* i1 = an + (h * AG + a) * 49;
    const float* i2 = na + (h * AG + a) * 49;
    float v1 = bil7(i1, y0, y1, wy, x0, x1, wx);
    float v2 = bil7(i2, y0, y1, wy, x0, x1, wx);
    g_bias1[(h * AG + a) * Nn + n] = v1 + ahb[(h * AG + a) * 64 + y] + awb[(h * AG + a) * 64 + x];
    g_bias2[(h * Nn + n) * AG + a] = v2 + hab[(h * 64 + y) * AG + a] + wab[(h * 64 + x) * AG + a];
}

// ---------------- K3: adaptive avg pool q -> agent ----------------
__global__ void k_pool() {
    int c = threadIdx.x;
    int a = blockIdx.x;
    int b = blockIdx.y;
    int p = a / 7, q = a % 7;
    int ys = (p * 64) / 7, ye = ((p + 1) * 64 + 6) / 7;
    int xs = (q * 64) / 7, xe = ((q + 1) * 64 + 6) / 7;
    float s = 0.f;
    for (int y = ys; y < ye; y++)
        for (int x = xs; x < xe; x++)
            s += g_q[(b * Nn + y * 64 + x) * Cc + c];
    g_agent[(b * AG + a) * Cc + c] = s * (1.0f / ((ye - ys) * (xe - xs)));
}

// ---------------- K4: stage-1 flash with n-split (partials) ----------------
// grid (NSPLIT, NH, Bb); each CTA covers 512 n. Writes unnormalized acc + (m, l).
__global__ __launch_bounds__(256) void k_fs1() {
    __shared__ __align__(16) float ah_s[AG * HD];
    __shared__ __align__(16) float k_s[64 * 32];
    __shared__ float v_s[64][33];
    __shared__ float s_s[AG][65];
    __shared__ float m_s[AG], r_s[AG], l_s[AG];

    int sp = blockIdx.x, h = blockIdx.y, b = blockIdx.z;
    int bh = b * NH + h;
    int t = threadIdx.x;
    int ta = t >> 5, td = t & 31;   // warp ta owns agent rows {ta, ta+8, ..}

    for (int idx = t; idx < AG * HD; idx += 256)
        ah_s[idx] = g_agent[(b * AG + (idx >> 5)) * Cc + h * HD + (idx & 31)] * SCALE;
    if (t < AG) { m_s[t] = -1e30f; l_s[t] = 0.f; }
    __syncthreads();

    float acc[7];
#pragma unroll
    for (int i = 0; i < 7; i++) acc[i] = 0.f;

    const float* kb = g_k + (size_t)b * Nn * Cc + h * HD;
    const float* vb = g_v + (size_t)b * Nn * Cc + h * HD;
    const float* bias = g_bias1 + (size_t)h * AG * Nn;

    for (int tile = 0; tile < 8; tile++) {
        int n0 = sp * 512 + tile * 64;
#pragma unroll
        for (int i = 0; i < 2; i++) {
            int idx = t + i * 256;             // 512 float4 each
            int r = idx >> 3, cd = idx & 7;
            float4 kk = *(const float4*)(kb + (size_t)(n0 + r) * Cc + cd * 4);
            float4 vv = *(const float4*)(vb + (size_t)(n0 + r) * Cc + cd * 4);
            *(float4*)&k_s[r * 32 + ((cd ^ (r & 7)) << 2)] = kk;
            v_s[r][cd * 4 + 0] = vv.x;
            v_s[r][cd * 4 + 1] = vv.y;
            v_s[r][cd * 4 + 2] = vv.z;
            v_s[r][cd * 4 + 3] = vv.w;
        }
        __syncthreads();
        // scores 49x64
        for (int idx = t; idx < AG * 64; idx += 256) {
            int a = idx >> 6, n = idx & 63;
            int sw = n & 7;
            const float* ap = &ah_s[a * HD];
            const float* kp = &k_s[n * 32];
            float s = 0.f;
#pragma unroll
            for (int i = 0; i < 8; i++) {
                float4 w = *(const float4*)&ap[i * 4];
                float4 kk = *(const float4*)&kp[(i ^ sw) << 2];
                s += w.x * kk.x + w.y * kk.y + w.z * kk.z + w.w * kk.w;
            }
            s_s[a][n] = s + bias[a * Nn + n0 + n];
        }
        __syncthreads();
        // warp-parallel online softmax update: warp ta owns rows ta+8i
#pragma unroll
        for (int i = 0; i < 7; i++) {
            int a = ta + i * 8;
            if (a < AG) {
                float s0 = s_s[a][td], s1 = s_s[a][td + 32];
                float mx = fmaxf(s0, s1);
#pragma unroll
                for (int off = 16; off > 0; off >>= 1)
                    mx = fmaxf(mx, __shfl_xor_sync(0xFFFFFFFFu, mx, off));
                float mnew = fmaxf(m_s[a], mx);
                float e0 = __expf(s0 - mnew), e1 = __expf(s1 - mnew);
                s_s[a][td] = e0;
                s_s[a][td + 32] = e1;
                float sum = e0 + e1;
#pragma unroll
                for (int off = 16; off > 0; off >>= 1)
                    sum += __shfl_xor_sync(0xFFFFFFFFu, sum, off);
                if (td == 0) {
                    float r = __expf(m_s[a] - mnew);
                    r_s[a] = r;
                    l_s[a] = l_s[a] * r + sum;
                    m_s[a] = mnew;
                }
            }
        }
        __syncthreads();
        // accumulate P@V
        {
#pragma unroll
            for (int i = 0; i < 7; i++) {
                int a = ta + i * 8;
                acc[i] *= (a < AG) ? r_s[a] : 0.f;
            }
#pragma unroll 4
            for (int n = 0; n < 64; n++) {
                float vv = v_s[n][td];
#pragma unroll
                for (int i = 0; i < 7; i++) {
                    int a = ta + i * 8;
                    if (a < AG) acc[i] += s_s[a][n] * vv;
                }
            }
        }
        __syncthreads();
    }
#pragma unroll
    for (int i = 0; i < 7; i++) {
        int a = ta + i * 8;
        if (a < AG)
            g_pacc[(((size_t)bh * NSPLIT + sp) * AG + a) * HD + td] = acc[i];
    }
    if (t < AG) {
        g_pm[(bh * NSPLIT + sp) * AG + t] = m_s[t];
        g_pl[(bh * NSPLIT + sp) * AG + t] = l_s[t];
    }
}

// ---------------- K4b: combine stage-1 partials ----------------
__global__ void k_fs1red() {
    int bh = blockIdx.x;
    int t = threadIdx.x;
    for (int idx = t; idx < AG * HD; idx += 256) {
        int a = idx >> 5, d = idx & 31;
        float mmax = -1e30f;
#pragma unroll
        for (int s = 0; s < NSPLIT; s++)
            mmax = fmaxf(mmax, g_pm[(bh * NSPLIT + s) * AG + a]);
        float num = 0.f, den = 0.f;
#pragma unroll
        for (int s = 0; s < NSPLIT; s++) {
            float w = __expf(g_pm[(bh * NSPLIT + s) * AG + a] - mmax);
            num += w * g_pacc[(((size_t)bh * NSPLIT + s) * AG + a) * HD + d];
            den += w * g_pl[(bh * NSPLIT + s) * AG + a];
        }
        g_agentv[((size_t)bh * AG + a) * HD + d] = num / den;
    }
}

// ---------------- K7: fused stage-2 ----------------
__global__ __launch_bounds__(256) void k_st2() {
    __shared__ __align__(16) float ah_s[AG * HD];
    __shared__ __align__(16) float av_s[AG * HD];
    __shared__ __align__(16) float p_sm[AG][128];
    __shared__ float li_sm[128];
    int t = threadIdx.x;
    int n0 = blockIdx.x * 128, h = blockIdx.y, b = blockIdx.z;
    for (int idx = t; idx < AG * HD; idx += 256) {
        int a = idx >> 5, d = idx & 31;
        ah_s[idx] = g_agent[(b * AG + a) * Cc + h * HD + d];
        av_s[idx] = g_agentv[((size_t)(b * NH + h) * AG + a) * HD + d];
    }
    __syncthreads();
    {
        int n_l = t & 127, a0 = t >> 7;
        float4 q4[8];
        const float4* qp = (const float4*)(g_q + ((size_t)b * Nn + n0 + n_l) * Cc + h * HD);
#pragma unroll
        for (int i = 0; i < 8; i++) q4[i] = qp[i];
        const float* b2 = g_bias2 + ((size_t)h * Nn + n0 + n_l) * AG;
        for (int a = a0; a < AG; a += 2) {
            float s = 0.f;
#pragma unroll
            for (int i = 0; i < 8; i++) {
                float4 w = *(const float4*)&ah_s[a * HD + i * 4];
                s += q4[i].x * w.x + q4[i].y * w.y + q4[i].z * w.z + q4[i].w * w.w;
            }
            p_sm[a][n_l] = s * SCALE + b2[a];
        }
    }
    __syncthreads();
    if (t < 128) {
        float mx = -1e30f;
        for (int a = 0; a < AG; a++) mx = fmaxf(mx, p_sm[a][t]);
        float sm = 0.f;
        for (int a = 0; a < AG; a++) {
            float e = __expf(p_sm[a][t] - mx);
            p_sm[a][t] = e;
            sm += e;
        }
        li_sm[t] = 1.0f / sm;
    }
    __syncthreads();
    {
        int d = t & 31, grp = t >> 5;
        int nb = grp * 16;
        float acc[16];
#pragma unroll
        for (int i = 0; i < 16; i++) acc[i] = 0.f;
        for (int a = 0; a < AG; a++) {
            float av = av_s[a * HD + d];
#pragma unroll
            for (int i4 = 0; i4 < 4; i4++) {
                float4 p4 = *(const float4*)&p_sm[a][nb + i4 * 4];
                acc[i4 * 4 + 0] += p4.x * av;
                acc[i4 * 4 + 1] += p4.y * av;
                acc[i4 * 4 + 2] += p4.z * av;
                acc[i4 * 4 + 3] += p4.w * av;
            }
        }
#pragma unroll
        for (int i = 0; i < 16; i++) {
            int n = nb + i;
            g_o[((size_t)b * Nn + n0 + n) * Cc + h * HD + d] = acc[i] * li_sm[n];
        }
    }
}

// ---------------- K8: depthwise 3x3 conv + bf16 hi/lo split of (o + dw) ----------------
__global__ void k_dw(const float* __restrict__ Wd, const float* __restrict__ bd) {
    int c = threadIdx.x;
    int n = blockIdx.x, b = blockIdx.y;
    int y = n >> 6, x = n & 63;
    float s = bd[c];
#pragma unroll
    for (int dy = -1; dy <= 1; dy++) {
        int yy = y + dy;
        if (yy < 0 || yy > 63) continue;
#pragma unroll
        for (int dx = -1; dx <= 1; dx++) {
            int xx = x + dx;
            if (xx < 0 || xx > 63) continue;
            s += g_v[((size_t)b * Nn + yy * 64 + xx) * Cc + c] * Wd[c * 9 + (dy + 1) * 3 + (dx + 1)];
        }
    }
    size_t idx = ((size_t)b * Nn + n) * Cc + c;
    float v = g_o[idx] + s;
    __nv_bfloat16 hi = __float2bfloat16(v);
    g_oh[idx] = hi;
    g_ol[idx] = __float2bfloat16(v - __bfloat162float(hi));
}

// ---------------- launch ----------------
extern "C" void kernel_launch(void* const* d_in, const int* in_sizes, int n_in,
                              void* d_out, int out_size) {
    const float* x     = (const float*)d_in[0];
    const float* Wq    = (const float*)d_in[1];
    const float* Wkv   = (const float*)d_in[2];
    const float* Wproj = (const float*)d_in[3];
    const float* bproj = (const float*)d_in[4];
    const float* Wdwc  = (const float*)d_in[5];
    const float* bdwc  = (const float*)d_in[6];
    const float* an    = (const float*)d_in[7];
    const float* na    = (const float*)d_in[8];
    const float* ahb   = (const float*)d_in[9];
    const float* awb   = (const float*)d_in[10];
    const float* hab   = (const float*)d_in[11];
    const float* wab   = (const float*)d_in[12];
    float* out = (float*)d_out;

    cudaFuncSetAttribute(k_gemm_mma<0>, cudaFuncAttributeMaxDynamicSharedMemorySize, SMEM_DYN);
    cudaFuncSetAttribute(k_gemm_mma<1>, cudaFuncAttributeMaxDynamicSharedMemorySize, SMEM_DYN);

    k_bias   <<<dim3(Nn / 256, AG, NH), 256>>>(an, na, ahb, awb, hab, wab);
    k_prep_w <<<1024, 256>>>(Wq, Wkv, Wproj);
    k_xsplit <<<dim3(128, 8, Bb), dim3(32, 8)>>>(x);
    k_gemm_mma<0><<<dim3(32, 12, Bb), 256, SMEM_DYN>>>(nullptr, nullptr);
    k_pool   <<<dim3(AG, Bb), 256>>>();
    k_fs1    <<<dim3(NSPLIT, NH, Bb), 256>>>();
    k_fs1red <<<Bb * NH, 256>>>();
    k_st2    <<<dim3(Nn / 128, NH, Bb), 256>>>();
    k_dw     <<<dim3(Nn, Bb), 256>>>(Wdwc, bdwc);
    k_gemm_mma<1><<<dim3(32, 4, Bb), 256, SMEM_DYN>>>(bproj, out);
}

// round 11
// speedup vs baseline: 1.5298x; 1.0658x over previous
#include <cuda_runtime.h>
#include <cuda_bf16.h>
#include <cstdint>

// ---------------- constants ----------------
namespace {
constexpr int Bb = 16;      // batch
constexpr int Cc = 256;     // channels
constexpr int Nn = 4096;    // H*W
constexpr int NH = 8;       // heads
constexpr int HD = 32;      // head dim
constexpr int AG = 49;      // agent tokens
constexpr int NSPLIT = 8;   // stage-1 n-splits
constexpr float SCALE = 0.17677669529663689f;  // 32^-0.5

// GEMM smem: per stage A(hi|lo) 128x32k pitch40 + B(hi|lo) 128x32k pitch40
constexpr int KP = 40;                          // k-pitch in bf16 (80B rows: conflict-free ldmatrix)
constexpr unsigned SA_SZ = 128 * KP * 2;        // 10240 per half
constexpr unsigned SB_SZ = 128 * KP * 2;        // 10240 per half
constexpr unsigned STAGE_SZ = 2 * SA_SZ + 2 * SB_SZ;  // 40960
constexpr unsigned SMEM_DYN = 2 * STAGE_SZ;     // 81920 (epilogue staging aliases this)
constexpr int SP = 136;                         // epilogue staging pitch (fp32): 128*136*4=69632 < 81920
}

// ---------------- scratch (device globals; no allocation allowed) ----------------
__device__ float g_q[Bb * Nn * Cc];
__device__ float g_k[Bb * Nn * Cc];
__device__ float g_v[Bb * Nn * Cc];
__device__ float g_o[Bb * Nn * Cc];            // attention out (pre-dwconv, pre-proj)
__device__ float g_agent[Bb * AG * Cc];
__device__ float g_agentv[Bb * NH * AG * HD];
__device__ float g_bias1[NH * AG * Nn];        // stage-1 bias [h][a][n]
__device__ float g_bias2[NH * Nn * AG];        // stage-2 bias [h][n][a]
__device__ float g_pacc[Bb * NH * NSPLIT * AG * HD];  // stage-1 partial acc
__device__ float g_pm[Bb * NH * NSPLIT * AG];
__device__ float g_pl[Bb * NH * NSPLIT * AG];

// bf16 hi/lo split operands for tensor-core GEMMs
__device__ __nv_bfloat16 g_xh[Bb * Nn * Cc];   // xt row-major [b][n][c]
__device__ __nv_bfloat16 g_xl[Bb * Nn * Cc];
__device__ __nv_bfloat16 g_oh[Bb * Nn * Cc];
__device__ __nv_bfloat16 g_ol[Bb * Nn * Cc];
__device__ __nv_bfloat16 g_wh[768 * Cc];       // qkv weights combined [q|k|v]
__device__ __nv_bfloat16 g_wl[768 * Cc];
__device__ __nv_bfloat16 g_pwh[Cc * Cc];       // proj weights
__device__ __nv_bfloat16 g_pwl[Cc * Cc];

// ---------------- PTX helpers (baseline sm_80+ features only) ----------------
__device__ __forceinline__ uint32_t smem_u32(const void* p) {
    uint32_t a;
    asm("{ .reg .u64 t; cvta.to.shared.u64 t, %1; cvt.u32.u64 %0, t; }" : "=r"(a) : "l"(p));
    return a;
}
__device__ __forceinline__ void ldm_x4(uint32_t* r, uint32_t addr) {
    asm volatile("ldmatrix.sync.aligned.m8n8.x4.shared.b16 {%0,%1,%2,%3}, [%4];"
                 : "=r"(r[0]), "=r"(r[1]), "=r"(r[2]), "=r"(r[3]) : "r"(addr));
}
__device__ __forceinline__ void mma_bf16(float* d, const uint32_t* a, uint32_t b0, uint32_t b1) {
    asm volatile(
        "mma.sync.aligned.m16n8k16.row.col.f32.bf16.bf16.f32 "
        "{%0,%1,%2,%3}, {%4,%5,%6,%7}, {%8,%9}, {%0,%1,%2,%3};"
        : "+f"(d[0]), "+f"(d[1]), "+f"(d[2]), "+f"(d[3])
        : "r"(a[0]), "r"(a[1]), "r"(a[2]), "r"(a[3]), "r"(b0), "r"(b1));
}
__device__ __forceinline__ void cp16(uint32_t dst, const void* src) {
    asm volatile("cp.async.ca.shared.global [%0], [%1], 16;" :: "r"(dst), "l"(src));
}
__device__ __forceinline__ void cp_commit() { asm volatile("cp.async.commit_group;" ::: "memory"); }
template <int N>
__device__ __forceinline__ void cp_wait() { asm volatile("cp.async.wait_group %0;" :: "n"(N) : "memory"); }

// ---------------- prep: bf16 hi/lo splits ----------------
__global__ void k_prep_w(const float* __restrict__ Wq, const float* __restrict__ Wkv,
                         const float* __restrict__ Wp) {
    int row = blockIdx.x, t = threadIdx.x;
    if (row < 768) {
        float v = (row < 256) ? Wq[row * 256 + t] : Wkv[(row - 256) * 256 + t];
        __nv_bfloat16 hi = __float2bfloat16(v);
        g_wh[row * 256 + t] = hi;
        g_wl[row * 256 + t] = __float2bfloat16(v - __bfloat162float(hi));
    } else {
        int r = row - 768;
        float v = Wp[r * 256 + t];
        __nv_bfloat16 hi = __float2bfloat16(v);
        g_pwh[r * 256 + t] = hi;
        g_pwl[r * 256 + t] = __float2bfloat16(v - __bfloat162float(hi));
    }
}

__global__ void k_xsplit(const float* __restrict__ x) {
    __shared__ float tile[32][33];
    int tx = threadIdx.x, ty = threadIdx.y;  // 32x8
    int n0 = blockIdx.x * 32, c0 = blockIdx.y * 32, b = blockIdx.z;
#pragma unroll
    for (int yy = 0; yy < 32; yy += 8)
        tile[ty + yy][tx] = x[((size_t)b * 256 + c0 + ty + yy) * 4096 + n0 + tx];
    __syncthreads();
#pragma unroll
    for (int yy = 0; yy < 32; yy += 8) {
        int nl = ty + yy;
        float v = tile[tx][nl];
        __nv_bfloat16 hi = __float2bfloat16(v);
        size_t o = ((size_t)b * 4096 + n0 + nl) * 256 + c0 + tx;
        g_xh[o] = hi;
        g_xl[o] = __float2bfloat16(v - __bfloat162float(hi));
    }
}

// ---------------- tensor-core GEMM: 128x128 CTA tiles, double-buffered k32 stages ----------------
// MODE 0: A = g_xh/g_xl, W = g_wh/g_wl (768 rows, 6 j-tiles) -> g_q/g_k/g_v row-major
// MODE 1: A = g_oh/g_ol, W = g_pwh/g_pwl (256 rows, 2 j-tiles) -> transposed out + bias
template <int MODE>
__global__ __launch_bounds__(256, 2)
void k_gemm_mma(const float* __restrict__ bias, float* __restrict__ outp) {
    extern __shared__ __align__(16) char dsm[];
    float* stag = (float*)dsm;                 // epilogue staging aliases pipeline smem

    const int t = threadIdx.x;
    const int lane = t & 31, wid = t >> 5;
    const int wm = wid & 3, wn = wid >> 2;     // warp tile: 32(m) x 64(n)
    const int b = blockIdx.z;
    const int n0 = blockIdx.x * 128;
    const int jt = blockIdx.y, j0 = jt * 128;

    const __nv_bfloat16* Agh = (MODE == 0 ? g_xh : g_oh) + ((size_t)b * 4096 + n0) * 256;
    const __nv_bfloat16* Agl = (MODE == 0 ? g_xl : g_ol) + ((size_t)b * 4096 + n0) * 256;
    const __nv_bfloat16* Wgh = ((MODE == 0) ? g_wh : g_pwh) + (size_t)j0 * 256;
    const __nv_bfloat16* Wgl = ((MODE == 0) ? g_wl : g_pwl) + (size_t)j0 * 256;

    const uint32_t uS = smem_u32(dsm);

    // stage loader: A/B each 512 16B-chunks per half (2 iters of 256)
    auto load_stage = [&](int st, int kt) {
        uint32_t base = uS + st * STAGE_SZ;
        int k0 = kt * 32;
#pragma unroll
        for (int it = 0; it < 2; it++) {
            int idx = t + it * 256;
            int r = idx >> 2, ch = idx & 3;
            uint32_t off = (uint32_t)((r * KP + ch * 8) * 2);
            const size_t g = (size_t)r * 256 + k0 + ch * 8;
            cp16(base + off, Agh + g);
            cp16(base + SA_SZ + off, Agl + g);
            cp16(base + 2 * SA_SZ + off, Wgh + g);
            cp16(base + 2 * SA_SZ + SB_SZ + off, Wgl + g);
        }
    };

    // per-thread ldmatrix byte offsets (within stage)
    const int q8 = lane >> 3, r8 = lane & 7;
    uint32_t aoff[2], boff[4];
#pragma unroll
    for (int mt = 0; mt < 2; mt++) {
        int row = wm * 32 + mt * 16 + (q8 & 1) * 8 + r8;
        aoff[mt] = (uint32_t)((row * KP + (q8 >> 1) * 8) * 2);
    }
#pragma unroll
    for (int p = 0; p < 4; p++) {
        int nrow = wn * 64 + p * 16 + (q8 >> 1) * 8 + r8;
        boff[p] = (uint32_t)((nrow * KP + (q8 & 1) * 8) * 2);
    }

    float acc[2][8][4];
#pragma unroll
    for (int mt = 0; mt < 2; mt++)
#pragma unroll
        for (int nt = 0; nt < 8; nt++)
#pragma unroll
            for (int e = 0; e < 4; e++) acc[mt][nt][e] = 0.f;

    load_stage(0, 0);
    cp_commit();

    for (int kt = 0; kt < 8; kt++) {
        cp_wait<0>();
        __syncthreads();
        if (kt < 7) {
            load_stage((kt + 1) & 1, kt + 1);
            cp_commit();
        }
        const uint32_t base = uS + (kt & 1) * STAGE_SZ;
        const uint32_t uAh = base, uAl = base + SA_SZ;
        const uint32_t uBh = base + 2 * SA_SZ, uBl = uBh + SB_SZ;
#pragma unroll
        for (int kh = 0; kh < 2; kh++) {
            uint32_t ko = (uint32_t)(kh * 32);   // 16 k-elems = 32 bytes
            uint32_t A_h[2][4], A_l[2][4];
            ldm_x4(A_h[0], uAh + aoff[0] + ko);
            ldm_x4(A_h[1], uAh + aoff[1] + ko);
            ldm_x4(A_l[0], uAl + aoff[0] + ko);
            ldm_x4(A_l[1], uAl + aoff[1] + ko);
#pragma unroll
            for (int p = 0; p < 4; p++) {
                uint32_t B_h[4], B_l[4];
                ldm_x4(B_h, uBh + boff[p] + ko);
                ldm_x4(B_l, uBl + boff[p] + ko);
#pragma unroll
                for (int mt = 0; mt < 2; mt++) {
#pragma unroll
                    for (int hf = 0; hf < 2; hf++) {
                        float* d = acc[mt][p * 2 + hf];
                        mma_bf16(d, A_h[mt], B_h[hf * 2], B_h[hf * 2 + 1]);
                        mma_bf16(d, A_h[mt], B_l[hf * 2], B_l[hf * 2 + 1]);
                        mma_bf16(d, A_l[mt], B_h[hf * 2], B_h[hf * 2 + 1]);
                    }
                }
            }
        }
        __syncthreads();
    }

    // ---- stage fragments to smem [128][SP] (pipeline smem is dead now) ----
    {
        int r0 = lane >> 2, c0 = (lane & 3) * 2;
#pragma unroll
        for (int mt = 0; mt < 2; mt++) {
#pragma unroll
            for (int nt = 0; nt < 8; nt++) {
                int row = wm * 32 + mt * 16 + r0;
                int col = wn * 64 + nt * 8 + c0;
                stag[row * SP + col]           = acc[mt][nt][0];
                stag[row * SP + col + 1]       = acc[mt][nt][1];
                stag[(row + 8) * SP + col]     = acc[mt][nt][2];
                stag[(row + 8) * SP + col + 1] = acc[mt][nt][3];
            }
        }
    }
    __syncthreads();

    // ---- coalesced stores ----
    if (MODE == 0) {
        float* dst = (jt < 2) ? g_q : (jt < 4) ? g_k : g_v;
        int jl = (jt & 1) * 128;
#pragma unroll
        for (int it = 0; it < 16; it++) {
            int idx = t + it * 256;          // 4096 float4
            int m = idx >> 5, j4 = (idx & 31) * 4;
            *(float4*)&dst[((size_t)b * 4096 + n0 + m) * 256 + jl + j4] =
                *(float4*)&stag[m * SP + j4];
        }
    } else {
        int m = t & 127, js = t >> 7;
#pragma unroll 8
        for (int j = js; j < 128; j += 2) {
            float v = stag[m * SP + j] + bias[j0 + j];
            outp[((size_t)b * 256 + j0 + j) * 4096 + n0 + m] = v;
        }
    }
}

// ---------------- bilinear coeffs for 7 -> 64 resize ----------------
__device__ __forceinline__ void lin7(int i, int& j0, int& j1, float& w) {
    float c = (i + 0.5f) * (7.0f / 64.0f) - 0.5f;
    float f = floorf(c);
    w = c - f;
    int j = (int)f;
    j0 = max(0, min(6, j));
    j1 = max(0, min(6, j + 1));
}

__device__ __forceinline__ float bil7(const float* img, int y0, int y1, float wy,
                                      int x0, int x1, float wx) {
    float v0 = img[y0 * 7 + x0] * (1.f - wx) + img[y0 * 7 + x1] * wx;
    float v1 = img[y1 * 7 + x0] * (1.f - wx) + img[y1 * 7 + x1] * wx;
    return v0 * (1.f - wy) + v1 * wy;
}

// ---------------- K1: position biases ----------------
__global__ void k_bias(const float* __restrict__ an, const float* __restrict__ na,
                       const float* __restrict__ ahb, const float* __restrict__ awb,
                       const float* __restrict__ hab, const float* __restrict__ wab) {
    int n = blockIdx.x * 256 + threadIdx.x;
    int a = blockIdx.y, h = blockIdx.z;
    int y = n >> 6, x = n & 63;
    int y0, y1, x0, x1; float wy, wx;
    lin7(y, y0, y1, wy);
    lin7(x, x0, x1, wx);
    const float* i1 = an + (h * AG + a) * 49;
    const float* i2 = na + (h * AG + a) * 49;
    float v1 = bil7(i1, y0, y1, wy, x0, x1, wx);
    float v2 = bil7(i2, y0, y1, wy, x0, x1, wx);
    g_bias1[(h * AG + a) * Nn + n] = v1 + ahb[(h * AG + a) * 64 + y] + awb[(h * AG + a) * 64 + x];
    g_bias2[(h * Nn + n) * AG + a] = v2 + hab[(h * 64 + y) * AG + a] + wab[(h * 64 + x) * AG + a];
}

// ---------------- K3: adaptive avg pool q -> agent ----------------
__global__ void k_pool() {
    int c = threadIdx.x;
    int a = blockIdx.x;
    int b = blockIdx.y;
    int p = a / 7, q = a % 7;
    int ys = (p * 64) / 7, ye = ((p + 1) * 64 + 6) / 7;
    int xs = (q * 64) / 7, xe = ((q + 1) * 64 + 6) / 7;
    float s = 0.f;
    for (int y = ys; y < ye; y++)
        for (int x = xs; x < xe; x++)
            s += g_q[(b * Nn + y * 64 + x) * Cc + c];
    g_agent[(b * AG + a) * Cc + c] = s * (1.0f / ((ye - ys) * (xe - xs)));
}

// ---------------- K4: stage-1 flash with n-split (partials) ----------------
__global__ __launch_bounds__(256) void k_fs1() {
    __shared__ __align__(16) float ah_s[AG * HD];
    __shared__ __align__(16) float k_s[64 * 32];
    __shared__ float v_s[64][33];
    __shared__ float s_s[AG][65];
    __shared__ float m_s[AG], r_s[AG], l_s[AG];

    int sp = blockIdx.x, h = blockIdx.y, b = blockIdx.z;
    int bh = b * NH + h;
    int t = threadIdx.x;
    int ta = t >> 5, td = t & 31;

    for (int idx = t; idx < AG * HD; idx += 256)
        ah_s[idx] = g_agent[(b * AG + (idx >> 5)) * Cc + h * HD + (idx & 31)] * SCALE;
    if (t < AG) { m_s[t] = -1e30f; l_s[t] = 0.f; }
    __syncthreads();

    float acc[7];
#pragma unroll
    for (int i = 0; i < 7; i++) acc[i] = 0.f;

    const float* kb = g_k + (size_t)b * Nn * Cc + h * HD;
    const float* vb = g_v + (size_t)b * Nn * Cc + h * HD;
    const float* bias = g_bias1 + (size_t)h * AG * Nn;

    for (int tile = 0; tile < 8; tile++) {
        int n0 = sp * 512 + tile * 64;
#pragma unroll
        for (int i = 0; i < 2; i++) {
            int idx = t + i * 256;
            int r = idx >> 3, cd = idx & 7;
            float4 kk = *(const float4*)(kb + (size_t)(n0 + r) * Cc + cd * 4);
            float4 vv = *(const float4*)(vb + (size_t)(n0 + r) * Cc + cd * 4);
            *(float4*)&k_s[r * 32 + ((cd ^ (r & 7)) << 2)] = kk;
            v_s[r][cd * 4 + 0] = vv.x;
            v_s[r][cd * 4 + 1] = vv.y;
            v_s[r][cd * 4 + 2] = vv.z;
            v_s[r][cd * 4 + 3] = vv.w;
        }
        __syncthreads();
        for (int idx = t; idx < AG * 64; idx += 256) {
            int a = idx >> 6, n = idx & 63;
            int sw = n & 7;
            const float* ap = &ah_s[a * HD];
            const float* kp = &k_s[n * 32];
            float s = 0.f;
#pragma unroll
            for (int i = 0; i < 8; i++) {
                float4 w = *(const float4*)&ap[i * 4];
                float4 kk = *(const float4*)&kp[(i ^ sw) << 2];
                s += w.x * kk.x + w.y * kk.y + w.z * kk.z + w.w * kk.w;
            }
            s_s[a][n] = s + bias[a * Nn + n0 + n];
        }
        __syncthreads();
#pragma unroll
        for (int i = 0; i < 7; i++) {
            int a = ta + i * 8;
            if (a < AG) {
                float s0 = s_s[a][td], s1 = s_s[a][td + 32];
                float mx = fmaxf(s0, s1);
#pragma unroll
                for (int off = 16; off > 0; off >>= 1)
                    mx = fmaxf(mx, __shfl_xor_sync(0xFFFFFFFFu, mx, off));
                float mnew = fmaxf(m_s[a], mx);
                float e0 = __expf(s0 - mnew), e1 = __expf(s1 - mnew);
                s_s[a][td] = e0;
                s_s[a][td + 32] = e1;
                float sum = e0 + e1;
#pragma unroll
                for (int off = 16; off > 0; off >>= 1)
                    sum += __shfl_xor_sync(0xFFFFFFFFu, sum, off);
                if (td == 0) {
                    float r = __expf(m_s[a] - mnew);
                    r_s[a] = r;
                    l_s[a] = l_s[a] * r + sum;
                    m_s[a] = mnew;
                }
            }
        }
        __syncthreads();
        {
#pragma unroll
            for (int i = 0; i < 7; i++) {
                int a = ta + i * 8;
                acc[i] *= (a < AG) ? r_s[a] : 0.f;
            }
#pragma unroll 4
            for (int n = 0; n < 64; n++) {
                float vv = v_s[n][td];
#pragma unroll
                for (int i = 0; i < 7; i++) {
                    int a = ta + i * 8;
                    if (a < AG) acc[i] += s_s[a][n] * vv;
                }
            }
        }
        __syncthreads();
    }
#pragma unroll
    for (int i = 0; i < 7; i++) {
        int a = ta + i * 8;
        if (a < AG)
            g_pacc[(((size_t)bh * NSPLIT + sp) * AG + a) * HD + td] = acc[i];
    }
    if (t < AG) {
        g_pm[(bh * NSPLIT + sp) * AG + t] = m_s[t];
        g_pl[(bh * NSPLIT + sp) * AG + t] = l_s[t];
    }
}

// ---------------- K4b: combine stage-1 partials ----------------
__global__ void k_fs1red() {
    int bh = blockIdx.x;
    int t = threadIdx.x;
    for (int idx = t; idx < AG * HD; idx += 256) {
        int a = idx >> 5, d = idx & 31;
        float mmax = -1e30f;
#pragma unroll
        for (int s = 0; s < NSPLIT; s++)
            mmax = fmaxf(mmax, g_pm[(bh * NSPLIT + s) * AG + a]);
        float num = 0.f, den = 0.f;
#pragma unroll
        for (int s = 0; s < NSPLIT; s++) {
            float w = __expf(g_pm[(bh * NSPLIT + s) * AG + a] - mmax);
            num += w * g_pacc[(((size_t)bh * NSPLIT + s) * AG + a) * HD + d];
            den += w * g_pl[(bh * NSPLIT + s) * AG + a];
        }
        g_agentv[((size_t)bh * AG + a) * HD + d] = num / den;
    }
}

// ---------------- K7: fused stage-2 ----------------
__global__ __launch_bounds__(256) void k_st2() {
    __shared__ __align__(16) float ah_s[AG * HD];
    __shared__ __align__(16) float av_s[AG * HD];
    __shared__ __align__(16) float p_sm[AG][128];
    __shared__ float li_sm[128];
    int t = threadIdx.x;
    int n0 = blockIdx.x * 128, h = blockIdx.y, b = blockIdx.z;
    for (int idx = t; idx < AG * HD; idx += 256) {
        int a = idx >> 5, d = idx & 31;
        ah_s[idx] = g_agent[(b * AG + a) * Cc + h * HD + d];
        av_s[idx] = g_agentv[((size_t)(b * NH + h) * AG + a) * HD + d];
    }
    __syncthreads();
    {
        int n_l = t & 127, a0 = t >> 7;
        float4 q4[8];
        const float4* qp = (const float4*)(g_q + ((size_t)b * Nn + n0 + n_l) * Cc + h * HD);
#pragma unroll
        for (int i = 0; i < 8; i++) q4[i] = qp[i];
        const float* b2 = g_bias2 + ((size_t)h * Nn + n0 + n_l) * AG;
        for (int a = a0; a < AG; a += 2) {
            float s = 0.f;
#pragma unroll
            for (int i = 0; i < 8; i++) {
                float4 w = *(const float4*)&ah_s[a * HD + i * 4];
                s += q4[i].x * w.x + q4[i].y * w.y + q4[i].z * w.z + q4[i].w * w.w;
            }
            p_sm[a][n_l] = s * SCALE + b2[a];
        }
    }
    __syncthreads();
    if (t < 128) {
        float mx = -1e30f;
        for (int a = 0; a < AG; a++) mx = fmaxf(mx, p_sm[a][t]);
        float sm = 0.f;
        for (int a = 0; a < AG; a++) {
            float e = __expf(p_sm[a][t] - mx);
            p_sm[a][t] = e;
            sm += e;
        }
        li_sm[t] = 1.0f / sm;
    }
    __syncthreads();
    {
        int d = t & 31, grp = t >> 5;
        int nb = grp * 16;
        float acc[16];
#pragma unroll
        for (int i = 0; i < 16; i++) acc[i] = 0.f;
        for (int a = 0; a < AG; a++) {
            float av = av_s[a * HD + d];
#pragma unroll
            for (int i4 = 0; i4 < 4; i4++) {
                float4 p4 = *(const float4*)&p_sm[a][nb + i4 * 4];
                acc[i4 * 4 + 0] += p4.x * av;
                acc[i4 * 4 + 1] += p4.y * av;
                acc[i4 * 4 + 2] += p4.z * av;
                acc[i4 * 4 + 3] += p4.w * av;
            }
        }
#pragma unroll
        for (int i = 0; i < 16; i++) {
            int n = nb + i;
            g_o[((size_t)b * Nn + n0 + n) * Cc + h * HD + d] = acc[i] * li_sm[n];
        }
    }
}

// ---------------- K8: depthwise 3x3 conv + bf16 hi/lo split of (o + dw) ----------------
__global__ void k_dw(const float* __restrict__ Wd, const float* __restrict__ bd) {
    int c = threadIdx.x;
    int n = blockIdx.x, b = blockIdx.y;
    int y = n >> 6, x = n & 63;
    float s = bd[c];
#pragma unroll
    for (int dy = -1; dy <= 1; dy++) {
        int yy = y + dy;
        if (yy < 0 || yy > 63) continue;
#pragma unroll
        for (int dx = -1; dx <= 1; dx++) {
            int xx = x + dx;
            if (xx < 0 || xx > 63) continue;
            s += g_v[((size_t)b * Nn + yy * 64 + xx) * Cc + c] * Wd[c * 9 + (dy + 1) * 3 + (dx + 1)];
        }
    }
    size_t idx = ((size_t)b * Nn + n) * Cc + c;
    float v = g_o[idx] + s;
    __nv_bfloat16 hi = __float2bfloat16(v);
    g_oh[idx] = hi;
    g_ol[idx] = __float2bfloat16(v - __bfloat162float(hi));
}

// ---------------- launch ----------------
extern "C" void kernel_launch(void* const* d_in, const int* in_sizes, int n_in,
                              void* d_out, int out_size) {
    const float* x     = (const float*)d_in[0];
    const float* Wq    = (const float*)d_in[1];
    const float* Wkv   = (const float*)d_in[2];
    const float* Wproj = (const float*)d_in[3];
    const float* bproj = (const float*)d_in[4];
    const float* Wdwc  = (const float*)d_in[5];
    const float* bdwc  = (const float*)d_in[6];
    const float* an    = (const float*)d_in[7];
    const float* na    = (const float*)d_in[8];
    const float* ahb   = (const float*)d_in[9];
    const float* awb   = (const float*)d_in[10];
    const float* hab   = (const float*)d_in[11];
    const float* wab   = (const float*)d_in[12];
    float* out = (float*)d_out;

    cudaFuncSetAttribute(k_gemm_mma<0>, cudaFuncAttributeMaxDynamicSharedMemorySize, SMEM_DYN);
    cudaFuncSetAttribute(k_gemm_mma<1>, cudaFuncAttributeMaxDynamicSharedMemorySize, SMEM_DYN);

    k_bias   <<<dim3(Nn / 256, AG, NH), 256>>>(an, na, ahb, awb, hab, wab);
    k_prep_w <<<1024, 256>>>(Wq, Wkv, Wproj);
    k_xsplit <<<dim3(128, 8, Bb), dim3(32, 8)>>>(x);
    k_gemm_mma<0><<<dim3(32, 6, Bb), 256, SMEM_DYN>>>(nullptr, nullptr);
    k_pool   <<<dim3(AG, Bb), 256>>>();
    k_fs1    <<<dim3(NSPLIT, NH, Bb), 256>>>();
    k_fs1red <<<Bb * NH, 256>>>();
    k_st2    <<<dim3(Nn / 128, NH, Bb), 256>>>();
    k_dw     <<<dim3(Nn, Bb), 256>>>(Wdwc, bdwc);
    k_gemm_mma<1><<<dim3(32, 2, Bb), 256, SMEM_DYN>>>(bproj, out);
}

// round 12
// speedup vs baseline: 1.6653x; 1.0886x over previous
#include <cuda_runtime.h>
#include <cuda_bf16.h>
#include <cstdint>

// ---------------- constants ----------------
namespace {
constexpr int Bb = 16;      // batch
constexpr int Cc = 256;     // channels
constexpr int Nn = 4096;    // H*W
constexpr int NH = 8;       // heads
constexpr int HD = 32;      // head dim
constexpr int AG = 49;      // agent tokens
constexpr int NSPLIT = 8;   // stage-1 n-splits
constexpr int B2P = 52;     // bias2 pitch (floats) for aligned float2 fragment loads
constexpr float SCALE = 0.17677669529663689f;  // 32^-0.5

// GEMM smem: per stage A(hi|lo) 128x32k pitch40 + B(hi|lo) 128x32k pitch40
constexpr int KP = 40;                          // k-pitch in bf16 (80B rows: conflict-free ldmatrix)
constexpr unsigned SA_SZ = 128 * KP * 2;        // 10240 per half
constexpr unsigned SB_SZ = 128 * KP * 2;        // 10240 per half
constexpr unsigned STAGE_SZ = 2 * SA_SZ + 2 * SB_SZ;  // 40960
constexpr unsigned SMEM_DYN = 2 * STAGE_SZ;     // 81920 (epilogue staging aliases this)
constexpr int SP = 136;                         // epilogue staging pitch (fp32)

// st2 smem offsets (bytes)
constexpr unsigned OFF_QH  = 0;                 // 128x40 bf16
constexpr unsigned OFF_QL  = 10240;
constexpr unsigned OFF_AHH = 20480;             // 64x40 bf16
constexpr unsigned OFF_AHL = 25600;
constexpr unsigned OFF_AVH = 30720;             // 32x72 bf16 (av^T)
constexpr unsigned OFF_AVL = 35328;
constexpr unsigned ST2_SMEM = 39936;
}

// ---------------- scratch (device globals; no allocation allowed) ----------------
__device__ float g_k[Bb * Nn * Cc];
__device__ float g_v[Bb * Nn * Cc];
__device__ float g_o[Bb * Nn * Cc];            // attention out (pre-dwconv, pre-proj)
__device__ float g_agent[Bb * AG * Cc];
__device__ float g_bias1[NH * AG * Nn];        // stage-1 bias [h][a][n]
__device__ float g_bias2[NH * Nn * B2P];       // stage-2 bias [h][n][a] pitch 52
__device__ float g_pacc[Bb * NH * NSPLIT * AG * HD];  // stage-1 partial acc
__device__ float g_pm[Bb * NH * NSPLIT * AG];
__device__ float g_pl[Bb * NH * NSPLIT * AG];

// bf16 hi/lo split operands for tensor-core work
__device__ __nv_bfloat16 g_xh[Bb * Nn * Cc];   // xt row-major [b][n][c]
__device__ __nv_bfloat16 g_xl[Bb * Nn * Cc];
__device__ __nv_bfloat16 g_qh[Bb * Nn * Cc];   // q hi/lo (from qkv GEMM epilogue)
__device__ __nv_bfloat16 g_ql[Bb * Nn * Cc];
__device__ __nv_bfloat16 g_oh[Bb * Nn * Cc];
__device__ __nv_bfloat16 g_ol[Bb * Nn * Cc];
__device__ __nv_bfloat16 g_ahh[Bb * AG * Cc];  // agent*SCALE hi/lo
__device__ __nv_bfloat16 g_ahl[Bb * AG * Cc];
__device__ __nv_bfloat16 g_avh[Bb * NH * AG * HD];  // agent_v hi/lo
__device__ __nv_bfloat16 g_avl[Bb * NH * AG * HD];
__device__ __nv_bfloat16 g_wh[768 * Cc];       // qkv weights combined [q|k|v]
__device__ __nv_bfloat16 g_wl[768 * Cc];
__device__ __nv_bfloat16 g_pwh[Cc * Cc];       // proj weights
__device__ __nv_bfloat16 g_pwl[Cc * Cc];

// ---------------- PTX helpers (baseline sm_80+ features only) ----------------
__device__ __forceinline__ uint32_t smem_u32(const void* p) {
    uint32_t a;
    asm("{ .reg .u64 t; cvta.to.shared.u64 t, %1; cvt.u32.u64 %0, t; }" : "=r"(a) : "l"(p));
    return a;
}
__device__ __forceinline__ void ldm_x4(uint32_t* r, uint32_t addr) {
    asm volatile("ldmatrix.sync.aligned.m8n8.x4.shared.b16 {%0,%1,%2,%3}, [%4];"
                 : "=r"(r[0]), "=r"(r[1]), "=r"(r[2]), "=r"(r[3]) : "r"(addr));
}
__device__ __forceinline__ void mma_bf16(float* d, const uint32_t* a, uint32_t b0, uint32_t b1) {
    asm volatile(
        "mma.sync.aligned.m16n8k16.row.col.f32.bf16.bf16.f32 "
        "{%0,%1,%2,%3}, {%4,%5,%6,%7}, {%8,%9}, {%0,%1,%2,%3};"
        : "+f"(d[0]), "+f"(d[1]), "+f"(d[2]), "+f"(d[3])
        : "r"(a[0]), "r"(a[1]), "r"(a[2]), "r"(a[3]), "r"(b0), "r"(b1));
}
__device__ __forceinline__ void cp16(uint32_t dst, const void* src) {
    asm volatile("cp.async.ca.shared.global [%0], [%1], 16;" :: "r"(dst), "l"(src));
}
__device__ __forceinline__ void cp_commit() { asm volatile("cp.async.commit_group;" ::: "memory"); }
template <int N>
__device__ __forceinline__ void cp_wait() { asm volatile("cp.async.wait_group %0;" :: "n"(N) : "memory"); }

__device__ __forceinline__ void split2(float x, float y, uint32_t& h, uint32_t& l) {
    __nv_bfloat16 hx = __float2bfloat16(x), hy = __float2bfloat16(y);
    __nv_bfloat162 hv; hv.x = hx; hv.y = hy;
    __nv_bfloat162 lv;
    lv.x = __float2bfloat16(x - __bfloat162float(hx));
    lv.y = __float2bfloat16(y - __bfloat162float(hy));
    h = *reinterpret_cast<uint32_t*>(&hv);
    l = *reinterpret_cast<uint32_t*>(&lv);
}

// ---------------- prep: bf16 hi/lo splits ----------------
__global__ void k_prep_w(const float* __restrict__ Wq, const float* __restrict__ Wkv,
                         const float* __restrict__ Wp) {
    int row = blockIdx.x, t = threadIdx.x;
    if (row < 768) {
        float v = (row < 256) ? Wq[row * 256 + t] : Wkv[(row - 256) * 256 + t];
        __nv_bfloat16 hi = __float2bfloat16(v);
        g_wh[row * 256 + t] = hi;
        g_wl[row * 256 + t] = __float2bfloat16(v - __bfloat162float(hi));
    } else {
        int r = row - 768;
        float v = Wp[r * 256 + t];
        __nv_bfloat16 hi = __float2bfloat16(v);
        g_pwh[r * 256 + t] = hi;
        g_pwl[r * 256 + t] = __float2bfloat16(v - __bfloat162float(hi));
    }
}

__global__ void k_xsplit(const float* __restrict__ x) {
    __shared__ float tile[32][33];
    int tx = threadIdx.x, ty = threadIdx.y;  // 32x8
    int n0 = blockIdx.x * 32, c0 = blockIdx.y * 32, b = blockIdx.z;
#pragma unroll
    for (int yy = 0; yy < 32; yy += 8)
        tile[ty + yy][tx] = x[((size_t)b * 256 + c0 + ty + yy) * 4096 + n0 + tx];
    __syncthreads();
#pragma unroll
    for (int yy = 0; yy < 32; yy += 8) {
        int nl = ty + yy;
        float v = tile[tx][nl];
        __nv_bfloat16 hi = __float2bfloat16(v);
        size_t o = ((size_t)b * 4096 + n0 + nl) * 256 + c0 + tx;
        g_xh[o] = hi;
        g_xl[o] = __float2bfloat16(v - __bfloat162float(hi));
    }
}

// ---------------- tensor-core GEMM: 128x128 CTA tiles, double-buffered k32 stages ----------------
// MODE 0: A = g_xh/g_xl, W = g_wh/g_wl (6 j-tiles) -> jt<2: q bf16 hi/lo; jt<4: g_k; else g_v
// MODE 1: A = g_oh/g_ol, W = g_pwh/g_pwl (2 j-tiles) -> transposed out + bias
template <int MODE>
__global__ __launch_bounds__(256, 2)
void k_gemm_mma(const float* __restrict__ bias, float* __restrict__ outp) {
    extern __shared__ __align__(16) char dsm[];
    float* stag = (float*)dsm;                 // epilogue staging aliases pipeline smem

    const int t = threadIdx.x;
    const int lane = t & 31, wid = t >> 5;
    const int wm = wid & 3, wn = wid >> 2;     // warp tile: 32(m) x 64(n)
    const int b = blockIdx.z;
    const int n0 = blockIdx.x * 128;
    const int jt = blockIdx.y, j0 = jt * 128;

    const __nv_bfloat16* Agh = (MODE == 0 ? g_xh : g_oh) + ((size_t)b * 4096 + n0) * 256;
    const __nv_bfloat16* Agl = (MODE == 0 ? g_xl : g_ol) + ((size_t)b * 4096 + n0) * 256;
    const __nv_bfloat16* Wgh = ((MODE == 0) ? g_wh : g_pwh) + (size_t)j0 * 256;
    const __nv_bfloat16* Wgl = ((MODE == 0) ? g_wl : g_pwl) + (size_t)j0 * 256;

    const uint32_t uS = smem_u32(dsm);

    auto load_stage = [&](int st, int kt) {
        uint32_t base = uS + st * STAGE_SZ;
        int k0 = kt * 32;
#pragma unroll
        for (int it = 0; it < 2; it++) {
            int idx = t + it * 256;
            int r = idx >> 2, ch = idx & 3;
            uint32_t off = (uint32_t)((r * KP + ch * 8) * 2);
            const size_t g = (size_t)r * 256 + k0 + ch * 8;
            cp16(base + off, Agh + g);
            cp16(base + SA_SZ + off, Agl + g);
            cp16(base + 2 * SA_SZ + off, Wgh + g);
            cp16(base + 2 * SA_SZ + SB_SZ + off, Wgl + g);
        }
    };

    const int q8 = lane >> 3, r8 = lane & 7;
    uint32_t aoff[2], boff[4];
#pragma unroll
    for (int mt = 0; mt < 2; mt++) {
        int row = wm * 32 + mt * 16 + (q8 & 1) * 8 + r8;
        aoff[mt] = (uint32_t)((row * KP + (q8 >> 1) * 8) * 2);
    }
#pragma unroll
    for (int p = 0; p < 4; p++) {
        int nrow = wn * 64 + p * 16 + (q8 >> 1) * 8 + r8;
        boff[p] = (uint32_t)((nrow * KP + (q8 & 1) * 8) * 2);
    }

    float acc[2][8][4];
#pragma unroll
    for (int mt = 0; mt < 2; mt++)
#pragma unroll
        for (int nt = 0; nt < 8; nt++)
#pragma unroll
            for (int e = 0; e < 4; e++) acc[mt][nt][e] = 0.f;

    load_stage(0, 0);
    cp_commit();

    for (int kt = 0; kt < 8; kt++) {
        cp_wait<0>();
        __syncthreads();
        if (kt < 7) {
            load_stage((kt + 1) & 1, kt + 1);
            cp_commit();
        }
        const uint32_t base = uS + (kt & 1) * STAGE_SZ;
        const uint32_t uAh = base, uAl = base + SA_SZ;
        const uint32_t uBh = base + 2 * SA_SZ, uBl = uBh + SB_SZ;
#pragma unroll
        for (int kh = 0; kh < 2; kh++) {
            uint32_t ko = (uint32_t)(kh * 32);
            uint32_t A_h[2][4], A_l[2][4];
            ldm_x4(A_h[0], uAh + aoff[0] + ko);
            ldm_x4(A_h[1], uAh + aoff[1] + ko);
            ldm_x4(A_l[0], uAl + aoff[0] + ko);
            ldm_x4(A_l[1], uAl + aoff[1] + ko);
#pragma unroll
            for (int p = 0; p < 4; p++) {
                uint32_t B_h[4], B_l[4];
                ldm_x4(B_h, uBh + boff[p] + ko);
                ldm_x4(B_l, uBl + boff[p] + ko);
#pragma unroll
                for (int mt = 0; mt < 2; mt++) {
#pragma unroll
                    for (int hf = 0; hf < 2; hf++) {
                        float* d = acc[mt][p * 2 + hf];
                        mma_bf16(d, A_h[mt], B_h[hf * 2], B_h[hf * 2 + 1]);
                        mma_bf16(d, A_h[mt], B_l[hf * 2], B_l[hf * 2 + 1]);
                        mma_bf16(d, A_l[mt], B_h[hf * 2], B_h[hf * 2 + 1]);
                    }
                }
            }
        }
        __syncthreads();
    }

    // ---- stage fragments to smem [128][SP] ----
    {
        int r0 = lane >> 2, c0 = (lane & 3) * 2;
#pragma unroll
        for (int mt = 0; mt < 2; mt++) {
#pragma unroll
            for (int nt = 0; nt < 8; nt++) {
                int row = wm * 32 + mt * 16 + r0;
                int col = wn * 64 + nt * 8 + c0;
                stag[row * SP + col]           = acc[mt][nt][0];
                stag[row * SP + col + 1]       = acc[mt][nt][1];
                stag[(row + 8) * SP + col]     = acc[mt][nt][2];
                stag[(row + 8) * SP + col + 1] = acc[mt][nt][3];
            }
        }
    }
    __syncthreads();

    // ---- coalesced stores ----
    if (MODE == 0) {
        int jl = (jt & 1) * 128;
        if (jt < 2) {
            // q -> bf16 hi/lo
#pragma unroll
            for (int it = 0; it < 16; it++) {
                int idx = t + it * 256;
                int m = idx >> 5, j4 = (idx & 31) * 4;
                float4 v = *(float4*)&stag[m * SP + j4];
                uint32_t h0, l0, h1, l1;
                split2(v.x, v.y, h0, l0);
                split2(v.z, v.w, h1, l1);
                size_t off = ((size_t)b * 4096 + n0 + m) * 256 + jl + j4;
                *(uint2*)&g_qh[off] = make_uint2(h0, h1);
                *(uint2*)&g_ql[off] = make_uint2(l0, l1);
            }
        } else {
            float* dst = (jt < 4) ? g_k : g_v;
#pragma unroll
            for (int it = 0; it < 16; it++) {
                int idx = t + it * 256;
                int m = idx >> 5, j4 = (idx & 31) * 4;
                *(float4*)&dst[((size_t)b * 4096 + n0 + m) * 256 + jl + j4] =
                    *(float4*)&stag[m * SP + j4];
            }
        }
    } else {
        int m = t & 127, js = t >> 7;
#pragma unroll 8
        for (int j = js; j < 128; j += 2) {
            float v = stag[m * SP + j] + bias[j0 + j];
            outp[((size_t)b * 256 + j0 + j) * 4096 + n0 + m] = v;
        }
    }
}

// ---------------- bilinear coeffs for 7 -> 64 resize ----------------
__device__ __forceinline__ void lin7(int i, int& j0, int& j1, float& w) {
    float c = (i + 0.5f) * (7.0f / 64.0f) - 0.5f;
    float f = floorf(c);
    w = c - f;
    int j = (int)f;
    j0 = max(0, min(6, j));
    j1 = max(0, min(6, j + 1));
}

__device__ __forceinline__ float bil7(const float* img, int y0, int y1, float wy,
                                      int x0, int x1, float wx) {
    float v0 = img[y0 * 7 + x0] * (1.f - wx) + img[y0 * 7 + x1] * wx;
    float v1 = img[y1 * 7 + x0] * (1.f - wx) + img[y1 * 7 + x1] * wx;
    return v0 * (1.f - wy) + v1 * wy;
}

// ---------------- K1: position biases ----------------
__global__ void k_bias(const float* __restrict__ an, const float* __restrict__ na,
                       const float* __restrict__ ahb, const float* __restrict__ awb,
                       const float* __restrict__ hab, const float* __restrict__ wab) {
    int n = blockIdx.x * 256 + threadIdx.x;
    int a = blockIdx.y, h = blockIdx.z;
    int y = n >> 6, x = n & 63;
    int y0, y1, x0, x1; float wy, wx;
    lin7(y, y0, y1, wy);
    lin7(x, x0, x1, wx);
    const float* i1 = an + (h * AG + a) * 49;
    const float* i2 = na + (h * AG + a) * 49;
    float v1 = bil7(i1, y0, y1, wy, x0, x1, wx);
    float v2 = bil7(i2, y0, y1, wy, x0, x1, wx);
    g_bias1[(h * AG + a) * Nn + n] = v1 + ahb[(h * AG + a) * 64 + y] + awb[(h * AG + a) * 64 + x];
    g_bias2[((size_t)h * Nn + n) * B2P + a] = v2 + hab[(h * 64 + y) * AG + a] + wab[(h * 64 + x) * AG + a];
}

// ---------------- K3: adaptive avg pool q -> agent (+ scaled hi/lo split) ----------------
__global__ void k_pool() {
    int c = threadIdx.x;
    int a = blockIdx.x;
    int b = blockIdx.y;
    int p = a / 7, q = a % 7;
    int ys = (p * 64) / 7, ye = ((p + 1) * 64 + 6) / 7;
    int xs = (q * 64) / 7, xe = ((q + 1) * 64 + 6) / 7;
    float s = 0.f;
    for (int y = ys; y < ye; y++)
        for (int x = xs; x < xe; x++) {
            size_t idx = ((size_t)b * Nn + y * 64 + x) * Cc + c;
            s += __bfloat162float(g_qh[idx]) + __bfloat162float(g_ql[idx]);
        }
    float val = s * (1.0f / ((ye - ys) * (xe - xs)));
    g_agent[(b * AG + a) * Cc + c] = val;
    float sc = val * SCALE;
    __nv_bfloat16 hi = __float2bfloat16(sc);
    g_ahh[(b * AG + a) * Cc + c] = hi;
    g_ahl[(b * AG + a) * Cc + c] = __float2bfloat16(sc - __bfloat162float(hi));
}

// ---------------- K4: stage-1 flash with n-split (partials) ----------------
__global__ __launch_bounds__(256) void k_fs1() {
    __shared__ __align__(16) float ah_s[AG * HD];
    __shared__ __align__(16) float k_s[64 * 32];
    __shared__ float v_s[64][33];
    __shared__ float s_s[AG][65];
    __shared__ float m_s[AG], r_s[AG], l_s[AG];

    int sp = blockIdx.x, h = blockIdx.y, b = blockIdx.z;
    int bh = b * NH + h;
    int t = threadIdx.x;
    int ta = t >> 5, td = t & 31;

    for (int idx = t; idx < AG * HD; idx += 256)
        ah_s[idx] = g_agent[(b * AG + (idx >> 5)) * Cc + h * HD + (idx & 31)] * SCALE;
    if (t < AG) { m_s[t] = -1e30f; l_s[t] = 0.f; }
    __syncthreads();

    float acc[7];
#pragma unroll
    for (int i = 0; i < 7; i++) acc[i] = 0.f;

    const float* kb = g_k + (size_t)b * Nn * Cc + h * HD;
    const float* vb = g_v + (size_t)b * Nn * Cc + h * HD;
    const float* bias = g_bias1 + (size_t)h * AG * Nn;

    for (int tile = 0; tile < 8; tile++) {
        int n0 = sp * 512 + tile * 64;
#pragma unroll
        for (int i = 0; i < 2; i++) {
            int idx = t + i * 256;
            int r = idx >> 3, cd = idx & 7;
            float4 kk = *(const float4*)(kb + (size_t)(n0 + r) * Cc + cd * 4);
            float4 vv = *(const float4*)(vb + (size_t)(n0 + r) * Cc + cd * 4);
            *(float4*)&k_s[r * 32 + ((cd ^ (r & 7)) << 2)] = kk;
            v_s[r][cd * 4 + 0] = vv.x;
            v_s[r][cd * 4 + 1] = vv.y;
            v_s[r][cd * 4 + 2] = vv.z;
            v_s[r][cd * 4 + 3] = vv.w;
        }
        __syncthreads();
        for (int idx = t; idx < AG * 64; idx += 256) {
            int a = idx >> 6, n = idx & 63;
            int sw = n & 7;
            const float* ap = &ah_s[a * HD];
            const float* kp = &k_s[n * 32];
            float s = 0.f;
#pragma unroll
            for (int i = 0; i < 8; i++) {
                float4 w = *(const float4*)&ap[i * 4];
                float4 kk = *(const float4*)&kp[(i ^ sw) << 2];
                s += w.x * kk.x + w.y * kk.y + w.z * kk.z + w.w * kk.w;
            }
            s_s[a][n] = s + bias[a * Nn + n0 + n];
        }
        __syncthreads();
#pragma unroll
        for (int i = 0; i < 7; i++) {
            int a = ta + i * 8;
            if (a < AG) {
                float s0 = s_s[a][td], s1 = s_s[a][td + 32];
                float mx = fmaxf(s0, s1);
#pragma unroll
                for (int off = 16; off > 0; off >>= 1)
                    mx = fmaxf(mx, __shfl_xor_sync(0xFFFFFFFFu, mx, off));
                float mnew = fmaxf(m_s[a], mx);
                float e0 = __expf(s0 - mnew), e1 = __expf(s1 - mnew);
                s_s[a][td] = e0;
                s_s[a][td + 32] = e1;
                float sum = e0 + e1;
#pragma unroll
                for (int off = 16; off > 0; off >>= 1)
                    sum += __shfl_xor_sync(0xFFFFFFFFu, sum, off);
                if (td == 0) {
                    float r = __expf(m_s[a] - mnew);
                    r_s[a] = r;
                    l_s[a] = l_s[a] * r + sum;
                    m_s[a] = mnew;
                }
            }
        }
        __syncthreads();
        {
#pragma unroll
            for (int i = 0; i < 7; i++) {
                int a = ta + i * 8;
                acc[i] *= (a < AG) ? r_s[a] : 0.f;
            }
#pragma unroll 4
            for (int n = 0; n < 64; n++) {
                float vv = v_s[n][td];
#pragma unroll
                for (int i = 0; i < 7; i++) {
                    int a = ta + i * 8;
                    if (a < AG) acc[i] += s_s[a][n] * vv;
                }
            }
        }
        __syncthreads();
    }
#pragma unroll
    for (int i = 0; i < 7; i++) {
        int a = ta + i * 8;
        if (a < AG)
            g_pacc[(((size_t)bh * NSPLIT + sp) * AG + a) * HD + td] = acc[i];
    }
    if (t < AG) {
        g_pm[(bh * NSPLIT + sp) * AG + t] = m_s[t];
        g_pl[(bh * NSPLIT + sp) * AG + t] = l_s[t];
    }
}

// ---------------- K4b: combine stage-1 partials -> agent_v bf16 hi/lo ----------------
__global__ void k_fs1red() {
    int bh = blockIdx.x;
    int t = threadIdx.x;
    for (int idx = t; idx < AG * HD; idx += 256) {
        int a = idx >> 5, d = idx & 31;
        float mmax = -1e30f;
#pragma unroll
        for (int s = 0; s < NSPLIT; s++)
            mmax = fmaxf(mmax, g_pm[(bh * NSPLIT + s) * AG + a]);
        float num = 0.f, den = 0.f;
#pragma unroll
        for (int s = 0; s < NSPLIT; s++) {
            float w = __expf(g_pm[(bh * NSPLIT + s) * AG + a] - mmax);
            num += w * g_pacc[(((size_t)bh * NSPLIT + s) * AG + a) * HD + d];
            den += w * g_pl[(bh * NSPLIT + s) * AG + a];
        }
        float val = num / den;
        __nv_bfloat16 hi = __float2bfloat16(val);
        g_avh[((size_t)bh * AG + a) * HD + d] = hi;
        g_avl[((size_t)bh * AG + a) * HD + d] = __float2bfloat16(val - __bfloat162float(hi));
    }
}

// ---------------- K7: stage-2 on tensor cores ----------------
// per (n0 block of 128, h, b): S = Q·(ah*SCALE)^T + bias2 ; P = softmax_a(S) ; out = P·av
__global__ __launch_bounds__(256, 2) void k_st2_tc() {
    __shared__ __align__(16) char sraw[ST2_SMEM];
    const int t = threadIdx.x;
    const int lane = t & 31, w = t >> 5;
    const int n0 = blockIdx.x * 128, h = blockIdx.y, b = blockIdx.z;
    const int bh = b * NH + h;
    const uint32_t uS = smem_u32(sraw);

    // ---- load Q tile (128 x 32, hi/lo) ----
    {
        const __nv_bfloat16* qh = g_qh + ((size_t)b * 4096 + n0) * 256 + h * 32;
        const __nv_bfloat16* ql = g_ql + ((size_t)b * 4096 + n0) * 256 + h * 32;
#pragma unroll
        for (int it = 0; it < 2; it++) {
            int idx = t + it * 256;
            int r = idx >> 2, ch = idx & 3;
            uint32_t off = (uint32_t)((r * 40 + ch * 8) * 2);
            *(uint4*)(sraw + OFF_QH + off) = *(const uint4*)(qh + (size_t)r * 256 + ch * 8);
            *(uint4*)(sraw + OFF_QL + off) = *(const uint4*)(ql + (size_t)r * 256 + ch * 8);
        }
    }
    // ---- load ah tile (64 x 32, rows >= 49 zero) ----
    {
        int r = t >> 2, ch = t & 3;
        uint32_t off = (uint32_t)((r * 40 + ch * 8) * 2);
        uint4 z = make_uint4(0, 0, 0, 0);
        uint4 vh = z, vl = z;
        if (r < AG) {
            vh = *(const uint4*)(g_ahh + ((size_t)b * AG + r) * 256 + h * 32 + ch * 8);
            vl = *(const uint4*)(g_ahl + ((size_t)b * AG + r) * 256 + h * 32 + ch * 8);
        }
        *(uint4*)(sraw + OFF_AHH + off) = vh;
        *(uint4*)(sraw + OFF_AHL + off) = vl;
    }
    // ---- load av^T (32 d-rows x 64 a-cols, pad zero) ----
#pragma unroll
    for (int it = 0; it < 8; it++) {
        int idx = t + it * 256;
        int a = idx >> 5, d = idx & 31;
        __nv_bfloat16 zh = __float2bfloat16(0.f);
        __nv_bfloat16 vh = zh, vl = zh;
        if (a < AG) {
            vh = g_avh[((size_t)bh * AG + a) * HD + d];
            vl = g_avl[((size_t)bh * AG + a) * HD + d];
        }
        ((__nv_bfloat16*)(sraw + OFF_AVH))[d * 72 + a] = vh;
        ((__nv_bfloat16*)(sraw + OFF_AVL))[d * 72 + a] = vl;
    }
    __syncthreads();

    // ---- fragment offsets ----
    const int q8 = lane >> 3, r8 = lane & 7;
    const uint32_t aoffQ = (uint32_t)(((w * 16 + (q8 & 1) * 8 + r8) * 40 + (q8 >> 1) * 8) * 2);
    uint32_t boffA[4];
#pragma unroll
    for (int p = 0; p < 4; p++)
        boffA[p] = (uint32_t)(((p * 16 + (q8 >> 1) * 8 + r8) * 40 + (q8 & 1) * 8) * 2);
    uint32_t boffV[2];
#pragma unroll
    for (int g = 0; g < 2; g++)
        boffV[g] = (uint32_t)(((g * 16 + (q8 >> 1) * 8 + r8) * 72 + (q8 & 1) * 8) * 2);

    // ---- GEMM1: c[8][4] = Q . ah^T (3-MMA hi/lo split) ----
    float c[8][4];
#pragma unroll
    for (int j = 0; j < 8; j++)
#pragma unroll
        for (int e = 0; e < 4; e++) c[j][e] = 0.f;
#pragma unroll
    for (int kk = 0; kk < 2; kk++) {
        uint32_t ko = (uint32_t)(kk * 32);
        uint32_t Ah[4], Al[4];
        ldm_x4(Ah, uS + OFF_QH + aoffQ + ko);
        ldm_x4(Al, uS + OFF_QL + aoffQ + ko);
#pragma unroll
        for (int p = 0; p < 4; p++) {
            uint32_t Bh[4], Bl[4];
            ldm_x4(Bh, uS + OFF_AHH + boffA[p] + ko);
            ldm_x4(Bl, uS + OFF_AHL + boffA[p] + ko);
#pragma unroll
            for (int hf = 0; hf < 2; hf++) {
                float* d = c[p * 2 + hf];
                mma_bf16(d, Ah, Bh[hf * 2], Bh[hf * 2 + 1]);
                mma_bf16(d, Ah, Bl[hf * 2], Bl[hf * 2 + 1]);
                mma_bf16(d, Al, Bh[hf * 2], Bh[hf * 2 + 1]);
            }
        }
    }

    // ---- bias2 add + pad masking (rows r0, r1 of this thread) ----
    const int r0 = w * 16 + (lane >> 2), r1 = r0 + 8;
    const int aq = (lane & 3) * 2;
    {
        const float* b2r0 = g_bias2 + ((size_t)h * Nn + n0 + r0) * B2P;
        const float* b2r1 = g_bias2 + ((size_t)h * Nn + n0 + r1) * B2P;
#pragma unroll
        for (int j = 0; j < 8; j++) {
            int a0 = j * 8 + aq;
            if (a0 < 48) {
                float2 u0 = *(const float2*)(b2r0 + a0);
                float2 u1 = *(const float2*)(b2r1 + a0);
                c[j][0] += u0.x; c[j][1] += u0.y;
                c[j][2] += u1.x; c[j][3] += u1.y;
            } else if (a0 == 48) {
                c[j][0] += b2r0[48]; c[j][1] = -1e30f;
                c[j][2] += b2r1[48]; c[j][3] = -1e30f;
            } else {
                c[j][0] = c[j][1] = c[j][2] = c[j][3] = -1e30f;
            }
        }
    }

    // ---- softmax over a (in-register, quad shfl) ----
    float m0 = -1e30f, m1 = -1e30f;
#pragma unroll
    for (int j = 0; j < 8; j++) {
        m0 = fmaxf(m0, fmaxf(c[j][0], c[j][1]));
        m1 = fmaxf(m1, fmaxf(c[j][2], c[j][3]));
    }
    m0 = fmaxf(m0, __shfl_xor_sync(0xFFFFFFFFu, m0, 1));
    m0 = fmaxf(m0, __shfl_xor_sync(0xFFFFFFFFu, m0, 2));
    m1 = fmaxf(m1, __shfl_xor_sync(0xFFFFFFFFu, m1, 1));
    m1 = fmaxf(m1, __shfl_xor_sync(0xFFFFFFFFu, m1, 2));
    float l0 = 0.f, l1 = 0.f;
#pragma unroll
    for (int j = 0; j < 8; j++) {
        c[j][0] = __expf(c[j][0] - m0); c[j][1] = __expf(c[j][1] - m0);
        c[j][2] = __expf(c[j][2] - m1); c[j][3] = __expf(c[j][3] - m1);
        l0 += c[j][0] + c[j][1];
        l1 += c[j][2] + c[j][3];
    }
    l0 += __shfl_xor_sync(0xFFFFFFFFu, l0, 1);
    l0 += __shfl_xor_sync(0xFFFFFFFFu, l0, 2);
    l1 += __shfl_xor_sync(0xFFFFFFFFu, l1, 1);
    l1 += __shfl_xor_sync(0xFFFFFFFFu, l1, 2);
    const float rl0 = 1.0f / l0, rl1 = 1.0f / l1;

    // ---- GEMM2: out = (P/l) . av  (P from c-frags, hi/lo split) ----
    float o[4][4];
#pragma unroll
    for (int g = 0; g < 4; g++)
#pragma unroll
        for (int e = 0; e < 4; e++) o[g][e] = 0.f;
#pragma unroll
    for (int kk = 0; kk < 4; kk++) {
        uint32_t ah2[4], al2[4];
        {
            float p00 = c[2 * kk][0] * rl0, p01 = c[2 * kk][1] * rl0;
            float p02 = c[2 * kk][2] * rl1, p03 = c[2 * kk][3] * rl1;
            float p10 = c[2 * kk + 1][0] * rl0, p11 = c[2 * kk + 1][1] * rl0;
            float p12 = c[2 * kk + 1][2] * rl1, p13 = c[2 * kk + 1][3] * rl1;
            split2(p00, p01, ah2[0], al2[0]);
            split2(p02, p03, ah2[1], al2[1]);
            split2(p10, p11, ah2[2], al2[2]);
            split2(p12, p13, ah2[3], al2[3]);
        }
        uint32_t ko = (uint32_t)(kk * 32);
#pragma unroll
        for (int g = 0; g < 2; g++) {
            uint32_t Bh[4], Bl[4];
            ldm_x4(Bh, uS + OFF_AVH + boffV[g] + ko);
            ldm_x4(Bl, uS + OFF_AVL + boffV[g] + ko);
#pragma unroll
            for (int hf = 0; hf < 2; hf++) {
                float* d = o[g * 2 + hf];
                mma_bf16(d, ah2, Bh[hf * 2], Bh[hf * 2 + 1]);
                mma_bf16(d, ah2, Bl[hf * 2], Bl[hf * 2 + 1]);
                mma_bf16(d, al2, Bh[hf * 2], Bh[hf * 2 + 1]);
            }
        }
    }

    // ---- stage + coalesced store ----
    __syncthreads();
    float* stg = (float*)sraw;  // 128 x 36 fp32 (aliases Q region)
#pragma unroll
    for (int g = 0; g < 4; g++) {
        int dcol = g * 8 + aq;
        stg[r0 * 36 + dcol]     = o[g][0];
        stg[r0 * 36 + dcol + 1] = o[g][1];
        stg[r1 * 36 + dcol]     = o[g][2];
        stg[r1 * 36 + dcol + 1] = o[g][3];
    }
    __syncthreads();
#pragma unroll
    for (int it = 0; it < 4; it++) {
        int idx = t + it * 256;
        int m = idx >> 3, d4 = (idx & 7) * 4;
        *(float4*)&g_o[((size_t)b * 4096 + n0 + m) * 256 + h * 32 + d4] =
            *(float4*)&stg[m * 36 + d4];
    }
}

// ---------------- K8: depthwise 3x3 conv + bf16 hi/lo split of (o + dw) ----------------
__global__ void k_dw(const float* __restrict__ Wd, const float* __restrict__ bd) {
    int c = threadIdx.x;
    int n = blockIdx.x, b = blockIdx.y;
    int y = n >> 6, x = n & 63;
    float s = bd[c];
#pragma unroll
    for (int dy = -1; dy <= 1; dy++) {
        int yy = y + dy;
        if (yy < 0 || yy > 63) continue;
#pragma unroll
        for (int dx = -1; dx <= 1; dx++) {
            int xx = x + dx;
            if (xx < 0 || xx > 63) continue;
            s += g_v[((size_t)b * Nn + yy * 64 + xx) * Cc + c] * Wd[c * 9 + (dy + 1) * 3 + (dx + 1)];
        }
    }
    size_t idx = ((size_t)b * Nn + n) * Cc + c;
    float v = g_o[idx] + s;
    __nv_bfloat16 hi = __float2bfloat16(v);
    g_oh[idx] = hi;
    g_ol[idx] = __float2bfloat16(v - __bfloat162float(hi));
}

// ---------------- launch ----------------
extern "C" void kernel_launch(void* const* d_in, const int* in_sizes, int n_in,
                              void* d_out, int out_size) {
    const float* x     = (const float*)d_in[0];
    const float* Wq    = (const float*)d_in[1];
    const float* Wkv   = (const float*)d_in[2];
    const float* Wproj = (const float*)d_in[3];
    const float* bproj = (const float*)d_in[4];
    const float* Wdwc  = (const float*)d_in[5];
    const float* bdwc  = (const float*)d_in[6];
    const float* an    = (const float*)d_in[7];
    const float* na    = (const float*)d_in[8];
    const float* ahb   = (const float*)d_in[9];
    const float* awb   = (const float*)d_in[10];
    const float* hab   = (const float*)d_in[11];
    const float* wab   = (const float*)d_in[12];
    float* out = (float*)d_out;

    cudaFuncSetAttribute(k_gemm_mma<0>, cudaFuncAttributeMaxDynamicSharedMemorySize, SMEM_DYN);
    cudaFuncSetAttribute(k_gemm_mma<1>, cudaFuncAttributeMaxDynamicSharedMemorySize, SMEM_DYN);

    k_bias   <<<dim3(Nn / 256, AG, NH), 256>>>(an, na, ahb, awb, hab, wab);
    k_prep_w <<<1024, 256>>>(Wq, Wkv, Wproj);
    k_xsplit <<<dim3(128, 8, Bb), dim3(32, 8)>>>(x);
    k_gemm_mma<0><<<dim3(32, 6, Bb), 256, SMEM_DYN>>>(nullptr, nullptr);
    k_pool   <<<dim3(AG, Bb), 256>>>();
    k_fs1    <<<dim3(NSPLIT, NH, Bb), 256>>>();
    k_fs1red <<<Bb * NH, 256>>>();
    k_st2_tc <<<dim3(Nn / 128, NH, Bb), 256>>>();
    k_dw     <<<dim3(Nn, Bb), 256>>>(Wdwc, bdwc);
    k_gemm_mma<1><<<dim3(32, 2, Bb), 256, SMEM_DYN>>>(bproj, out);
}

// round 14
// speedup vs baseline: 1.8440x; 1.1073x over previous
#include <cuda_runtime.h>
#include <cuda_bf16.h>
#include <cstdint>

// ---------------- constants ----------------
namespace {
constexpr int Bb = 16;      // batch
constexpr int Cc = 256;     // channels
constexpr int Nn = 4096;    // H*W
constexpr int NH = 8;       // heads
constexpr int HD = 32;      // head dim
constexpr int AG = 49;      // agent tokens
constexpr int NSPLIT = 8;   // stage-1 n-splits
constexpr int B2P = 52;     // bias2 pitch (floats) for aligned float2 fragment loads
constexpr float SCALE = 0.17677669529663689f;  // 32^-0.5

// GEMM smem: per stage A(hi|lo) 128x32k pitch40 + B(hi|lo) 128x32k pitch40
constexpr int KP = 40;                          // k-pitch in bf16 (80B rows: conflict-free ldmatrix)
constexpr unsigned SA_SZ = 128 * KP * 2;        // 10240 per half
constexpr unsigned SB_SZ = 128 * KP * 2;        // 10240 per half
constexpr unsigned STAGE_SZ = 2 * SA_SZ + 2 * SB_SZ;  // 40960
constexpr unsigned SMEM_DYN = 2 * STAGE_SZ;     // 81920 (epilogue staging aliases this)
constexpr int SP = 136;                         // epilogue staging pitch (fp32)

// st2 smem offsets (bytes) — dynamic smem
constexpr unsigned OFF_QH  = 0;                 // 128x40 bf16
constexpr unsigned OFF_QL  = 10240;
constexpr unsigned OFF_AHH = 20480;             // 64x40 bf16
constexpr unsigned OFF_AHL = 25600;
constexpr unsigned OFF_AVH = 30720;             // 32x72 bf16 (av^T)
constexpr unsigned OFF_AVL = 35328;
constexpr unsigned OFF_VH  = 39936;             // 4*64 x 33-pitch fp32 v halo = 33792
constexpr unsigned OFF_WD  = 73728;             // 32*9 fp32 = 1152
constexpr unsigned OFF_BD  = 74880;             // 32 fp32 = 128
constexpr unsigned ST2_DYN = 75008;
}

// ---------------- scratch (device globals; no allocation allowed) ----------------
__device__ float g_k[Bb * Nn * Cc];
__device__ float g_v[Bb * Nn * Cc];
__device__ float g_agent[Bb * AG * Cc];
__device__ float g_bias1[NH * AG * Nn];        // stage-1 bias [h][a][n]
__device__ float g_bias2[NH * Nn * B2P];       // stage-2 bias [h][n][a] pitch 52
__device__ float g_pacc[Bb * NH * NSPLIT * AG * HD];  // stage-1 partial acc
__device__ float g_pm[Bb * NH * NSPLIT * AG];
__device__ float g_pl[Bb * NH * NSPLIT * AG];

// bf16 hi/lo split operands for tensor-core work
__device__ __nv_bfloat16 g_xh[Bb * Nn * Cc];   // xt row-major [b][n][c]
__device__ __nv_bfloat16 g_xl[Bb * Nn * Cc];
__device__ __nv_bfloat16 g_qh[Bb * Nn * Cc];   // q hi/lo (from qkv GEMM epilogue)
__device__ __nv_bfloat16 g_ql[Bb * Nn * Cc];
__device__ __nv_bfloat16 g_oh[Bb * Nn * Cc];   // attention-out + dw, hi/lo (from st2 epilogue)
__device__ __nv_bfloat16 g_ol[Bb * Nn * Cc];
__device__ __nv_bfloat16 g_ahh[Bb * AG * Cc];  // agent*SCALE hi/lo
__device__ __nv_bfloat16 g_ahl[Bb * AG * Cc];
__device__ __nv_bfloat16 g_avh[Bb * NH * AG * HD];  // agent_v hi/lo
__device__ __nv_bfloat16 g_avl[Bb * NH * AG * HD];
__device__ __nv_bfloat16 g_wh[768 * Cc];       // qkv weights combined [q|k|v]
__device__ __nv_bfloat16 g_wl[768 * Cc];
__device__ __nv_bfloat16 g_pwh[Cc * Cc];       // proj weights
__device__ __nv_bfloat16 g_pwl[Cc * Cc];

// ---------------- PTX helpers (baseline sm_80+ features only) ----------------
__device__ __forceinline__ uint32_t smem_u32(const void* p) {
    uint32_t a;
    asm("{ .reg .u64 t; cvta.to.shared.u64 t, %1; cvt.u32.u64 %0, t; }" : "=r"(a) : "l"(p));
    return a;
}
__device__ __forceinline__ void ldm_x4(uint32_t* r, uint32_t addr) {
    asm volatile("ldmatrix.sync.aligned.m8n8.x4.shared.b16 {%0,%1,%2,%3}, [%4];"
                 : "=r"(r[0]), "=r"(r[1]), "=r"(r[2]), "=r"(r[3]) : "r"(addr));
}
__device__ __forceinline__ void mma_bf16(float* d, const uint32_t* a, uint32_t b0, uint32_t b1) {
    asm volatile(
        "mma.sync.aligned.m16n8k16.row.col.f32.bf16.bf16.f32 "
        "{%0,%1,%2,%3}, {%4,%5,%6,%7}, {%8,%9}, {%0,%1,%2,%3};"
        : "+f"(d[0]), "+f"(d[1]), "+f"(d[2]), "+f"(d[3])
        : "r"(a[0]), "r"(a[1]), "r"(a[2]), "r"(a[3]), "r"(b0), "r"(b1));
}
__device__ __forceinline__ void cp16(uint32_t dst, const void* src) {
    asm volatile("cp.async.ca.shared.global [%0], [%1], 16;" :: "r"(dst), "l"(src));
}
__device__ __forceinline__ void cp_commit() { asm volatile("cp.async.commit_group;" ::: "memory"); }
template <int N>
__device__ __forceinline__ void cp_wait() { asm volatile("cp.async.wait_group %0;" :: "n"(N) : "memory"); }

__device__ __forceinline__ void split2(float x, float y, uint32_t& h, uint32_t& l) {
    __nv_bfloat16 hx = __float2bfloat16(x), hy = __float2bfloat16(y);
    __nv_bfloat162 hv; hv.x = hx; hv.y = hy;
    __nv_bfloat162 lv;
    lv.x = __float2bfloat16(x - __bfloat162float(hx));
    lv.y = __float2bfloat16(y - __bfloat162float(hy));
    h = *reinterpret_cast<uint32_t*>(&hv);
    l = *reinterpret_cast<uint32_t*>(&lv);
}

// ---------------- prep: bf16 hi/lo splits ----------------
__global__ void k_prep_w(const float* __restrict__ Wq, const float* __restrict__ Wkv,
                         const float* __restrict__ Wp) {
    int row = blockIdx.x, t = threadIdx.x;
    if (row < 768) {
        float v = (row < 256) ? Wq[row * 256 + t] : Wkv[(row - 256) * 256 + t];
        __nv_bfloat16 hi = __float2bfloat16(v);
        g_wh[row * 256 + t] = hi;
        g_wl[row * 256 + t] = __float2bfloat16(v - __bfloat162float(hi));
    } else {
        int r = row - 768;
        float v = Wp[r * 256 + t];
        __nv_bfloat16 hi = __float2bfloat16(v);
        g_pwh[r * 256 + t] = hi;
        g_pwl[r * 256 + t] = __float2bfloat16(v - __bfloat162float(hi));
    }
}

__global__ void k_xsplit(const float* __restrict__ x) {
    __shared__ float tile[32][33];
    int tx = threadIdx.x, ty = threadIdx.y;  // 32x8
    int n0 = blockIdx.x * 32, c0 = blockIdx.y * 32, b = blockIdx.z;
#pragma unroll
    for (int yy = 0; yy < 32; yy += 8)
        tile[ty + yy][tx] = x[((size_t)b * 256 + c0 + ty + yy) * 4096 + n0 + tx];
    __syncthreads();
#pragma unroll
    for (int yy = 0; yy < 32; yy += 8) {
        int nl = ty + yy;
        float v = tile[tx][nl];
        __nv_bfloat16 hi = __float2bfloat16(v);
        size_t o = ((size_t)b * 4096 + n0 + nl) * 256 + c0 + tx;
        g_xh[o] = hi;
        g_xl[o] = __float2bfloat16(v - __bfloat162float(hi));
    }
}

// ---------------- tensor-core GEMM: 128x128 CTA tiles, double-buffered k32 stages ----------------
// MODE 0: A = g_xh/g_xl, W = g_wh/g_wl (6 j-tiles) -> jt<2: q bf16 hi/lo; jt<4: g_k; else g_v
// MODE 1: A = g_oh/g_ol, W = g_pwh/g_pwl (2 j-tiles) -> transposed out + bias
template <int MODE>
__global__ __launch_bounds__(256, 2)
void k_gemm_mma(const float* __restrict__ bias, float* __restrict__ outp) {
    extern __shared__ __align__(16) char dsm[];
    float* stag = (float*)dsm;                 // epilogue staging aliases pipeline smem

    const int t = threadIdx.x;
    const int lane = t & 31, wid = t >> 5;
    const int wm = wid & 3, wn = wid >> 2;     // warp tile: 32(m) x 64(n)
    const int b = blockIdx.z;
    const int n0 = blockIdx.x * 128;
    const int jt = blockIdx.y, j0 = jt * 128;

    const __nv_bfloat16* Agh = (MODE == 0 ? g_xh : g_oh) + ((size_t)b * 4096 + n0) * 256;
    const __nv_bfloat16* Agl = (MODE == 0 ? g_xl : g_ol) + ((size_t)b * 4096 + n0) * 256;
    const __nv_bfloat16* Wgh = ((MODE == 0) ? g_wh : g_pwh) + (size_t)j0 * 256;
    const __nv_bfloat16* Wgl = ((MODE == 0) ? g_wl : g_pwl) + (size_t)j0 * 256;

    const uint32_t uS = smem_u32(dsm);

    auto load_stage = [&](int st, int kt) {
        uint32_t base = uS + st * STAGE_SZ;
        int k0 = kt * 32;
#pragma unroll
        for (int it = 0; it < 2; it++) {
            int idx = t + it * 256;
            int r = idx >> 2, ch = idx & 3;
            uint32_t off = (uint32_t)((r * KP + ch * 8) * 2);
            const size_t g = (size_t)r * 256 + k0 + ch * 8;
            cp16(base + off, Agh + g);
            cp16(base + SA_SZ + off, Agl + g);
            cp16(base + 2 * SA_SZ + off, Wgh + g);
            cp16(base + 2 * SA_SZ + SB_SZ + off, Wgl + g);
        }
    };

    const int q8 = lane >> 3, r8 = lane & 7;
    uint32_t aoff[2], boff[4];
#pragma unroll
    for (int mt = 0; mt < 2; mt++) {
        int row = wm * 32 + mt * 16 + (q8 & 1) * 8 + r8;
        aoff[mt] = (uint32_t)((row * KP + (q8 >> 1) * 8) * 2);
    }
#pragma unroll
    for (int p = 0; p < 4; p++) {
        int nrow = wn * 64 + p * 16 + (q8 >> 1) * 8 + r8;
        boff[p] = (uint32_t)((nrow * KP + (q8 & 1) * 8) * 2);
    }

    float acc[2][8][4];
#pragma unroll
    for (int mt = 0; mt < 2; mt++)
#pragma unroll
        for (int nt = 0; nt < 8; nt++)
#pragma unroll
            for (int e = 0; e < 4; e++) acc[mt][nt][e] = 0.f;

    load_stage(0, 0);
    cp_commit();

    for (int kt = 0; kt < 8; kt++) {
        cp_wait<0>();
        __syncthreads();
        if (kt < 7) {
            load_stage((kt + 1) & 1, kt + 1);
            cp_commit();
        }
        const uint32_t base = uS + (kt & 1) * STAGE_SZ;
        const uint32_t uAh = base, uAl = base + SA_SZ;
        const uint32_t uBh = base + 2 * SA_SZ, uBl = uBh + SB_SZ;
#pragma unroll
        for (int kh = 0; kh < 2; kh++) {
            uint32_t ko = (uint32_t)(kh * 32);
            uint32_t A_h[2][4], A_l[2][4];
            ldm_x4(A_h[0], uAh + aoff[0] + ko);
            ldm_x4(A_h[1], uAh + aoff[1] + ko);
            ldm_x4(A_l[0], uAl + aoff[0] + ko);
            ldm_x4(A_l[1], uAl + aoff[1] + ko);
#pragma unroll
            for (int p = 0; p < 4; p++) {
                uint32_t B_h[4], B_l[4];
                ldm_x4(B_h, uBh + boff[p] + ko);
                ldm_x4(B_l, uBl + boff[p] + ko);
#pragma unroll
                for (int mt = 0; mt < 2; mt++) {
#pragma unroll
                    for (int hf = 0; hf < 2; hf++) {
                        float* d = acc[mt][p * 2 + hf];
                        mma_bf16(d, A_h[mt], B_h[hf * 2], B_h[hf * 2 + 1]);
                        mma_bf16(d, A_h[mt], B_l[hf * 2], B_l[hf * 2 + 1]);
                        mma_bf16(d, A_l[mt], B_h[hf * 2], B_h[hf * 2 + 1]);
                    }
                }
            }
        }
        __syncthreads();
    }

    // ---- stage fragments to smem [128][SP] ----
    {
        int r0 = lane >> 2, c0 = (lane & 3) * 2;
#pragma unroll
        for (int mt = 0; mt < 2; mt++) {
#pragma unroll
            for (int nt = 0; nt < 8; nt++) {
                int row = wm * 32 + mt * 16 + r0;
                int col = wn * 64 + nt * 8 + c0;
                stag[row * SP + col]           = acc[mt][nt][0];
                stag[row * SP + col + 1]       = acc[mt][nt][1];
                stag[(row + 8) * SP + col]     = acc[mt][nt][2];
                stag[(row + 8) * SP + col + 1] = acc[mt][nt][3];
            }
        }
    }
    __syncthreads();

    // ---- coalesced stores ----
    if (MODE == 0) {
        int jl = (jt & 1) * 128;
        if (jt < 2) {
#pragma unroll
            for (int it = 0; it < 16; it++) {
                int idx = t + it * 256;
                int m = idx >> 5, j4 = (idx & 31) * 4;
                float4 v = *(float4*)&stag[m * SP + j4];
                uint32_t h0, l0, h1, l1;
                split2(v.x, v.y, h0, l0);
                split2(v.z, v.w, h1, l1);
                size_t off = ((size_t)b * 4096 + n0 + m) * 256 + jl + j4;
                *(uint2*)&g_qh[off] = make_uint2(h0, h1);
                *(uint2*)&g_ql[off] = make_uint2(l0, l1);
            }
        } else {
            float* dst = (jt < 4) ? g_k : g_v;
#pragma unroll
            for (int it = 0; it < 16; it++) {
                int idx = t + it * 256;
                int m = idx >> 5, j4 = (idx & 31) * 4;
                *(float4*)&dst[((size_t)b * 4096 + n0 + m) * 256 + jl + j4] =
                    *(float4*)&stag[m * SP + j4];
            }
        }
    } else {
        int m = t & 127, js = t >> 7;
#pragma unroll 8
        for (int j = js; j < 128; j += 2) {
            float v = stag[m * SP + j] + bias[j0 + j];
            outp[((size_t)b * 256 + j0 + j) * 4096 + n0 + m] = v;
        }
    }
}

// ---------------- bilinear coeffs for 7 -> 64 resize ----------------
__device__ __forceinline__ void lin7(int i, int& j0, int& j1, float& w) {
    float c = (i + 0.5f) * (7.0f / 64.0f) - 0.5f;
    float f = floorf(c);
    w = c - f;
    int j = (int)f;
    j0 = max(0, min(6, j));
    j1 = max(0, min(6, j + 1));
}

__device__ __forceinline__ float bil7(const float* img, int y0, int y1, float wy,
                                      int x0, int x1, float wx) {
    float v0 = img[y0 * 7 + x0] * (1.f - wx) + img[y0 * 7 + x1] * wx;
    float v1 = img[y1 * 7 + x0] * (1.f - wx) + img[y1 * 7 + x1] * wx;
    return v0 * (1.f - wy) + v1 * wy;
}

// ---------------- K1: position biases ----------------
__global__ void k_bias(const float* __restrict__ an, const float* __restrict__ na,
                       const float* __restrict__ ahb, const float* __restrict__ awb,
                       const float* __restrict__ hab, const float* __restrict__ wab) {
    int n = blockIdx.x * 256 + threadIdx.x;
    int a = blockIdx.y, h = blockIdx.z;
    int y = n >> 6, x = n & 63;
    int y0, y1, x0, x1; float wy, wx;
    lin7(y, y0, y1, wy);
    lin7(x, x0, x1, wx);
    const float* i1 = an + (h * AG + a) * 49;
    const float* i2 = na + (h * AG + a) * 49;
    float v1 = bil7(i1, y0, y1, wy, x0, x1, wx);
    float v2 = bil7(i2, y0, y1, wy, x0, x1, wx);
    g_bias1[(h * AG + a) * Nn + n] = v1 + ahb[(h * AG + a) * 64 + y] + awb[(h * AG + a) * 64 + x];
    g_bias2[((size_t)h * Nn + n) * B2P + a] = v2 + hab[(h * 64 + y) * AG + a] + wab[(h * 64 + x) * AG + a];
}

// ---------------- K3: adaptive avg pool q -> agent (+ scaled hi/lo split) ----------------
__global__ void k_pool() {
    int c = threadIdx.x;
    int a = blockIdx.x;
    int b = blockIdx.y;
    int p = a / 7, q = a % 7;
    int ys = (p * 64) / 7, ye = ((p + 1) * 64 + 6) / 7;
    int xs = (q * 64) / 7, xe = ((q + 1) * 64 + 6) / 7;
    float s = 0.f;
    for (int y = ys; y < ye; y++)
        for (int x = xs; x < xe; x++) {
            size_t idx = ((size_t)b * Nn + y * 64 + x) * Cc + c;
            s += __bfloat162float(g_qh[idx]) + __bfloat162float(g_ql[idx]);
        }
    float val = s * (1.0f / ((ye - ys) * (xe - xs)));
    g_agent[(b * AG + a) * Cc + c] = val;
    float sc = val * SCALE;
    __nv_bfloat16 hi = __float2bfloat16(sc);
    g_ahh[(b * AG + a) * Cc + c] = hi;
    g_ahl[(b * AG + a) * Cc + c] = __float2bfloat16(sc - __bfloat162float(hi));
}

// ---------------- K4: stage-1 flash with n-split (partials) ----------------
__global__ __launch_bounds__(256) void k_fs1() {
    __shared__ __align__(16) float ah_s[AG * HD];
    __shared__ __align__(16) float k_s[64 * 32];
    __shared__ float v_s[64][33];
    __shared__ __align__(16) float s_s[AG][68];
    __shared__ float m_s[AG], r_s[AG], l_s[AG];

    int sp = blockIdx.x, h = blockIdx.y, b = blockIdx.z;
    int bh = b * NH + h;
    int t = threadIdx.x;
    int ta = t >> 5, td = t & 31;

    for (int idx = t; idx < AG * HD; idx += 256)
        ah_s[idx] = g_agent[(b * AG + (idx >> 5)) * Cc + h * HD + (idx & 31)] * SCALE;
    if (t < AG) { m_s[t] = -1e30f; l_s[t] = 0.f; }
    __syncthreads();

    float acc[7];
#pragma unroll
    for (int i = 0; i < 7; i++) acc[i] = 0.f;

    const float* kb = g_k + (size_t)b * Nn * Cc + h * HD;
    const float* vb = g_v + (size_t)b * Nn * Cc + h * HD;
    const float* bias = g_bias1 + (size_t)h * AG * Nn;

    for (int tile = 0; tile < 8; tile++) {
        int n0 = sp * 512 + tile * 64;
#pragma unroll
        for (int i = 0; i < 2; i++) {
            int idx = t + i * 256;
            int r = idx >> 3, cd = idx & 7;
            float4 kk = *(const float4*)(kb + (size_t)(n0 + r) * Cc + cd * 4);
            float4 vv = *(const float4*)(vb + (size_t)(n0 + r) * Cc + cd * 4);
            *(float4*)&k_s[r * 32 + ((cd ^ (r & 7)) << 2)] = kk;
            v_s[r][cd * 4 + 0] = vv.x;
            v_s[r][cd * 4 + 1] = vv.y;
            v_s[r][cd * 4 + 2] = vv.z;
            v_s[r][cd * 4 + 3] = vv.w;
        }
        __syncthreads();
        for (int idx = t; idx < AG * 64; idx += 256) {
            int a = idx >> 6, n = idx & 63;
            int sw = n & 7;
            const float* ap = &ah_s[a * HD];
            const float* kp = &k_s[n * 32];
            float s = 0.f;
#pragma unroll
            for (int i = 0; i < 8; i++) {
                float4 w = *(const float4*)&ap[i * 4];
                float4 kk = *(const float4*)&kp[(i ^ sw) << 2];
                s += w.x * kk.x + w.y * kk.y + w.z * kk.z + w.w * kk.w;
            }
            s_s[a][n] = s + bias[a * Nn + n0 + n];
        }
        __syncthreads();
#pragma unroll
        for (int i = 0; i < 7; i++) {
            int a = ta + i * 8;
            if (a < AG) {
                float s0 = s_s[a][td], s1 = s_s[a][td + 32];
                float mx = fmaxf(s0, s1);
#pragma unroll
                for (int off = 16; off > 0; off >>= 1)
                    mx = fmaxf(mx, __shfl_xor_sync(0xFFFFFFFFu, mx, off));
                float mnew = fmaxf(m_s[a], mx);
                float e0 = __expf(s0 - mnew), e1 = __expf(s1 - mnew);
                s_s[a][td] = e0;
                s_s[a][td + 32] = e1;
                float sum = e0 + e1;
#pragma unroll
                for (int off = 16; off > 0; off >>= 1)
                    sum += __shfl_xor_sync(0xFFFFFFFFu, sum, off);
                if (td == 0) {
                    float r = __expf(m_s[a] - mnew);
                    r_s[a] = r;
                    l_s[a] = l_s[a] * r + sum;
                    m_s[a] = mnew;
                }
            }
        }
        __syncthreads();
        // P@V: float4 score loads, v in registers
        {
#pragma unroll
            for (int i = 0; i < 7; i++) {
                int a = ta + i * 8;
                acc[i] *= (a < AG) ? r_s[a] : 0.f;
            }
#pragma unroll 2
            for (int n4 = 0; n4 < 16; n4++) {
                int nb = n4 * 4;
                float v0 = v_s[nb][td], v1 = v_s[nb + 1][td];
                float v2 = v_s[nb + 2][td], v3 = v_s[nb + 3][td];
#pragma unroll
                for (int i = 0; i < 7; i++) {
                    int a = ta + i * 8;
                    if (a < AG) {
                        float4 s4 = *(const float4*)&s_s[a][nb];
                        acc[i] += s4.x * v0 + s4.y * v1 + s4.z * v2 + s4.w * v3;
                    }
                }
            }
        }
        __syncthreads();
    }
#pragma unroll
    for (int i = 0; i < 7; i++) {
        int a = ta + i * 8;
        if (a < AG)
            g_pacc[(((size_t)bh * NSPLIT + sp) * AG + a) * HD + td] = acc[i];
    }
    if (t < AG) {
        g_pm[(bh * NSPLIT + sp) * AG + t] = m_s[t];
        g_pl[(bh * NSPLIT + sp) * AG + t] = l_s[t];
    }
}

// ---------------- K4b: combine stage-1 partials -> agent_v bf16 hi/lo ----------------
__global__ void k_fs1red() {
    int bh = blockIdx.x;
    int t = threadIdx.x;
    for (int idx = t; idx < AG * HD; idx += 256) {
        int a = idx >> 5, d = idx & 31;
        float mmax = -1e30f;
#pragma unroll
        for (int s = 0; s < NSPLIT; s++)
            mmax = fmaxf(mmax, g_pm[(bh * NSPLIT + s) * AG + a]);
        float num = 0.f, den = 0.f;
#pragma unroll
        for (int s = 0; s < NSPLIT; s++) {
            float w = __expf(g_pm[(bh * NSPLIT + s) * AG + a] - mmax);
            num += w * g_pacc[(((size_t)bh * NSPLIT + s) * AG + a) * HD + d];
            den += w * g_pl[(bh * NSPLIT + s) * AG + a];
        }
        float val = num / den;
        __nv_bfloat16 hi = __float2bfloat16(val);
        g_avh[((size_t)bh * AG + a) * HD + d] = hi;
        g_avl[((size_t)bh * AG + a) * HD + d] = __float2bfloat16(val - __bfloat162float(hi));
    }
}

// ---------------- K7: stage-2 on tensor cores + fused depthwise conv epilogue ----------------
// per (n0 block of 128, h, b): S = Q·(ah*SCALE)^T + bias2 ; P = softmax_a(S) ;
// out = P·av + dwconv(v)[channels 32h..32h+32] -> g_oh/g_ol directly
__global__ __launch_bounds__(256, 2) void k_st2_tc(const float* __restrict__ Wd,
                                                   const float* __restrict__ bdv) {
    extern __shared__ __align__(16) char sraw[];
    const int t = threadIdx.x;
    const int lane = t & 31, w = t >> 5;
    const int n0 = blockIdx.x * 128, h = blockIdx.y, b = blockIdx.z;
    const int bh = b * NH + h;
    const int y0 = n0 >> 6;                  // block covers image rows y0, y0+1
    const uint32_t uS = smem_u32(sraw);
    float* vh_s = (float*)(sraw + OFF_VH);   // [4 rows][64 x] pitch 33 fp32
    float* wd_s = (float*)(sraw + OFF_WD);   // [32][9]
    float* bd_s = (float*)(sraw + OFF_BD);   // [32]

    // ---- load Q tile (128 x 32, hi/lo) ----
    {
        const __nv_bfloat16* qh = g_qh + ((size_t)b * 4096 + n0) * 256 + h * 32;
        const __nv_bfloat16* ql = g_ql + ((size_t)b * 4096 + n0) * 256 + h * 32;
#pragma unroll
        for (int it = 0; it < 2; it++) {
            int idx = t + it * 256;
            int r = idx >> 2, ch = idx & 3;
            uint32_t off = (uint32_t)((r * 40 + ch * 8) * 2);
            *(uint4*)(sraw + OFF_QH + off) = *(const uint4*)(qh + (size_t)r * 256 + ch * 8);
            *(uint4*)(sraw + OFF_QL + off) = *(const uint4*)(ql + (size_t)r * 256 + ch * 8);
        }
    }
    // ---- load ah tile (64 x 32, rows >= 49 zero) ----
    {
        int r = t >> 2, ch = t & 3;
        uint32_t off = (uint32_t)((r * 40 + ch * 8) * 2);
        uint4 z = make_uint4(0, 0, 0, 0);
        uint4 vh = z, vl = z;
        if (r < AG) {
            vh = *(const uint4*)(g_ahh + ((size_t)b * AG + r) * 256 + h * 32 + ch * 8);
            vl = *(const uint4*)(g_ahl + ((size_t)b * AG + r) * 256 + h * 32 + ch * 8);
        }
        *(uint4*)(sraw + OFF_AHH + off) = vh;
        *(uint4*)(sraw + OFF_AHL + off) = vl;
    }
    // ---- load av^T (32 d-rows x 64 a-cols, pad zero) ----
#pragma unroll
    for (int it = 0; it < 8; it++) {
        int idx = t + it * 256;
        int a = idx >> 5, d = idx & 31;
        __nv_bfloat16 zh = __float2bfloat16(0.f);
        __nv_bfloat16 vh = zh, vl = zh;
        if (a < AG) {
            vh = g_avh[((size_t)bh * AG + a) * HD + d];
            vl = g_avl[((size_t)bh * AG + a) * HD + d];
        }
        ((__nv_bfloat16*)(sraw + OFF_AVH))[d * 72 + a] = vh;
        ((__nv_bfloat16*)(sraw + OFF_AVL))[d * 72 + a] = vl;
    }
    // ---- load v halo (rows y0-1..y0+2, 32 channels of this head) ----
#pragma unroll
    for (int it = 0; it < 32; it++) {
        int idx = t + it * 256;              // 8192 = 4*64*32
        int rr = idx >> 11;
        int rem = idx & 2047;
        int xx = rem >> 5, c = rem & 31;
        int yy = y0 - 1 + rr;
        float vv = 0.f;
        if (yy >= 0 && yy <= 63)
            vv = g_v[((size_t)b * 4096 + yy * 64 + xx) * 256 + h * 32 + c];
        vh_s[(rr * 64 + xx) * 33 + c] = vv;
    }
    for (int i = t; i < 288; i += 256) wd_s[i] = Wd[h * 288 + i];
    if (t < 32) bd_s[t] = bdv[h * 32 + t];
    __syncthreads();

    // ---- fragment offsets ----
    const int q8 = lane >> 3, r8 = lane & 7;
    const uint32_t aoffQ = (uint32_t)(((w * 16 + (q8 & 1) * 8 + r8) * 40 + (q8 >> 1) * 8) * 2);
    uint32_t boffA[4];
#pragma unroll
    for (int p = 0; p < 4; p++)
        boffA[p] = (uint32_t)(((p * 16 + (q8 >> 1) * 8 + r8) * 40 + (q8 & 1) * 8) * 2);
    uint32_t boffV[2];
#pragma unroll
    for (int g = 0; g < 2; g++)
        boffV[g] = (uint32_t)(((g * 16 + (q8 >> 1) * 8 + r8) * 72 + (q8 & 1) * 8) * 2);

    // ---- GEMM1: c[8][4] = Q . ah^T (3-MMA hi/lo split) ----
    float c[8][4];
#pragma unroll
    for (int j = 0; j < 8; j++)
#pragma unroll
        for (int e = 0; e < 4; e++) c[j][e] = 0.f;
#pragma unroll
    for (int kk = 0; kk < 2; kk++) {
        uint32_t ko = (uint32_t)(kk * 32);
        uint32_t Ah[4], Al[4];
        ldm_x4(Ah, uS + OFF_QH + aoffQ + ko);
        ldm_x4(Al, uS + OFF_QL + aoffQ + ko);
#pragma unroll
        for (int p = 0; p < 4; p++) {
            uint32_t Bh[4], Bl[4];
            ldm_x4(Bh, uS + OFF_AHH + boffA[p] + ko);
            ldm_x4(Bl, uS + OFF_AHL + boffA[p] + ko);
#pragma unroll
            for (int hf = 0; hf < 2; hf++) {
                float* d = c[p * 2 + hf];
                mma_bf16(d, Ah, Bh[hf * 2], Bh[hf * 2 + 1]);
                mma_bf16(d, Ah, Bl[hf * 2], Bl[hf * 2 + 1]);
                mma_bf16(d, Al, Bh[hf * 2], Bh[hf * 2 + 1]);
            }
        }
    }

    // ---- bias2 add + pad masking ----
    const int r0 = w * 16 + (lane >> 2), r1 = r0 + 8;
    const int aq = (lane & 3) * 2;
    {
        const float* b2r0 = g_bias2 + ((size_t)h * Nn + n0 + r0) * B2P;
        const float* b2r1 = g_bias2 + ((size_t)h * Nn + n0 + r1) * B2P;
#pragma unroll
        for (int j = 0; j < 8; j++) {
            int a0 = j * 8 + aq;
            if (a0 < 48) {
                float2 u0 = *(const float2*)(b2r0 + a0);
                float2 u1 = *(const float2*)(b2r1 + a0);
                c[j][0] += u0.x; c[j][1] += u0.y;
                c[j][2] += u1.x; c[j][3] += u1.y;
            } else if (a0 == 48) {
                c[j][0] += b2r0[48]; c[j][1] = -1e30f;
                c[j][2] += b2r1[48]; c[j][3] = -1e30f;
            } else {
                c[j][0] = c[j][1] = c[j][2] = c[j][3] = -1e30f;
            }
        }
    }

    // ---- softmax over a (in-register, quad shfl) ----
    float m0 = -1e30f, m1 = -1e30f;
#pragma unroll
    for (int j = 0; j < 8; j++) {
        m0 = fmaxf(m0, fmaxf(c[j][0], c[j][1]));
        m1 = fmaxf(m1, fmaxf(c[j][2], c[j][3]));
    }
    m0 = fmaxf(m0, __shfl_xor_sync(0xFFFFFFFFu, m0, 1));
    m0 = fmaxf(m0, __shfl_xor_sync(0xFFFFFFFFu, m0, 2));
    m1 = fmaxf(m1, __shfl_xor_sync(0xFFFFFFFFu, m1, 1));
    m1 = fmaxf(m1, __shfl_xor_sync(0xFFFFFFFFu, m1, 2));
    float l0 = 0.f, l1 = 0.f;
#pragma unroll
    for (int j = 0; j < 8; j++) {
        c[j][0] = __expf(c[j][0] - m0); c[j][1] = __expf(c[j][1] - m0);
        c[j][2] = __expf(c[j][2] - m1); c[j][3] = __expf(c[j][3] - m1);
        l0 += c[j][0] + c[j][1];
        l1 += c[j][2] + c[j][3];
    }
    l0 += __shfl_xor_sync(0xFFFFFFFFu, l0, 1);
    l0 += __shfl_xor_sync(0xFFFFFFFFu, l0, 2);
    l1 += __shfl_xor_sync(0xFFFFFFFFu, l1, 1);
    l1 += __shfl_xor_sync(0xFFFFFFFFu, l1, 2);
    const float rl0 = 1.0f / l0, rl1 = 1.0f / l1;

    // ---- GEMM2: out = (P/l) . av ----
    float o[4][4];
#pragma unroll
    for (int g = 0; g < 4; g++)
#pragma unroll
        for (int e = 0; e < 4; e++) o[g][e] = 0.f;
#pragma unroll
    for (int kk = 0; kk < 4; kk++) {
        uint32_t ah2[4], al2[4];
        {
            float p00 = c[2 * kk][0] * rl0, p01 = c[2 * kk][1] * rl0;
            float p02 = c[2 * kk][2] * rl1, p03 = c[2 * kk][3] * rl1;
            float p10 = c[2 * kk + 1][0] * rl0, p11 = c[2 * kk + 1][1] * rl0;
            float p12 = c[2 * kk + 1][2] * rl1, p13 = c[2 * kk + 1][3] * rl1;
            split2(p00, p01, ah2[0], al2[0]);
            split2(p02, p03, ah2[1], al2[1]);
            split2(p10, p11, ah2[2], al2[2]);
            split2(p12, p13, ah2[3], al2[3]);
        }
        uint32_t ko = (uint32_t)(kk * 32);
#pragma unroll
        for (int g = 0; g < 2; g++) {
            uint32_t Bh[4], Bl[4];
            ldm_x4(Bh, uS + OFF_AVH + boffV[g] + ko);
            ldm_x4(Bl, uS + OFF_AVL + boffV[g] + ko);
#pragma unroll
            for (int hf = 0; hf < 2; hf++) {
                float* d = o[g * 2 + hf];
                mma_bf16(d, ah2, Bh[hf * 2], Bh[hf * 2 + 1]);
                mma_bf16(d, ah2, Bl[hf * 2], Bl[hf * 2 + 1]);
                mma_bf16(d, al2, Bh[hf * 2], Bh[hf * 2 + 1]);
            }
        }
    }

    // ---- stage attention-out, then dw-conv add + split + store ----
    __syncthreads();
    float* stg = (float*)sraw;  // 128 x 36 fp32 (aliases Q region; vh/wd/bd untouched)
#pragma unroll
    for (int g = 0; g < 4; g++) {
        int dcol = g * 8 + aq;
        stg[r0 * 36 + dcol]     = o[g][0];
        stg[r0 * 36 + dcol + 1] = o[g][1];
        stg[r1 * 36 + dcol]     = o[g][2];
        stg[r1 * 36 + dcol + 1] = o[g][3];
    }
    __syncthreads();
#pragma unroll
    for (int it = 0; it < 4; it++) {
        int idx = t + it * 256;
        int m = idx >> 3, d4 = (idx & 7) * 4;
        int n = n0 + m, y = n >> 6, x = n & 63;
        float4 base = *(float4*)&stg[m * 36 + d4];
        float outv[4] = {base.x, base.y, base.z, base.w};
#pragma unroll
        for (int ci = 0; ci < 4; ci++) {
            int cch = d4 + ci;
            float s = bd_s[cch];
#pragma unroll
            for (int dy = -1; dy <= 1; dy++) {
                int yy = y + dy;
                if (yy < 0 || yy > 63) continue;
                int rr = yy - y0 + 1;
#pragma unroll
                for (int dx = -1; dx <= 1; dx++) {
                    int xx = x + dx;
                    if (xx < 0 || xx > 63) continue;
                    s += vh_s[(rr * 64 + xx) * 33 + cch] * wd_s[cch * 9 + (dy + 1) * 3 + (dx + 1)];
                }
            }
            outv[ci] += s;
        }
        uint32_t h0, l0, h1, l1;
        split2(outv[0], outv[1], h0, l0);
        split2(outv[2], outv[3], h1, l1);
        size_t off = ((size_t)b * 4096 + n) * 256 + h * 32 + d4;
        *(uint2*)&g_oh[off] = make_uint2(h0, h1);
        *(uint2*)&g_ol[off] = make_uint2(l0, l1);
    }
}

// ---------------- launch ----------------
extern "C" void kernel_launch(void* const* d_in, const int* in_sizes, int n_in,
                              void* d_out, int out_size) {
    const float* x     = (const float*)d_in[0];
    const float* Wq    = (const float*)d_in[1];
    const float* Wkv   = (const float*)d_in[2];
    const float* Wproj = (const float*)d_in[3];
    const float* bproj = (const float*)d_in[4];
    const float* Wdwc  = (const float*)d_in[5];
    const float* bdwc  = (const float*)d_in[6];
    const float* an    = (const float*)d_in[7];
    const float* na    = (const float*)d_in[8];
    const float* ahb   = (const float*)d_in[9];
    const float* awb   = (const float*)d_in[10];
    const float* hab   = (const float*)d_in[11];
    const float* wab   = (const float*)d_in[12];
    float* out = (float*)d_out;

    cudaFuncSetAttribute(k_gemm_mma<0>, cudaFuncAttributeMaxDynamicSharedMemorySize, SMEM_DYN);
    cudaFuncSetAttribute(k_gemm_mma<1>, cudaFuncAttributeMaxDynamicSharedMemorySize, SMEM_DYN);
    cudaFuncSetAttribute(k_st2_tc, cudaFuncAttributeMaxDynamicSharedMemorySize, ST2_DYN);

    k_bias   <<<dim3(Nn / 256, AG, NH), 256>>>(an, na, ahb, awb, hab, wab);
    k_prep_w <<<1024, 256>>>(Wq, Wkv, Wproj);
    k_xsplit <<<dim3(128, 8, Bb), dim3(32, 8)>>>(x);
    k_gemm_mma<0><<<dim3(32, 6, Bb), 256, SMEM_DYN>>>(nullptr, nullptr);
    k_pool   <<<dim3(AG, Bb), 256>>>();
    k_fs1    <<<dim3(NSPLIT, NH, Bb), 256>>>();
    k_fs1red <<<Bb * NH, 256>>>();
    k_st2_tc <<<dim3(Nn / 128, NH, Bb), 256, ST2_DYN>>>(Wdwc, bdwc);
    k_gemm_mma<1><<<dim3(32, 2, Bb), 256, SMEM_DYN>>>(bproj, out);
}

// round 15
// speedup vs baseline: 2.3946x; 1.2986x over previous
#include <cuda_runtime.h>
#include <cuda_bf16.h>
#include <cstdint>

// ---------------- constants ----------------
namespace {
constexpr int Bb = 16;      // batch
constexpr int Cc = 256;     // channels
constexpr int Nn = 4096;    // H*W
constexpr int NH = 8;       // heads
constexpr int HD = 32;      // head dim
constexpr int AG = 49;      // agent tokens
constexpr int NSPLIT = 8;   // stage-1 n-splits
constexpr int B2P = 52;     // bias2 pitch (floats) for aligned float2 fragment loads
constexpr float SCALE = 0.17677669529663689f;  // 32^-0.5

// GEMM smem: per stage A(hi|lo) 128x32k pitch40 + B(hi|lo) 128x32k pitch40
constexpr int KP = 40;                          // k-pitch in bf16 (80B rows: conflict-free ldmatrix)
constexpr unsigned SA_SZ = 128 * KP * 2;        // 10240 per half
constexpr unsigned SB_SZ = 128 * KP * 2;        // 10240 per half
constexpr unsigned STAGE_SZ = 2 * SA_SZ + 2 * SB_SZ;  // 40960
constexpr unsigned SMEM_DYN = 2 * STAGE_SZ;     // 81920 (epilogue staging aliases this)
constexpr int SP = 136;                         // epilogue staging pitch (fp32)

// st2 smem offsets (bytes) — dynamic smem
constexpr unsigned OFF_QH  = 0;                 // 128x40 bf16
constexpr unsigned OFF_QL  = 10240;
constexpr unsigned OFF_AHH = 20480;             // 64x40 bf16
constexpr unsigned OFF_AHL = 25600;
constexpr unsigned OFF_AVH = 30720;             // 32x72 bf16 (av^T)
constexpr unsigned OFF_AVL = 35328;
constexpr unsigned OFF_VH  = 39936;             // 4*64 x 33-pitch fp32 v halo = 33792
constexpr unsigned OFF_WD  = 73728;             // 32*9 fp32 = 1152
constexpr unsigned OFF_BD  = 74880;             // 32 fp32 = 128
constexpr unsigned ST2_DYN = 75008;

// fs1_tc smem offsets (bytes) — static smem
constexpr unsigned F_AHH = 0;      // 64x40 bf16
constexpr unsigned F_AHL = 5120;
constexpr unsigned F_KH  = 10240;  // 64x40 bf16
constexpr unsigned F_KL  = 15360;
constexpr unsigned F_VTH = 20480;  // 32x72 bf16 (v^T)
constexpr unsigned F_VTL = 25088;
constexpr unsigned F_SZ  = 29696;
}

// ---------------- scratch (device globals; no allocation allowed) ----------------
__device__ float g_k[Bb * Nn * Cc];
__device__ float g_v[Bb * Nn * Cc];
__device__ float g_bias1[NH * AG * Nn];        // stage-1 bias [h][a][n]
__device__ float g_bias2[NH * Nn * B2P];       // stage-2 bias [h][n][a] pitch 52
__device__ float g_pacc[Bb * NH * NSPLIT * AG * HD];  // stage-1 partial acc
__device__ float g_pm[Bb * NH * NSPLIT * AG];
__device__ float g_pl[Bb * NH * NSPLIT * AG];

// bf16 hi/lo split operands for tensor-core work
__device__ __nv_bfloat16 g_xh[Bb * Nn * Cc];   // xt row-major [b][n][c]
__device__ __nv_bfloat16 g_xl[Bb * Nn * Cc];
__device__ __nv_bfloat16 g_qh[Bb * Nn * Cc];   // q hi/lo (from qkv GEMM epilogue)
__device__ __nv_bfloat16 g_ql[Bb * Nn * Cc];
__device__ __nv_bfloat16 g_oh[Bb * Nn * Cc];   // attention-out + dw, hi/lo (from st2 epilogue)
__device__ __nv_bfloat16 g_ol[Bb * Nn * Cc];
__device__ __nv_bfloat16 g_ahh[Bb * AG * Cc];  // agent*SCALE hi/lo
__device__ __nv_bfloat16 g_ahl[Bb * AG * Cc];
__device__ __nv_bfloat16 g_avh[Bb * NH * AG * HD];  // agent_v hi/lo
__device__ __nv_bfloat16 g_avl[Bb * NH * AG * HD];
__device__ __nv_bfloat16 g_wh[768 * Cc];       // qkv weights combined [q|k|v]
__device__ __nv_bfloat16 g_wl[768 * Cc];
__device__ __nv_bfloat16 g_pwh[Cc * Cc];       // proj weights
__device__ __nv_bfloat16 g_pwl[Cc * Cc];

// ---------------- PTX helpers (baseline sm_80+ features only) ----------------
__device__ __forceinline__ uint32_t smem_u32(const void* p) {
    uint32_t a;
    asm("{ .reg .u64 t; cvta.to.shared.u64 t, %1; cvt.u32.u64 %0, t; }" : "=r"(a) : "l"(p));
    return a;
}
__device__ __forceinline__ void ldm_x4(uint32_t* r, uint32_t addr) {
    asm volatile("ldmatrix.sync.aligned.m8n8.x4.shared.b16 {%0,%1,%2,%3}, [%4];"
                 : "=r"(r[0]), "=r"(r[1]), "=r"(r[2]), "=r"(r[3]) : "r"(addr));
}
__device__ __forceinline__ void mma_bf16(float* d, const uint32_t* a, uint32_t b0, uint32_t b1) {
    asm volatile(
        "mma.sync.aligned.m16n8k16.row.col.f32.bf16.bf16.f32 "
        "{%0,%1,%2,%3}, {%4,%5,%6,%7}, {%8,%9}, {%0,%1,%2,%3};"
        : "+f"(d[0]), "+f"(d[1]), "+f"(d[2]), "+f"(d[3])
        : "r"(a[0]), "r"(a[1]), "r"(a[2]), "r"(a[3]), "r"(b0), "r"(b1));
}
__device__ __forceinline__ void cp16(uint32_t dst, const void* src) {
    asm volatile("cp.async.ca.shared.global [%0], [%1], 16;" :: "r"(dst), "l"(src));
}
__device__ __forceinline__ void cp_commit() { asm volatile("cp.async.commit_group;" ::: "memory"); }
template <int N>
__device__ __forceinline__ void cp_wait() { asm volatile("cp.async.wait_group %0;" :: "n"(N) : "memory"); }

__device__ __forceinline__ void split2(float x, float y, uint32_t& h, uint32_t& l) {
    __nv_bfloat16 hx = __float2bfloat16(x), hy = __float2bfloat16(y);
    __nv_bfloat162 hv; hv.x = hx; hv.y = hy;
    __nv_bfloat162 lv;
    lv.x = __float2bfloat16(x - __bfloat162float(hx));
    lv.y = __float2bfloat16(y - __bfloat162float(hy));
    h = *reinterpret_cast<uint32_t*>(&hv);
    l = *reinterpret_cast<uint32_t*>(&lv);
}

// ---------------- prep: bf16 hi/lo splits ----------------
__global__ void k_prep_w(const float* __restrict__ Wq, const float* __restrict__ Wkv,
                         const float* __restrict__ Wp) {
    int row = blockIdx.x, t = threadIdx.x;
    if (row < 768) {
        float v = (row < 256) ? Wq[row * 256 + t] : Wkv[(row - 256) * 256 + t];
        __nv_bfloat16 hi = __float2bfloat16(v);
        g_wh[row * 256 + t] = hi;
        g_wl[row * 256 + t] = __float2bfloat16(v - __bfloat162float(hi));
    } else {
        int r = row - 768;
        float v = Wp[r * 256 + t];
        __nv_bfloat16 hi = __float2bfloat16(v);
        g_pwh[r * 256 + t] = hi;
        g_pwl[r * 256 + t] = __float2bfloat16(v - __bfloat162float(hi));
    }
}

__global__ void k_xsplit(const float* __restrict__ x) {
    __shared__ float tile[32][33];
    int tx = threadIdx.x, ty = threadIdx.y;  // 32x8
    int n0 = blockIdx.x * 32, c0 = blockIdx.y * 32, b = blockIdx.z;
#pragma unroll
    for (int yy = 0; yy < 32; yy += 8)
        tile[ty + yy][tx] = x[((size_t)b * 256 + c0 + ty + yy) * 4096 + n0 + tx];
    __syncthreads();
#pragma unroll
    for (int yy = 0; yy < 32; yy += 8) {
        int nl = ty + yy;
        float v = tile[tx][nl];
        __nv_bfloat16 hi = __float2bfloat16(v);
        size_t o = ((size_t)b * 4096 + n0 + nl) * 256 + c0 + tx;
        g_xh[o] = hi;
        g_xl[o] = __float2bfloat16(v - __bfloat162float(hi));
    }
}

// ---------------- tensor-core GEMM: 128x128 CTA tiles, double-buffered k32 stages ----------------
// MODE 0: A = g_xh/g_xl, W = g_wh/g_wl (6 j-tiles) -> jt<2: q bf16 hi/lo; jt<4: g_k; else g_v
// MODE 1: A = g_oh/g_ol, W = g_pwh/g_pwl (2 j-tiles) -> transposed out + bias
template <int MODE>
__global__ __launch_bounds__(256, 2)
void k_gemm_mma(const float* __restrict__ bias, float* __restrict__ outp) {
    extern __shared__ __align__(16) char dsm[];
    float* stag = (float*)dsm;                 // epilogue staging aliases pipeline smem

    const int t = threadIdx.x;
    const int lane = t & 31, wid = t >> 5;
    const int wm = wid & 3, wn = wid >> 2;     // warp tile: 32(m) x 64(n)
    const int b = blockIdx.z;
    const int n0 = blockIdx.x * 128;
    const int jt = blockIdx.y, j0 = jt * 128;

    const __nv_bfloat16* Agh = (MODE == 0 ? g_xh : g_oh) + ((size_t)b * 4096 + n0) * 256;
    const __nv_bfloat16* Agl = (MODE == 0 ? g_xl : g_ol) + ((size_t)b * 4096 + n0) * 256;
    const __nv_bfloat16* Wgh = ((MODE == 0) ? g_wh : g_pwh) + (size_t)j0 * 256;
    const __nv_bfloat16* Wgl = ((MODE == 0) ? g_wl : g_pwl) + (size_t)j0 * 256;

    const uint32_t uS = smem_u32(dsm);

    auto load_stage = [&](int st, int kt) {
        uint32_t base = uS + st * STAGE_SZ;
        int k0 = kt * 32;
#pragma unroll
        for (int it = 0; it < 2; it++) {
            int idx = t + it * 256;
            int r = idx >> 2, ch = idx & 3;
            uint32_t off = (uint32_t)((r * KP + ch * 8) * 2);
            const size_t g = (size_t)r * 256 + k0 + ch * 8;
            cp16(base + off, Agh + g);
            cp16(base + SA_SZ + off, Agl + g);
            cp16(base + 2 * SA_SZ + off, Wgh + g);
            cp16(base + 2 * SA_SZ + SB_SZ + off, Wgl + g);
        }
    };

    const int q8 = lane >> 3, r8 = lane & 7;
    uint32_t aoff[2], boff[4];
#pragma unroll
    for (int mt = 0; mt < 2; mt++) {
        int row = wm * 32 + mt * 16 + (q8 & 1) * 8 + r8;
        aoff[mt] = (uint32_t)((row * KP + (q8 >> 1) * 8) * 2);
    }
#pragma unroll
    for (int p = 0; p < 4; p++) {
        int nrow = wn * 64 + p * 16 + (q8 >> 1) * 8 + r8;
        boff[p] = (uint32_t)((nrow * KP + (q8 & 1) * 8) * 2);
    }

    float acc[2][8][4];
#pragma unroll
    for (int mt = 0; mt < 2; mt++)
#pragma unroll
        for (int nt = 0; nt < 8; nt++)
#pragma unroll
            for (int e = 0; e < 4; e++) acc[mt][nt][e] = 0.f;

    load_stage(0, 0);
    cp_commit();

    for (int kt = 0; kt < 8; kt++) {
        cp_wait<0>();
        __syncthreads();
        if (kt < 7) {
            load_stage((kt + 1) & 1, kt + 1);
            cp_commit();
        }
        const uint32_t base = uS + (kt & 1) * STAGE_SZ;
        const uint32_t uAh = base, uAl = base + SA_SZ;
        const uint32_t uBh = base + 2 * SA_SZ, uBl = uBh + SB_SZ;
#pragma unroll
        for (int kh = 0; kh < 2; kh++) {
            uint32_t ko = (uint32_t)(kh * 32);
            uint32_t A_h[2][4], A_l[2][4];
            ldm_x4(A_h[0], uAh + aoff[0] + ko);
            ldm_x4(A_h[1], uAh + aoff[1] + ko);
            ldm_x4(A_l[0], uAl + aoff[0] + ko);
            ldm_x4(A_l[1], uAl + aoff[1] + ko);
#pragma unroll
            for (int p = 0; p < 4; p++) {
                uint32_t B_h[4], B_l[4];
                ldm_x4(B_h, uBh + boff[p] + ko);
                ldm_x4(B_l, uBl + boff[p] + ko);
#pragma unroll
                for (int mt = 0; mt < 2; mt++) {
#pragma unroll
                    for (int hf = 0; hf < 2; hf++) {
                        float* d = acc[mt][p * 2 + hf];
                        mma_bf16(d, A_h[mt], B_h[hf * 2], B_h[hf * 2 + 1]);
                        mma_bf16(d, A_h[mt], B_l[hf * 2], B_l[hf * 2 + 1]);
                        mma_bf16(d, A_l[mt], B_h[hf * 2], B_h[hf * 2 + 1]);
                    }
                }
            }
        }
        __syncthreads();
    }

    // ---- stage fragments to smem [128][SP] ----
    {
        int r0 = lane >> 2, c0 = (lane & 3) * 2;
#pragma unroll
        for (int mt = 0; mt < 2; mt++) {
#pragma unroll
            for (int nt = 0; nt < 8; nt++) {
                int row = wm * 32 + mt * 16 + r0;
                int col = wn * 64 + nt * 8 + c0;
                stag[row * SP + col]           = acc[mt][nt][0];
                stag[row * SP + col + 1]       = acc[mt][nt][1];
                stag[(row + 8) * SP + col]     = acc[mt][nt][2];
                stag[(row + 8) * SP + col + 1] = acc[mt][nt][3];
            }
        }
    }
    __syncthreads();

    // ---- coalesced stores ----
    if (MODE == 0) {
        int jl = (jt & 1) * 128;
        if (jt < 2) {
#pragma unroll
            for (int it = 0; it < 16; it++) {
                int idx = t + it * 256;
                int m = idx >> 5, j4 = (idx & 31) * 4;
                float4 v = *(float4*)&stag[m * SP + j4];
                uint32_t h0, l0, h1, l1;
                split2(v.x, v.y, h0, l0);
                split2(v.z, v.w, h1, l1);
                size_t off = ((size_t)b * 4096 + n0 + m) * 256 + jl + j4;
                *(uint2*)&g_qh[off] = make_uint2(h0, h1);
                *(uint2*)&g_ql[off] = make_uint2(l0, l1);
            }
        } else {
            float* dst = (jt < 4) ? g_k : g_v;
#pragma unroll
            for (int it = 0; it < 16; it++) {
                int idx = t + it * 256;
                int m = idx >> 5, j4 = (idx & 31) * 4;
                *(float4*)&dst[((size_t)b * 4096 + n0 + m) * 256 + jl + j4] =
                    *(float4*)&stag[m * SP + j4];
            }
        }
    } else {
        int m = t & 127, js = t >> 7;
#pragma unroll 8
        for (int j = js; j < 128; j += 2) {
            float v = stag[m * SP + j] + bias[j0 + j];
            outp[((size_t)b * 256 + j0 + j) * 4096 + n0 + m] = v;
        }
    }
}

// ---------------- bilinear coeffs for 7 -> 64 resize ----------------
__device__ __forceinline__ void lin7(int i, int& j0, int& j1, float& w) {
    float c = (i + 0.5f) * (7.0f / 64.0f) - 0.5f;
    float f = floorf(c);
    w = c - f;
    int j = (int)f;
    j0 = max(0, min(6, j));
    j1 = max(0, min(6, j + 1));
}

__device__ __forceinline__ float bil7(const float* img, int y0, int y1, float wy,
                                      int x0, int x1, float wx) {
    float v0 = img[y0 * 7 + x0] * (1.f - wx) + img[y0 * 7 + x1] * wx;
    float v1 = img[y1 * 7 + x0] * (1.f - wx) + img[y1 * 7 + x1] * wx;
    return v0 * (1.f - wy) + v1 * wy;
}

// ---------------- K1: position biases ----------------
__global__ void k_bias(const float* __restrict__ an, const float* __restrict__ na,
                       const float* __restrict__ ahb, const float* __restrict__ awb,
                       const float* __restrict__ hab, const float* __restrict__ wab) {
    int n = blockIdx.x * 256 + threadIdx.x;
    int a = blockIdx.y, h = blockIdx.z;
    int y = n >> 6, x = n & 63;
    int y0, y1, x0, x1; float wy, wx;
    lin7(y, y0, y1, wy);
    lin7(x, x0, x1, wx);
    const float* i1 = an + (h * AG + a) * 49;
    const float* i2 = na + (h * AG + a) * 49;
    float v1 = bil7(i1, y0, y1, wy, x0, x1, wx);
    float v2 = bil7(i2, y0, y1, wy, x0, x1, wx);
    g_bias1[(h * AG + a) * Nn + n] = v1 + ahb[(h * AG + a) * 64 + y] + awb[(h * AG + a) * 64 + x];
    g_bias2[((size_t)h * Nn + n) * B2P + a] = v2 + hab[(h * 64 + y) * AG + a] + wab[(h * 64 + x) * AG + a];
}

// ---------------- K3: adaptive avg pool q -> agent (scaled hi/lo split only) ----------------
__global__ void k_pool() {
    int c = threadIdx.x;
    int a = blockIdx.x;
    int b = blockIdx.y;
    int p = a / 7, q = a % 7;
    int ys = (p * 64) / 7, ye = ((p + 1) * 64 + 6) / 7;
    int xs = (q * 64) / 7, xe = ((q + 1) * 64 + 6) / 7;
    float s = 0.f;
    for (int y = ys; y < ye; y++)
        for (int x = xs; x < xe; x++) {
            size_t idx = ((size_t)b * Nn + y * 64 + x) * Cc + c;
            s += __bfloat162float(g_qh[idx]) + __bfloat162float(g_ql[idx]);
        }
    float sc = s * (1.0f / ((ye - ys) * (xe - xs))) * SCALE;
    __nv_bfloat16 hi = __float2bfloat16(sc);
    g_ahh[(b * AG + a) * Cc + c] = hi;
    g_ahl[(b * AG + a) * Cc + c] = __float2bfloat16(sc - __bfloat162float(hi));
}

// ---------------- K4: stage-1 on tensor cores (flash, n-split partials) ----------------
// per (sp, h, b) CTA (128 thr, 4 warps): loop 8 n-tiles of 64:
//   S = (ah*SCALE)·k^T + bias1 ; online softmax over n ; o += P·v  (all 3-MMA hi/lo)
__global__ __launch_bounds__(128, 4) void k_fs1_tc() {
    __shared__ __align__(16) char sm[F_SZ];
    const uint32_t uS = smem_u32(sm);
    const int t = threadIdx.x;
    const int lane = t & 31, w = t >> 5;
    const int sp = blockIdx.x, h = blockIdx.y, b = blockIdx.z;
    const int bh = b * NH + h;

    // ---- load ah (64x32 hi/lo, rows >= 49 zero) ----
#pragma unroll
    for (int i = 0; i < 2; i++) {
        int idx = t + i * 128;
        int r = idx >> 2, ch = idx & 3;
        uint32_t off = (uint32_t)((r * 40 + ch * 8) * 2);
        uint4 z = make_uint4(0, 0, 0, 0);
        uint4 vh = z, vl = z;
        if (r < AG) {
            vh = *(const uint4*)(g_ahh + ((size_t)b * AG + r) * 256 + h * 32 + ch * 8);
            vl = *(const uint4*)(g_ahl + ((size_t)b * AG + r) * 256 + h * 32 + ch * 8);
        }
        *(uint4*)(sm + F_AHH + off) = vh;
        *(uint4*)(sm + F_AHL + off) = vl;
    }

    // ---- fragment offsets ----
    const int q8 = lane >> 3, r8 = lane & 7;
    const uint32_t aoffA = (uint32_t)(((w * 16 + (q8 & 1) * 8 + r8) * 40 + (q8 >> 1) * 8) * 2);
    uint32_t boffK[4];
#pragma unroll
    for (int p = 0; p < 4; p++)
        boffK[p] = (uint32_t)(((p * 16 + (q8 >> 1) * 8 + r8) * 40 + (q8 & 1) * 8) * 2);
    uint32_t boffV[2];
#pragma unroll
    for (int g = 0; g < 2; g++)
        boffV[g] = (uint32_t)(((g * 16 + (q8 >> 1) * 8 + r8) * 72 + (q8 & 1) * 8) * 2);

    const int r0 = w * 16 + (lane >> 2), r1 = r0 + 8;
    const int aq = (lane & 3) * 2;

    float o[4][4];
#pragma unroll
    for (int g = 0; g < 4; g++)
#pragma unroll
        for (int e = 0; e < 4; e++) o[g][e] = 0.f;
    float m0r = -1e30f, m1r = -1e30f, l0r = 0.f, l1r = 0.f;

    const float* kb = g_k + (size_t)b * Nn * Cc + h * HD;
    const float* vb = g_v + (size_t)b * Nn * Cc + h * HD;
    const float* bias = g_bias1 + (size_t)h * AG * Nn;

    for (int tile = 0; tile < 8; tile++) {
        int n0 = sp * 512 + tile * 64;
        __syncthreads();   // previous GEMM2 fragment reads complete
        // ---- load+split k (row-major) and v (transposed) ----
        __nv_bfloat16* vth = (__nv_bfloat16*)(sm + F_VTH);
        __nv_bfloat16* vtl = (__nv_bfloat16*)(sm + F_VTL);
#pragma unroll
        for (int i = 0; i < 4; i++) {
            int idx = t + i * 128;
            int r = idx >> 3, c4 = (idx & 7) * 4;
            float4 kk = *(const float4*)(kb + (size_t)(n0 + r) * Cc + c4);
            uint32_t kh0, kl0, kh1, kl1;
            split2(kk.x, kk.y, kh0, kl0);
            split2(kk.z, kk.w, kh1, kl1);
            *(uint2*)(sm + F_KH + (r * 40 + c4) * 2) = make_uint2(kh0, kh1);
            *(uint2*)(sm + F_KL + (r * 40 + c4) * 2) = make_uint2(kl0, kl1);
            float4 vv = *(const float4*)(vb + (size_t)(n0 + r) * Cc + c4);
            float vals[4] = {vv.x, vv.y, vv.z, vv.w};
#pragma unroll
            for (int j = 0; j < 4; j++) {
                __nv_bfloat16 hi = __float2bfloat16(vals[j]);
                vth[(c4 + j) * 72 + r] = hi;
                vtl[(c4 + j) * 72 + r] = __float2bfloat16(vals[j] - __bfloat162float(hi));
            }
        }
        __syncthreads();

        // ---- GEMM1: c = ah . k^T (3-MMA hi/lo) ----
        float c[8][4];
#pragma unroll
        for (int j = 0; j < 8; j++)
#pragma unroll
            for (int e = 0; e < 4; e++) c[j][e] = 0.f;
#pragma unroll
        for (int kk = 0; kk < 2; kk++) {
            uint32_t ko = (uint32_t)(kk * 32);
            uint32_t Ah[4], Al[4];
            ldm_x4(Ah, uS + F_AHH + aoffA + ko);
            ldm_x4(Al, uS + F_AHL + aoffA + ko);
#pragma unroll
            for (int p = 0; p < 4; p++) {
                uint32_t Bh[4], Bl[4];
                ldm_x4(Bh, uS + F_KH + boffK[p] + ko);
                ldm_x4(Bl, uS + F_KL + boffK[p] + ko);
#pragma unroll
                for (int hf = 0; hf < 2; hf++) {
                    float* d = c[p * 2 + hf];
                    mma_bf16(d, Ah, Bh[hf * 2], Bh[hf * 2 + 1]);
                    mma_bf16(d, Ah, Bl[hf * 2], Bl[hf * 2 + 1]);
                    mma_bf16(d, Al, Bh[hf * 2], Bh[hf * 2 + 1]);
                }
            }
        }

        // ---- bias1 add (rows guarded: bias1 has only AG rows) ----
        if (r0 < AG) {
            const float* br = bias + (size_t)r0 * Nn + n0;
#pragma unroll
            for (int j = 0; j < 8; j++) {
                float2 u = *(const float2*)(br + j * 8 + aq);
                c[j][0] += u.x; c[j][1] += u.y;
            }
        }
        if (r1 < AG) {
            const float* br = bias + (size_t)r1 * Nn + n0;
#pragma unroll
            for (int j = 0; j < 8; j++) {
                float2 u = *(const float2*)(br + j * 8 + aq);
                c[j][2] += u.x; c[j][3] += u.y;
            }
        }

        // ---- online softmax over n (quad shfl) ----
        float tm0 = -1e30f, tm1 = -1e30f;
#pragma unroll
        for (int j = 0; j < 8; j++) {
            tm0 = fmaxf(tm0, fmaxf(c[j][0], c[j][1]));
            tm1 = fmaxf(tm1, fmaxf(c[j][2], c[j][3]));
        }
        tm0 = fmaxf(tm0, __shfl_xor_sync(0xFFFFFFFFu, tm0, 1));
        tm0 = fmaxf(tm0, __shfl_xor_sync(0xFFFFFFFFu, tm0, 2));
        tm1 = fmaxf(tm1, __shfl_xor_sync(0xFFFFFFFFu, tm1, 1));
        tm1 = fmaxf(tm1, __shfl_xor_sync(0xFFFFFFFFu, tm1, 2));
        float mn0 = fmaxf(m0r, tm0), mn1 = fmaxf(m1r, tm1);
        float f0 = __expf(m0r - mn0), f1 = __expf(m1r - mn1);
        float ts0 = 0.f, ts1 = 0.f;
#pragma unroll
        for (int j = 0; j < 8; j++) {
            c[j][0] = __expf(c[j][0] - mn0); c[j][1] = __expf(c[j][1] - mn0);
            c[j][2] = __expf(c[j][2] - mn1); c[j][3] = __expf(c[j][3] - mn1);
            ts0 += c[j][0] + c[j][1];
            ts1 += c[j][2] + c[j][3];
        }
        ts0 += __shfl_xor_sync(0xFFFFFFFFu, ts0, 1);
        ts0 += __shfl_xor_sync(0xFFFFFFFFu, ts0, 2);
        ts1 += __shfl_xor_sync(0xFFFFFFFFu, ts1, 1);
        ts1 += __shfl_xor_sync(0xFFFFFFFFu, ts1, 2);
        l0r = l0r * f0 + ts0;
        l1r = l1r * f1 + ts1;
        m0r = mn0; m1r = mn1;
#pragma unroll
        for (int g = 0; g < 4; g++) {
            o[g][0] *= f0; o[g][1] *= f0;
            o[g][2] *= f1; o[g][3] *= f1;
        }

        // ---- GEMM2: o += P . v  (P from c frags, hi/lo split) ----
#pragma unroll
        for (int kk = 0; kk < 4; kk++) {
            uint32_t ah2[4], al2[4];
            split2(c[2 * kk][0], c[2 * kk][1], ah2[0], al2[0]);
            split2(c[2 * kk][2], c[2 * kk][3], ah2[1], al2[1]);
            split2(c[2 * kk + 1][0], c[2 * kk + 1][1], ah2[2], al2[2]);
            split2(c[2 * kk + 1][2], c[2 * kk + 1][3], ah2[3], al2[3]);
            uint32_t ko = (uint32_t)(kk * 32);
#pragma unroll
            for (int g = 0; g < 2; g++) {
                uint32_t Bh[4], Bl[4];
                ldm_x4(Bh, uS + F_VTH + boffV[g] + ko);
                ldm_x4(Bl, uS + F_VTL + boffV[g] + ko);
#pragma unroll
                for (int hf = 0; hf < 2; hf++) {
                    float* d = o[g * 2 + hf];
                    mma_bf16(d, ah2, Bh[hf * 2], Bh[hf * 2 + 1]);
                    mma_bf16(d, ah2, Bl[hf * 2], Bl[hf * 2 + 1]);
                    mma_bf16(d, al2, Bh[hf * 2], Bh[hf * 2 + 1]);
                }
            }
        }
    }

    // ---- store partials (unnormalized acc + m, l) ----
    float* pacc = g_pacc + ((size_t)bh * NSPLIT + sp) * AG * HD;
    if (r0 < AG) {
#pragma unroll
        for (int g = 0; g < 4; g++) {
            pacc[r0 * HD + g * 8 + aq]     = o[g][0];
            pacc[r0 * HD + g * 8 + aq + 1] = o[g][1];
        }
    }
    if (r1 < AG) {
#pragma unroll
        for (int g = 0; g < 4; g++) {
            pacc[r1 * HD + g * 8 + aq]     = o[g][2];
            pacc[r1 * HD + g * 8 + aq + 1] = o[g][3];
        }
    }
    if ((lane & 3) == 0) {
        if (r0 < AG) {
            g_pm[(bh * NSPLIT + sp) * AG + r0] = m0r;
            g_pl[(bh * NSPLIT + sp) * AG + r0] = l0r;
        }
        if (r1 < AG) {
            g_pm[(bh * NSPLIT + sp) * AG + r1] = m1r;
            g_pl[(bh * NSPLIT + sp) * AG + r1] = l1r;
        }
    }
}

// ---------------- K4b: combine stage-1 partials -> agent_v bf16 hi/lo ----------------
__global__ void k_fs1red() {
    int bh = blockIdx.x;
    int t = threadIdx.x;
    for (int idx = t; idx < AG * HD; idx += 256) {
        int a = idx >> 5, d = idx & 31;
        float mmax = -1e30f;
#pragma unroll
        for (int s = 0; s < NSPLIT; s++)
            mmax = fmaxf(mmax, g_pm[(bh * NSPLIT + s) * AG + a]);
        float num = 0.f, den = 0.f;
#pragma unroll
        for (int s = 0; s < NSPLIT; s++) {
            float w = __expf(g_pm[(bh * NSPLIT + s) * AG + a] - mmax);
            num += w * g_pacc[(((size_t)bh * NSPLIT + s) * AG + a) * HD + d];
            den += w * g_pl[(bh * NSPLIT + s) * AG + a];
        }
        float val = num / den;
        __nv_bfloat16 hi = __float2bfloat16(val);
        g_avh[((size_t)bh * AG + a) * HD + d] = hi;
        g_avl[((size_t)bh * AG + a) * HD + d] = __float2bfloat16(val - __bfloat162float(hi));
    }
}

// ---------------- K7: stage-2 on tensor cores + fused depthwise conv epilogue ----------------
__global__ __launch_bounds__(256, 2) void k_st2_tc(const float* __restrict__ Wd,
                                                   const float* __restrict__ bdv) {
    extern __shared__ __align__(16) char sraw[];
    const int t = threadIdx.x;
    const int lane = t & 31, w = t >> 5;
    const int n0 = blockIdx.x * 128, h = blockIdx.y, b = blockIdx.z;
    const int bh = b * NH + h;
    const int y0 = n0 >> 6;
    const uint32_t uS = smem_u32(sraw);
    float* vh_s = (float*)(sraw + OFF_VH);
    float* wd_s = (float*)(sraw + OFF_WD);
    float* bd_s = (float*)(sraw + OFF_BD);

    {
        const __nv_bfloat16* qh = g_qh + ((size_t)b * 4096 + n0) * 256 + h * 32;
        const __nv_bfloat16* ql = g_ql + ((size_t)b * 4096 + n0) * 256 + h * 32;
#pragma unroll
        for (int it = 0; it < 2; it++) {
            int idx = t + it * 256;
            int r = idx >> 2, ch = idx & 3;
            uint32_t off = (uint32_t)((r * 40 + ch * 8) * 2);
            *(uint4*)(sraw + OFF_QH + off) = *(const uint4*)(qh + (size_t)r * 256 + ch * 8);
            *(uint4*)(sraw + OFF_QL + off) = *(const uint4*)(ql + (size_t)r * 256 + ch * 8);
        }
    }
    {
        int r = t >> 2, ch = t & 3;
        uint32_t off = (uint32_t)((r * 40 + ch * 8) * 2);
        uint4 z = make_uint4(0, 0, 0, 0);
        uint4 vh = z, vl = z;
        if (r < AG) {
            vh = *(const uint4*)(g_ahh + ((size_t)b * AG + r) * 256 + h * 32 + ch * 8);
            vl = *(const uint4*)(g_ahl + ((size_t)b * AG + r) * 256 + h * 32 + ch * 8);
        }
        *(uint4*)(sraw + OFF_AHH + off) = vh;
        *(uint4*)(sraw + OFF_AHL + off) = vl;
    }
#pragma unroll
    for (int it = 0; it < 8; it++) {
        int idx = t + it * 256;
        int a = idx >> 5, d = idx & 31;
        __nv_bfloat16 zh = __float2bfloat16(0.f);
        __nv_bfloat16 vh = zh, vl = zh;
        if (a < AG) {
            vh = g_avh[((size_t)bh * AG + a) * HD + d];
            vl = g_avl[((size_t)bh * AG + a) * HD + d];
        }
        ((__nv_bfloat16*)(sraw + OFF_AVH))[d * 72 + a] = vh;
        ((__nv_bfloat16*)(sraw + OFF_AVL))[d * 72 + a] = vl;
    }
#pragma unroll
    for (int it = 0; it < 32; it++) {
        int idx = t + it * 256;
        int rr = idx >> 11;
        int rem = idx & 2047;
        int xx = rem >> 5, c = rem & 31;
        int yy = y0 - 1 + rr;
        float vv = 0.f;
        if (yy >= 0 && yy <= 63)
            vv = g_v[((size_t)b * 4096 + yy * 64 + xx) * 256 + h * 32 + c];
        vh_s[(rr * 64 + xx) * 33 + c] = vv;
    }
    for (int i = t; i < 288; i += 256) wd_s[i] = Wd[h * 288 + i];
    if (t < 32) bd_s[t] = bdv[h * 32 + t];
    __syncthreads();

    const int q8 = lane >> 3, r8 = lane & 7;
    const uint32_t aoffQ = (uint32_t)(((w * 16 + (q8 & 1) * 8 + r8) * 40 + (q8 >> 1) * 8) * 2);
    uint32_t boffA[4];
#pragma unroll
    for (int p = 0; p < 4; p++)
        boffA[p] = (uint32_t)(((p * 16 + (q8 >> 1) * 8 + r8) * 40 + (q8 & 1) * 8) * 2);
    uint32_t boffV[2];
#pragma unroll
    for (int g = 0; g < 2; g++)
        boffV[g] = (uint32_t)(((g * 16 + (q8 >> 1) * 8 + r8) * 72 + (q8 & 1) * 8) * 2);

    float c[8][4];
#pragma unroll
    for (int j = 0; j < 8; j++)
#pragma unroll
        for (int e = 0; e < 4; e++) c[j][e] = 0.f;
#pragma unroll
    for (int kk = 0; kk < 2; kk++) {
        uint32_t ko = (uint32_t)(kk * 32);
        uint32_t Ah[4], Al[4];
        ldm_x4(Ah, uS + OFF_QH + aoffQ + ko);
        ldm_x4(Al, uS + OFF_QL + aoffQ + ko);
#pragma unroll
        for (int p = 0; p < 4; p++) {
            uint32_t Bh[4], Bl[4];
            ldm_x4(Bh, uS + OFF_AHH + boffA[p] + ko);
            ldm_x4(Bl, uS + OFF_AHL + boffA[p] + ko);
#pragma unroll
            for (int hf = 0; hf < 2; hf++) {
                float* d = c[p * 2 + hf];
                mma_bf16(d, Ah, Bh[hf * 2], Bh[hf * 2 + 1]);
                mma_bf16(d, Ah, Bl[hf * 2], Bl[hf * 2 + 1]);
                mma_bf16(d, Al, Bh[hf * 2], Bh[hf * 2 + 1]);
            }
        }
    }

    const int r0 = w * 16 + (lane >> 2), r1 = r0 + 8;
    const int aq = (lane & 3) * 2;
    {
        const float* b2r0 = g_bias2 + ((size_t)h * Nn + n0 + r0) * B2P;
        const float* b2r1 = g_bias2 + ((size_t)h * Nn + n0 + r1) * B2P;
#pragma unroll
        for (int j = 0; j < 8; j++) {
            int a0 = j * 8 + aq;
            if (a0 < 48) {
                float2 u0 = *(const float2*)(b2r0 + a0);
                float2 u1 = *(const float2*)(b2r1 + a0);
                c[j][0] += u0.x; c[j][1] += u0.y;
                c[j][2] += u1.x; c[j][3] += u1.y;
            } else if (a0 == 48) {
                c[j][0] += b2r0[48]; c[j][1] = -1e30f;
                c[j][2] += b2r1[48]; c[j][3] = -1e30f;
            } else {
                c[j][0] = c[j][1] = c[j][2] = c[j][3] = -1e30f;
            }
        }
    }

    float m0 = -1e30f, m1 = -1e30f;
#pragma unroll
    for (int j = 0; j < 8; j++) {
        m0 = fmaxf(m0, fmaxf(c[j][0], c[j][1]));
        m1 = fmaxf(m1, fmaxf(c[j][2], c[j][3]));
    }
    m0 = fmaxf(m0, __shfl_xor_sync(0xFFFFFFFFu, m0, 1));
    m0 = fmaxf(m0, __shfl_xor_sync(0xFFFFFFFFu, m0, 2));
    m1 = fmaxf(m1, __shfl_xor_sync(0xFFFFFFFFu, m1, 1));
    m1 = fmaxf(m1, __shfl_xor_sync(0xFFFFFFFFu, m1, 2));
    float l0 = 0.f, l1 = 0.f;
#pragma unroll
    for (int j = 0; j < 8; j++) {
        c[j][0] = __expf(c[j][0] - m0); c[j][1] = __expf(c[j][1] - m0);
        c[j][2] = __expf(c[j][2] - m1); c[j][3] = __expf(c[j][3] - m1);
        l0 += c[j][0] + c[j][1];
        l1 += c[j][2] + c[j][3];
    }
    l0 += __shfl_xor_sync(0xFFFFFFFFu, l0, 1);
    l0 += __shfl_xor_sync(0xFFFFFFFFu, l0, 2);
    l1 += __shfl_xor_sync(0xFFFFFFFFu, l1, 1);
    l1 += __shfl_xor_sync(0xFFFFFFFFu, l1, 2);
    const float rl0 = 1.0f / l0, rl1 = 1.0f / l1;

    float o[4][4];
#pragma unroll
    for (int g = 0; g < 4; g++)
#pragma unroll
        for (int e = 0; e < 4; e++) o[g][e] = 0.f;
#pragma unroll
    for (int kk = 0; kk < 4; kk++) {
        uint32_t ah2[4], al2[4];
        split2(c[2 * kk][0] * rl0, c[2 * kk][1] * rl0, ah2[0], al2[0]);
        split2(c[2 * kk][2] * rl1, c[2 * kk][3] * rl1, ah2[1], al2[1]);
        split2(c[2 * kk + 1][0] * rl0, c[2 * kk + 1][1] * rl0, ah2[2], al2[2]);
        split2(c[2 * kk + 1][2] * rl1, c[2 * kk + 1][3] * rl1, ah2[3], al2[3]);
        uint32_t ko = (uint32_t)(kk * 32);
#pragma unroll
        for (int g = 0; g < 2; g++) {
            uint32_t Bh[4], Bl[4];
            ldm_x4(Bh, uS + OFF_AVH + boffV[g] + ko);
            ldm_x4(Bl, uS + OFF_AVL + boffV[g] + ko);
#pragma unroll
            for (int hf = 0; hf < 2; hf++) {
                float* d = o[g * 2 + hf];
                mma_bf16(d, ah2, Bh[hf * 2], Bh[hf * 2 + 1]);
                mma_bf16(d, ah2, Bl[hf * 2], Bl[hf * 2 + 1]);
                mma_bf16(d, al2, Bh[hf * 2], Bh[hf * 2 + 1]);
            }
        }
    }

    __syncthreads();
    float* stg = (float*)sraw;
#pragma unroll
    for (int g = 0; g < 4; g++) {
        int dcol = g * 8 + aq;
        stg[r0 * 36 + dcol]     = o[g][0];
        stg[r0 * 36 + dcol + 1] = o[g][1];
        stg[r1 * 36 + dcol]     = o[g][2];
        stg[r1 * 36 + dcol + 1] = o[g][3];
    }
    __syncthreads();
#pragma unroll
    for (int it = 0; it < 4; it++) {
        int idx = t + it * 256;
        int m = idx >> 3, d4 = (idx & 7) * 4;
        int n = n0 + m, y = n >> 6, x = n & 63;
        float4 base = *(float4*)&stg[m * 36 + d4];
        float outv[4] = {base.x, base.y, base.z, base.w};
#pragma unroll
        for (int ci = 0; ci < 4; ci++) {
            int cch = d4 + ci;
            float s = bd_s[cch];
#pragma unroll
            for (int dy = -1; dy <= 1; dy++) {
                int yy = y + dy;
                if (yy < 0 || yy > 63) continue;
                int rr = yy - y0 + 1;
#pragma unroll
                for (int dx = -1; dx <= 1; dx++) {
                    int xx = x + dx;
                    if (xx < 0 || xx > 63) continue;
                    s += vh_s[(rr * 64 + xx) * 33 + cch] * wd_s[cch * 9 + (dy + 1) * 3 + (dx + 1)];
                }
            }
            outv[ci] += s;
        }
        uint32_t h0, l0u, h1, l1u;
        split2(outv[0], outv[1], h0, l0u);
        split2(outv[2], outv[3], h1, l1u);
        size_t off = ((size_t)b * 4096 + n) * 256 + h * 32 + d4;
        *(uint2*)&g_oh[off] = make_uint2(h0, h1);
        *(uint2*)&g_ol[off] = make_uint2(l0u, l1u);
    }
}

// ---------------- launch ----------------
extern "C" void kernel_launch(void* const* d_in, const int* in_sizes, int n_in,
                              void* d_out, int out_size) {
    const float* x     = (const float*)d_in[0];
    const float* Wq    = (const float*)d_in[1];
    const float* Wkv   = (const float*)d_in[2];
    const float* Wproj = (const float*)d_in[3];
    const float* bproj = (const float*)d_in[4];
    const float* Wdwc  = (const float*)d_in[5];
    const float* bdwc  = (const float*)d_in[6];
    const float* an    = (const float*)d_in[7];
    const float* na    = (const float*)d_in[8];
    const float* ahb   = (const float*)d_in[9];
    const float* awb   = (const float*)d_in[10];
    const float* hab   = (const float*)d_in[11];
    const float* wab   = (const float*)d_in[12];
    float* out = (float*)d_out;

    cudaFuncSetAttribute(k_gemm_mma<0>, cudaFuncAttributeMaxDynamicSharedMemorySize, SMEM_DYN);
    cudaFuncSetAttribute(k_gemm_mma<1>, cudaFuncAttributeMaxDynamicSharedMemorySize, SMEM_DYN);
    cudaFuncSetAttribute(k_st2_tc, cudaFuncAttributeMaxDynamicSharedMemorySize, ST2_DYN);

    k_bias   <<<dim3(Nn / 256, AG, NH), 256>>>(an, na, ahb, awb, hab, wab);
    k_prep_w <<<1024, 256>>>(Wq, Wkv, Wproj);
    k_xsplit <<<dim3(128, 8, Bb), dim3(32, 8)>>>(x);
    k_gemm_mma<0><<<dim3(32, 6, Bb), 256, SMEM_DYN>>>(nullptr, nullptr);
    k_pool   <<<dim3(AG, Bb), 256>>>();
    k_fs1_tc <<<dim3(NSPLIT, NH, Bb), 128>>>();
    k_fs1red <<<Bb * NH, 256>>>();
    k_st2_tc <<<dim3(Nn / 128, NH, Bb), 256, ST2_DYN>>>(Wdwc, bdwc);
    k_gemm_mma<1><<<dim3(32, 2, Bb), 256, SMEM_DYN>>>(bproj, out);
}

// round 16
// speedup vs baseline: 2.7600x; 1.1526x over previous
#include <cuda_runtime.h>
#include <cuda_bf16.h>
#include <cuda_fp16.h>
#include <cstdint>

// ---------------- constants ----------------
namespace {
constexpr int Bb = 16;      // batch
constexpr int Cc = 256;     // channels
constexpr int Nn = 4096;    // H*W
constexpr int NH = 8;       // heads
constexpr int HD = 32;      // head dim
constexpr int AG = 49;      // agent tokens
constexpr int NSPLIT = 8;   // stage-1 n-splits
constexpr int B2P = 52;     // bias2 pitch (floats) for aligned float2 fragment loads
constexpr float SCALE = 0.17677669529663689f;  // 32^-0.5

// GEMM smem: per stage A-hi + A-lo + B (fp16, 128x32k pitch40 each)
constexpr int KP = 40;                          // k-pitch (80B rows: conflict-free ldmatrix)
constexpr unsigned SA_SZ = 128 * KP * 2;        // 10240 per buffer
constexpr unsigned STAGE_SZ = 3 * SA_SZ;        // 30720
constexpr int SP = 136;                         // epilogue staging pitch (fp32)
constexpr unsigned SMEM_DYN = 128 * SP * 4;     // 69632 >= 2*STAGE_SZ (61440)

// st2 smem offsets (bytes) — dynamic smem
constexpr unsigned OFF_QH  = 0;                 // 128x40 bf16
constexpr unsigned OFF_QL  = 10240;
constexpr unsigned OFF_AHH = 20480;             // 64x40 bf16
constexpr unsigned OFF_AHL = 25600;
constexpr unsigned OFF_AVH = 30720;             // 32x72 bf16 (av^T)
constexpr unsigned OFF_AVL = 35328;
constexpr unsigned OFF_VH  = 39936;             // 4*64 x 33-pitch fp32 v halo = 33792
constexpr unsigned OFF_WD  = 73728;             // 32*9 fp32 = 1152
constexpr unsigned OFF_BD  = 74880;             // 32 fp32 = 128
constexpr unsigned ST2_DYN = 75008;

// fs1_tc smem offsets (bytes) — static smem
constexpr unsigned F_AHH = 0;      // 64x40 bf16
constexpr unsigned F_AHL = 5120;
constexpr unsigned F_KH  = 10240;  // 64x40 bf16
constexpr unsigned F_KL  = 15360;
constexpr unsigned F_VTH = 20480;  // 32x72 bf16 (v^T)
constexpr unsigned F_VTL = 25088;
constexpr unsigned F_SZ  = 29696;
}

// ---------------- scratch (device globals; no allocation allowed) ----------------
__device__ float g_k[Bb * Nn * Cc];
__device__ float g_v[Bb * Nn * Cc];
__device__ float g_bias1[NH * AG * Nn];        // stage-1 bias [h][a][n]
__device__ float g_bias2[NH * Nn * B2P];       // stage-2 bias [h][n][a] pitch 52
__device__ float g_pacc[Bb * NH * NSPLIT * AG * HD];  // stage-1 partial acc
__device__ float g_pm[Bb * NH * NSPLIT * AG];
__device__ float g_pl[Bb * NH * NSPLIT * AG];

// fp16 operands for the two big GEMMs (A hi/lo split, B single fp16)
__device__ __half g_xh[Bb * Nn * Cc];          // xt row-major [b][n][c]
__device__ __half g_xl[Bb * Nn * Cc];
__device__ __half g_oh[Bb * Nn * Cc];          // attention-out + dw (from st2 epilogue)
__device__ __half g_ol[Bb * Nn * Cc];
__device__ __half g_wf[768 * Cc];              // qkv weights combined [q|k|v]
__device__ __half g_pwf[Cc * Cc];              // proj weights

// bf16 hi/lo operands for the attention tensor-core kernels
__device__ __nv_bfloat16 g_qh[Bb * Nn * Cc];   // q hi/lo (from qkv GEMM epilogue)
__device__ __nv_bfloat16 g_ql[Bb * Nn * Cc];
__device__ __nv_bfloat16 g_ahh[Bb * AG * Cc];  // agent*SCALE hi/lo
__device__ __nv_bfloat16 g_ahl[Bb * AG * Cc];
__device__ __nv_bfloat16 g_avh[Bb * NH * AG * HD];  // agent_v hi/lo
__device__ __nv_bfloat16 g_avl[Bb * NH * AG * HD];

// ---------------- PTX helpers (baseline sm_80+ features only) ----------------
__device__ __forceinline__ uint32_t smem_u32(const void* p) {
    uint32_t a;
    asm("{ .reg .u64 t; cvta.to.shared.u64 t, %1; cvt.u32.u64 %0, t; }" : "=r"(a) : "l"(p));
    return a;
}
__device__ __forceinline__ void ldm_x4(uint32_t* r, uint32_t addr) {
    asm volatile("ldmatrix.sync.aligned.m8n8.x4.shared.b16 {%0,%1,%2,%3}, [%4];"
                 : "=r"(r[0]), "=r"(r[1]), "=r"(r[2]), "=r"(r[3]) : "r"(addr));
}
__device__ __forceinline__ void mma_bf16(float* d, const uint32_t* a, uint32_t b0, uint32_t b1) {
    asm volatile(
        "mma.sync.aligned.m16n8k16.row.col.f32.bf16.bf16.f32 "
        "{%0,%1,%2,%3}, {%4,%5,%6,%7}, {%8,%9}, {%0,%1,%2,%3};"
        : "+f"(d[0]), "+f"(d[1]), "+f"(d[2]), "+f"(d[3])
        : "r"(a[0]), "r"(a[1]), "r"(a[2]), "r"(a[3]), "r"(b0), "r"(b1));
}
__device__ __forceinline__ void mma_f16(float* d, const uint32_t* a, uint32_t b0, uint32_t b1) {
    asm volatile(
        "mma.sync.aligned.m16n8k16.row.col.f32.f16.f16.f32 "
        "{%0,%1,%2,%3}, {%4,%5,%6,%7}, {%8,%9}, {%0,%1,%2,%3};"
        : "+f"(d[0]), "+f"(d[1]), "+f"(d[2]), "+f"(d[3])
        : "r"(a[0]), "r"(a[1]), "r"(a[2]), "r"(a[3]), "r"(b0), "r"(b1));
}
__device__ __forceinline__ void cp16(uint32_t dst, const void* src) {
    asm volatile("cp.async.ca.shared.global [%0], [%1], 16;" :: "r"(dst), "l"(src));
}
__device__ __forceinline__ void cp_commit() { asm volatile("cp.async.commit_group;" ::: "memory"); }
template <int N>
__device__ __forceinline__ void cp_wait() { asm volatile("cp.async.wait_group %0;" :: "n"(N) : "memory"); }

// bf16 pair split (attention path)
__device__ __forceinline__ void split2(float x, float y, uint32_t& h, uint32_t& l) {
    __nv_bfloat16 hx = __float2bfloat16(x), hy = __float2bfloat16(y);
    __nv_bfloat162 hv; hv.x = hx; hv.y = hy;
    __nv_bfloat162 lv;
    lv.x = __float2bfloat16(x - __bfloat162float(hx));
    lv.y = __float2bfloat16(y - __bfloat162float(hy));
    h = *reinterpret_cast<uint32_t*>(&hv);
    l = *reinterpret_cast<uint32_t*>(&lv);
}
// fp16 pair split (GEMM A path)
__device__ __forceinline__ void split2h(float x, float y, uint32_t& h, uint32_t& l) {
    __half hx = __float2half(x), hy = __float2half(y);
    __half2 hv; hv.x = hx; hv.y = hy;
    __half2 lv;
    lv.x = __float2half(x - __half2float(hx));
    lv.y = __float2half(y - __half2float(hy));
    h = *reinterpret_cast<uint32_t*>(&hv);
    l = *reinterpret_cast<uint32_t*>(&lv);
}

// ---------------- prep: fp16 weights ----------------
__global__ void k_prep_w(const float* __restrict__ Wq, const float* __restrict__ Wkv,
                         const float* __restrict__ Wp) {
    int row = blockIdx.x, t = threadIdx.x;
    if (row < 768) {
        float v = (row < 256) ? Wq[row * 256 + t] : Wkv[(row - 256) * 256 + t];
        g_wf[row * 256 + t] = __float2half(v);
    } else {
        int r = row - 768;
        g_pwf[r * 256 + t] = __float2half(Wp[r * 256 + t]);
    }
}

__global__ void k_xsplit(const float* __restrict__ x) {
    __shared__ float tile[32][33];
    int tx = threadIdx.x, ty = threadIdx.y;  // 32x8
    int n0 = blockIdx.x * 32, c0 = blockIdx.y * 32, b = blockIdx.z;
#pragma unroll
    for (int yy = 0; yy < 32; yy += 8)
        tile[ty + yy][tx] = x[((size_t)b * 256 + c0 + ty + yy) * 4096 + n0 + tx];
    __syncthreads();
#pragma unroll
    for (int yy = 0; yy < 32; yy += 8) {
        int nl = ty + yy;
        float v = tile[tx][nl];
        __half hi = __float2half(v);
        size_t o = ((size_t)b * 4096 + n0 + nl) * 256 + c0 + tx;
        g_xh[o] = hi;
        g_xl[o] = __float2half(v - __half2float(hi));
    }
}

// ---------------- tensor-core GEMM: 128x128 tiles, fp16 A-split 2-MMA ----------------
// MODE 0: A = g_xh/g_xl, W = g_wf (6 j-tiles) -> jt<2: q bf16 hi/lo; jt<4: g_k; else g_v
// MODE 1: A = g_oh/g_ol, W = g_pwf (2 j-tiles) -> transposed out + bias
template <int MODE>
__global__ __launch_bounds__(256, 2)
void k_gemm_mma(const float* __restrict__ bias, float* __restrict__ outp) {
    extern __shared__ __align__(16) char dsm[];
    float* stag = (float*)dsm;                 // epilogue staging aliases pipeline smem

    const int t = threadIdx.x;
    const int lane = t & 31, wid = t >> 5;
    const int wm = wid & 3, wn = wid >> 2;     // warp tile: 32(m) x 64(n)
    const int b = blockIdx.z;
    const int n0 = blockIdx.x * 128;
    const int jt = blockIdx.y, j0 = jt * 128;

    const __half* Agh = (MODE == 0 ? g_xh : g_oh) + ((size_t)b * 4096 + n0) * 256;
    const __half* Agl = (MODE == 0 ? g_xl : g_ol) + ((size_t)b * 4096 + n0) * 256;
    const __half* Wg  = ((MODE == 0) ? g_wf : g_pwf) + (size_t)j0 * 256;

    const uint32_t uS = smem_u32(dsm);

    auto load_stage = [&](int st, int kt) {
        uint32_t base = uS + st * STAGE_SZ;
        int k0 = kt * 32;
#pragma unroll
        for (int it = 0; it < 2; it++) {
            int idx = t + it * 256;
            int r = idx >> 2, ch = idx & 3;
            uint32_t off = (uint32_t)((r * KP + ch * 8) * 2);
            const size_t g = (size_t)r * 256 + k0 + ch * 8;
            cp16(base + off, Agh + g);
            cp16(base + SA_SZ + off, Agl + g);
            cp16(base + 2 * SA_SZ + off, Wg + g);
        }
    };

    const int q8 = lane >> 3, r8 = lane & 7;
    uint32_t aoff[2], boff[4];
#pragma unroll
    for (int mt = 0; mt < 2; mt++) {
        int row = wm * 32 + mt * 16 + (q8 & 1) * 8 + r8;
        aoff[mt] = (uint32_t)((row * KP + (q8 >> 1) * 8) * 2);
    }
#pragma unroll
    for (int p = 0; p < 4; p++) {
        int nrow = wn * 64 + p * 16 + (q8 >> 1) * 8 + r8;
        boff[p] = (uint32_t)((nrow * KP + (q8 & 1) * 8) * 2);
    }

    float acc[2][8][4];
#pragma unroll
    for (int mt = 0; mt < 2; mt++)
#pragma unroll
        for (int nt = 0; nt < 8; nt++)
#pragma unroll
            for (int e = 0; e < 4; e++) acc[mt][nt][e] = 0.f;

    load_stage(0, 0);
    cp_commit();

    for (int kt = 0; kt < 8; kt++) {
        cp_wait<0>();
        __syncthreads();
        if (kt < 7) {
            load_stage((kt + 1) & 1, kt + 1);
            cp_commit();
        }
        const uint32_t base = uS + (kt & 1) * STAGE_SZ;
        const uint32_t uAh = base, uAl = base + SA_SZ;
        const uint32_t uB = base + 2 * SA_SZ;
#pragma unroll
        for (int kh = 0; kh < 2; kh++) {
            uint32_t ko = (uint32_t)(kh * 32);
            uint32_t A_h[2][4], A_l[2][4];
            ldm_x4(A_h[0], uAh + aoff[0] + ko);
            ldm_x4(A_h[1], uAh + aoff[1] + ko);
            ldm_x4(A_l[0], uAl + aoff[0] + ko);
            ldm_x4(A_l[1], uAl + aoff[1] + ko);
#pragma unroll
            for (int p = 0; p < 4; p++) {
                uint32_t B[4];
                ldm_x4(B, uB + boff[p] + ko);
#pragma unroll
                for (int mt = 0; mt < 2; mt++) {
#pragma unroll
                    for (int hf = 0; hf < 2; hf++) {
                        float* d = acc[mt][p * 2 + hf];
                        mma_f16(d, A_h[mt], B[hf * 2], B[hf * 2 + 1]);
                        mma_f16(d, A_l[mt], B[hf * 2], B[hf * 2 + 1]);
                    }
                }
            }
        }
        // no end-of-loop sync: next iteration's top sync guards buffer reuse
    }
    __syncthreads();   // all compute done before staging overwrites pipeline smem

    // ---- stage fragments to smem [128][SP] ----
    {
        int r0 = lane >> 2, c0 = (lane & 3) * 2;
#pragma unroll
        for (int mt = 0; mt < 2; mt++) {
#pragma unroll
            for (int nt = 0; nt < 8; nt++) {
                int row = wm * 32 + mt * 16 + r0;
                int col = wn * 64 + nt * 8 + c0;
                stag[row * SP + col]           = acc[mt][nt][0];
                stag[row * SP + col + 1]       = acc[mt][nt][1];
                stag[(row + 8) * SP + col]     = acc[mt][nt][2];
                stag[(row + 8) * SP + col + 1] = acc[mt][nt][3];
            }
        }
    }
    __syncthreads();

    // ---- coalesced stores ----
    if (MODE == 0) {
        int jl = (jt & 1) * 128;
        if (jt < 2) {
#pragma unroll
            for (int it = 0; it < 16; it++) {
                int idx = t + it * 256;
                int m = idx >> 5, j4 = (idx & 31) * 4;
                float4 v = *(float4*)&stag[m * SP + j4];
                uint32_t h0, l0, h1, l1;
                split2(v.x, v.y, h0, l0);
                split2(v.z, v.w, h1, l1);
                size_t off = ((size_t)b * 4096 + n0 + m) * 256 + jl + j4;
                *(uint2*)&g_qh[off] = make_uint2(h0, h1);
                *(uint2*)&g_ql[off] = make_uint2(l0, l1);
            }
        } else {
            float* dst = (jt < 4) ? g_k : g_v;
#pragma unroll
            for (int it = 0; it < 16; it++) {
                int idx = t + it * 256;
                int m = idx >> 5, j4 = (idx & 31) * 4;
                *(float4*)&dst[((size_t)b * 4096 + n0 + m) * 256 + jl + j4] =
                    *(float4*)&stag[m * SP + j4];
            }
        }
    } else {
        int m = t & 127, js = t >> 7;
#pragma unroll 8
        for (int j = js; j < 128; j += 2) {
            float v = stag[m * SP + j] + bias[j0 + j];
            outp[((size_t)b * 256 + j0 + j) * 4096 + n0 + m] = v;
        }
    }
}

// ---------------- bilinear coeffs for 7 -> 64 resize ----------------
__device__ __forceinline__ void lin7(int i, int& j0, int& j1, float& w) {
    float c = (i + 0.5f) * (7.0f / 64.0f) - 0.5f;
    float f = floorf(c);
    w = c - f;
    int j = (int)f;
    j0 = max(0, min(6, j));
    j1 = max(0, min(6, j + 1));
}

__device__ __forceinline__ float bil7(const float* img, int y0, int y1, float wy,
                                      int x0, int x1, float wx) {
    float v0 = img[y0 * 7 + x0] * (1.f - wx) + img[y0 * 7 + x1] * wx;
    float v1 = img[y1 * 7 + x0] * (1.f - wx) + img[y1 * 7 + x1] * wx;
    return v0 * (1.f - wy) + v1 * wy;
}

// ---------------- K1: position biases ----------------
__global__ void k_bias(const float* __restrict__ an, const float* __restrict__ na,
                       const float* __restrict__ ahb, const float* __restrict__ awb,
                       const float* __restrict__ hab, const float* __restrict__ wab) {
    int n = blockIdx.x * 256 + threadIdx.x;
    int a = blockIdx.y, h = blockIdx.z;
    int y = n >> 6, x = n & 63;
    int y0, y1, x0, x1; float wy, wx;
    lin7(y, y0, y1, wy);
    lin7(x, x0, x1, wx);
    const float* i1 = an + (h * AG + a) * 49;
    const float* i2 = na + (h * AG + a) * 49;
    float v1 = bil7(i1, y0, y1, wy, x0, x1, wx);
    float v2 = bil7(i2, y0, y1, wy, x0, x1, wx);
    g_bias1[(h * AG + a) * Nn + n] = v1 + ahb[(h * AG + a) * 64 + y] + awb[(h * AG + a) * 64 + x];
    g_bias2[((size_t)h * Nn + n) * B2P + a] = v2 + hab[(h * 64 + y) * AG + a] + wab[(h * 64 + x) * AG + a];
}

// ---------------- K3: adaptive avg pool q -> agent (scaled bf16 hi/lo split) ----------------
__global__ void k_pool() {
    int c = threadIdx.x;
    int a = blockIdx.x;
    int b = blockIdx.y;
    int p = a / 7, q = a % 7;
    int ys = (p * 64) / 7, ye = ((p + 1) * 64 + 6) / 7;
    int xs = (q * 64) / 7, xe = ((q + 1) * 64 + 6) / 7;
    float s = 0.f;
    for (int y = ys; y < ye; y++)
        for (int x = xs; x < xe; x++) {
            size_t idx = ((size_t)b * Nn + y * 64 + x) * Cc + c;
            s += __bfloat162float(g_qh[idx]) + __bfloat162float(g_ql[idx]);
        }
    float sc = s * (1.0f / ((ye - ys) * (xe - xs))) * SCALE;
    __nv_bfloat16 hi = __float2bfloat16(sc);
    g_ahh[(b * AG + a) * Cc + c] = hi;
    g_ahl[(b * AG + a) * Cc + c] = __float2bfloat16(sc - __bfloat162float(hi));
}

// ---------------- K4: stage-1 on tensor cores (flash, n-split partials) ----------------
__global__ __launch_bounds__(128, 4) void k_fs1_tc() {
    __shared__ __align__(16) char sm[F_SZ];
    const uint32_t uS = smem_u32(sm);
    const int t = threadIdx.x;
    const int lane = t & 31, w = t >> 5;
    const int sp = blockIdx.x, h = blockIdx.y, b = blockIdx.z;
    const int bh = b * NH + h;

#pragma unroll
    for (int i = 0; i < 2; i++) {
        int idx = t + i * 128;
        int r = idx >> 2, ch = idx & 3;
        uint32_t off = (uint32_t)((r * 40 + ch * 8) * 2);
        uint4 z = make_uint4(0, 0, 0, 0);
        uint4 vh = z, vl = z;
        if (r < AG) {
            vh = *(const uint4*)(g_ahh + ((size_t)b * AG + r) * 256 + h * 32 + ch * 8);
            vl = *(const uint4*)(g_ahl + ((size_t)b * AG + r) * 256 + h * 32 + ch * 8);
        }
        *(uint4*)(sm + F_AHH + off) = vh;
        *(uint4*)(sm + F_AHL + off) = vl;
    }

    const int q8 = lane >> 3, r8 = lane & 7;
    const uint32_t aoffA = (uint32_t)(((w * 16 + (q8 & 1) * 8 + r8) * 40 + (q8 >> 1) * 8) * 2);
    uint32_t boffK[4];
#pragma unroll
    for (int p = 0; p < 4; p++)
        boffK[p] = (uint32_t)(((p * 16 + (q8 >> 1) * 8 + r8) * 40 + (q8 & 1) * 8) * 2);
    uint32_t boffV[2];
#pragma unroll
    for (int g = 0; g < 2; g++)
        boffV[g] = (uint32_t)(((g * 16 + (q8 >> 1) * 8 + r8) * 72 + (q8 & 1) * 8) * 2);

    const int r0 = w * 16 + (lane >> 2), r1 = r0 + 8;
    const int aq = (lane & 3) * 2;

    float o[4][4];
#pragma unroll
    for (int g = 0; g < 4; g++)
#pragma unroll
        for (int e = 0; e < 4; e++) o[g][e] = 0.f;
    float m0r = -1e30f, m1r = -1e30f, l0r = 0.f, l1r = 0.f;

    const float* kb = g_k + (size_t)b * Nn * Cc + h * HD;
    const float* vb = g_v + (size_t)b * Nn * Cc + h * HD;
    const float* bias = g_bias1 + (size_t)h * AG * Nn;

    for (int tile = 0; tile < 8; tile++) {
        int n0 = sp * 512 + tile * 64;
        __syncthreads();
        __nv_bfloat16* vth = (__nv_bfloat16*)(sm + F_VTH);
        __nv_bfloat16* vtl = (__nv_bfloat16*)(sm + F_VTL);
#pragma unroll
        for (int i = 0; i < 4; i++) {
            int idx = t + i * 128;
            int r = idx >> 3, c4 = (idx & 7) * 4;
            float4 kk = *(const float4*)(kb + (size_t)(n0 + r) * Cc + c4);
            uint32_t kh0, kl0, kh1, kl1;
            split2(kk.x, kk.y, kh0, kl0);
            split2(kk.z, kk.w, kh1, kl1);
            *(uint2*)(sm + F_KH + (r * 40 + c4) * 2) = make_uint2(kh0, kh1);
            *(uint2*)(sm + F_KL + (r * 40 + c4) * 2) = make_uint2(kl0, kl1);
            float4 vv = *(const float4*)(vb + (size_t)(n0 + r) * Cc + c4);
            float vals[4] = {vv.x, vv.y, vv.z, vv.w};
#pragma unroll
            for (int j = 0; j < 4; j++) {
                __nv_bfloat16 hi = __float2bfloat16(vals[j]);
                vth[(c4 + j) * 72 + r] = hi;
                vtl[(c4 + j) * 72 + r] = __float2bfloat16(vals[j] - __bfloat162float(hi));
            }
        }
        __syncthreads();

        float c[8][4];
#pragma unroll
        for (int j = 0; j < 8; j++)
#pragma unroll
            for (int e = 0; e < 4; e++) c[j][e] = 0.f;
#pragma unroll
        for (int kk = 0; kk < 2; kk++) {
            uint32_t ko = (uint32_t)(kk * 32);
            uint32_t Ah[4], Al[4];
            ldm_x4(Ah, uS + F_AHH + aoffA + ko);
            ldm_x4(Al, uS + F_AHL + aoffA + ko);
#pragma unroll
            for (int p = 0; p < 4; p++) {
                uint32_t Bh[4], Bl[4];
                ldm_x4(Bh, uS + F_KH + boffK[p] + ko);
                ldm_x4(Bl, uS + F_KL + boffK[p] + ko);
#pragma unroll
                for (int hf = 0; hf < 2; hf++) {
                    float* d = c[p * 2 + hf];
                    mma_bf16(d, Ah, Bh[hf * 2], Bh[hf * 2 + 1]);
                    mma_bf16(d, Ah, Bl[hf * 2], Bl[hf * 2 + 1]);
                    mma_bf16(d, Al, Bh[hf * 2], Bh[hf * 2 + 1]);
                }
            }
        }

        if (r0 < AG) {
            const float* br = bias + (size_t)r0 * Nn + n0;
#pragma unroll
            for (int j = 0; j < 8; j++) {
                float2 u = *(const float2*)(br + j * 8 + aq);
                c[j][0] += u.x; c[j][1] += u.y;
            }
        }
        if (r1 < AG) {
            const float* br = bias + (size_t)r1 * Nn + n0;
#pragma unroll
            for (int j = 0; j < 8; j++) {
                float2 u = *(const float2*)(br + j * 8 + aq);
                c[j][2] += u.x; c[j][3] += u.y;
            }
        }

        float tm0 = -1e30f, tm1 = -1e30f;
#pragma unroll
        for (int j = 0; j < 8; j++) {
            tm0 = fmaxf(tm0, fmaxf(c[j][0], c[j][1]));
            tm1 = fmaxf(tm1, fmaxf(c[j][2], c[j][3]));
        }
        tm0 = fmaxf(tm0, __shfl_xor_sync(0xFFFFFFFFu, tm0, 1));
        tm0 = fmaxf(tm0, __shfl_xor_sync(0xFFFFFFFFu, tm0, 2));
        tm1 = fmaxf(tm1, __shfl_xor_sync(0xFFFFFFFFu, tm1, 1));
        tm1 = fmaxf(tm1, __shfl_xor_sync(0xFFFFFFFFu, tm1, 2));
        float mn0 = fmaxf(m0r, tm0), mn1 = fmaxf(m1r, tm1);
        float f0 = __expf(m0r - mn0), f1 = __expf(m1r - mn1);
        float ts0 = 0.f, ts1 = 0.f;
#pragma unroll
        for (int j = 0; j < 8; j++) {
            c[j][0] = __expf(c[j][0] - mn0); c[j][1] = __expf(c[j][1] - mn0);
            c[j][2] = __expf(c[j][2] - mn1); c[j][3] = __expf(c[j][3] - mn1);
            ts0 += c[j][0] + c[j][1];
            ts1 += c[j][2] + c[j][3];
        }
        ts0 += __shfl_xor_sync(0xFFFFFFFFu, ts0, 1);
        ts0 += __shfl_xor_sync(0xFFFFFFFFu, ts0, 2);
        ts1 += __shfl_xor_sync(0xFFFFFFFFu, ts1, 1);
        ts1 += __shfl_xor_sync(0xFFFFFFFFu, ts1, 2);
        l0r = l0r * f0 + ts0;
        l1r = l1r * f1 + ts1;
        m0r = mn0; m1r = mn1;
#pragma unroll
        for (int g = 0; g < 4; g++) {
            o[g][0] *= f0; o[g][1] *= f0;
            o[g][2] *= f1; o[g][3] *= f1;
        }

#pragma unroll
        for (int kk = 0; kk < 4; kk++) {
            uint32_t ah2[4], al2[4];
            split2(c[2 * kk][0], c[2 * kk][1], ah2[0], al2[0]);
            split2(c[2 * kk][2], c[2 * kk][3], ah2[1], al2[1]);
            split2(c[2 * kk + 1][0], c[2 * kk + 1][1], ah2[2], al2[2]);
            split2(c[2 * kk + 1][2], c[2 * kk + 1][3], ah2[3], al2[3]);
            uint32_t ko = (uint32_t)(kk * 32);
#pragma unroll
            for (int g = 0; g < 2; g++) {
                uint32_t Bh[4], Bl[4];
                ldm_x4(Bh, uS + F_VTH + boffV[g] + ko);
                ldm_x4(Bl, uS + F_VTL + boffV[g] + ko);
#pragma unroll
                for (int hf = 0; hf < 2; hf++) {
                    float* d = o[g * 2 + hf];
                    mma_bf16(d, ah2, Bh[hf * 2], Bh[hf * 2 + 1]);
                    mma_bf16(d, ah2, Bl[hf * 2], Bl[hf * 2 + 1]);
                    mma_bf16(d, al2, Bh[hf * 2], Bh[hf * 2 + 1]);
                }
            }
        }
    }

    float* pacc = g_pacc + ((size_t)bh * NSPLIT + sp) * AG * HD;
    if (r0 < AG) {
#pragma unroll
        for (int g = 0; g < 4; g++) {
            pacc[r0 * HD + g * 8 + aq]     = o[g][0];
            pacc[r0 * HD + g * 8 + aq + 1] = o[g][1];
        }
    }
    if (r1 < AG) {
#pragma unroll
        for (int g = 0; g < 4; g++) {
            pacc[r1 * HD + g * 8 + aq]     = o[g][2];
            pacc[r1 * HD + g * 8 + aq + 1] = o[g][3];
        }
    }
    if ((lane & 3) == 0) {
        if (r0 < AG) {
            g_pm[(bh * NSPLIT + sp) * AG + r0] = m0r;
            g_pl[(bh * NSPLIT + sp) * AG + r0] = l0r;
        }
        if (r1 < AG) {
            g_pm[(bh * NSPLIT + sp) * AG + r1] = m1r;
            g_pl[(bh * NSPLIT + sp) * AG + r1] = l1r;
        }
    }
}

// ---------------- K4b: combine stage-1 partials -> agent_v bf16 hi/lo ----------------
__global__ void k_fs1red() {
    int bh = blockIdx.x;
    int t = threadIdx.x;
    for (int idx = t; idx < AG * HD; idx += 256) {
        int a = idx >> 5, d = idx & 31;
        float mmax = -1e30f;
#pragma unroll
        for (int s = 0; s < NSPLIT; s++)
            mmax = fmaxf(mmax, g_pm[(bh * NSPLIT + s) * AG + a]);
        float num = 0.f, den = 0.f;
#pragma unroll
        for (int s = 0; s < NSPLIT; s++) {
            float w = __expf(g_pm[(bh * NSPLIT + s) * AG + a] - mmax);
            num += w * g_pacc[(((size_t)bh * NSPLIT + s) * AG + a) * HD + d];
            den += w * g_pl[(bh * NSPLIT + s) * AG + a];
        }
        float val = num / den;
        __nv_bfloat16 hi = __float2bfloat16(val);
        g_avh[((size_t)bh * AG + a) * HD + d] = hi;
        g_avl[((size_t)bh * AG + a) * HD + d] = __float2bfloat16(val - __bfloat162float(hi));
    }
}

// ---------------- K7: stage-2 on tensor cores + fused depthwise conv epilogue ----------------
__global__ __launch_bounds__(256, 2) void k_st2_tc(const float* __restrict__ Wd,
                                                   const float* __restrict__ bdv) {
    extern __shared__ __align__(16) char sraw[];
    const int t = threadIdx.x;
    const int lane = t & 31, w = t >> 5;
    const int n0 = blockIdx.x * 128, h = blockIdx.y, b = blockIdx.z;
    const int bh = b * NH + h;
    const int y0 = n0 >> 6;
    const uint32_t uS = smem_u32(sraw);
    float* vh_s = (float*)(sraw + OFF_VH);
    float* wd_s = (float*)(sraw + OFF_WD);
    float* bd_s = (float*)(sraw + OFF_BD);

    {
        const __nv_bfloat16* qh = g_qh + ((size_t)b * 4096 + n0) * 256 + h * 32;
        const __nv_bfloat16* ql = g_ql + ((size_t)b * 4096 + n0) * 256 + h * 32;
#pragma unroll
        for (int it = 0; it < 2; it++) {
            int idx = t + it * 256;
            int r = idx >> 2, ch = idx & 3;
            uint32_t off = (uint32_t)((r * 40 + ch * 8) * 2);
            *(uint4*)(sraw + OFF_QH + off) = *(const uint4*)(qh + (size_t)r * 256 + ch * 8);
            *(uint4*)(sraw + OFF_QL + off) = *(const uint4*)(ql + (size_t)r * 256 + ch * 8);
        }
    }
    {
        int r = t >> 2, ch = t & 3;
        uint32_t off = (uint32_t)((r * 40 + ch * 8) * 2);
        uint4 z = make_uint4(0, 0, 0, 0);
        uint4 vh = z, vl = z;
        if (r < AG) {
            vh = *(const uint4*)(g_ahh + ((size_t)b * AG + r) * 256 + h * 32 + ch * 8);
            vl = *(const uint4*)(g_ahl + ((size_t)b * AG + r) * 256 + h * 32 + ch * 8);
        }
        *(uint4*)(sraw + OFF_AHH + off) = vh;
        *(uint4*)(sraw + OFF_AHL + off) = vl;
    }
#pragma unroll
    for (int it = 0; it < 8; it++) {
        int idx = t + it * 256;
        int a = idx >> 5, d = idx & 31;
        __nv_bfloat16 zh = __float2bfloat16(0.f);
        __nv_bfloat16 vh = zh, vl = zh;
        if (a < AG) {
            vh = g_avh[((size_t)bh * AG + a) * HD + d];
            vl = g_avl[((size_t)bh * AG + a) * HD + d];
        }
        ((__nv_bfloat16*)(sraw + OFF_AVH))[d * 72 + a] = vh;
        ((__nv_bfloat16*)(sraw + OFF_AVL))[d * 72 + a] = vl;
    }
#pragma unroll
    for (int it = 0; it < 32; it++) {
        int idx = t + it * 256;
        int rr = idx >> 11;
        int rem = idx & 2047;
        int xx = rem >> 5, c = rem & 31;
        int yy = y0 - 1 + rr;
        float vv = 0.f;
        if (yy >= 0 && yy <= 63)
            vv = g_v[((size_t)b * 4096 + yy * 64 + xx) * 256 + h * 32 + c];
        vh_s[(rr * 64 + xx) * 33 + c] = vv;
    }
    for (int i = t; i < 288; i += 256) wd_s[i] = Wd[h * 288 + i];
    if (t < 32) bd_s[t] = bdv[h * 32 + t];
    __syncthreads();

    const int q8 = lane >> 3, r8 = lane & 7;
    const uint32_t aoffQ = (uint32_t)(((w * 16 + (q8 & 1) * 8 + r8) * 40 + (q8 >> 1) * 8) * 2);
    uint32_t boffA[4];
#pragma unroll
    for (int p = 0; p < 4; p++)
        boffA[p] = (uint32_t)(((p * 16 + (q8 >> 1) * 8 + r8) * 40 + (q8 & 1) * 8) * 2);
    uint32_t boffV[2];
#pragma unroll
    for (int g = 0; g < 2; g++)
        boffV[g] = (uint32_t)(((g * 16 + (q8 >> 1) * 8 + r8) * 72 + (q8 & 1) * 8) * 2);

    float c[8][4];
#pragma unroll
    for (int j = 0; j < 8; j++)
#pragma unroll
        for (int e = 0; e < 4; e++) c[j][e] = 0.f;
#pragma unroll
    for (int kk = 0; kk < 2; kk++) {
        uint32_t ko = (uint32_t)(kk * 32);
        uint32_t Ah[4], Al[4];
        ldm_x4(Ah, uS + OFF_QH + aoffQ + ko);
        ldm_x4(Al, uS + OFF_QL + aoffQ + ko);
#pragma unroll
        for (int p = 0; p < 4; p++) {
            uint32_t Bh[4], Bl[4];
            ldm_x4(Bh, uS + OFF_AHH + boffA[p] + ko);
            ldm_x4(Bl, uS + OFF_AHL + boffA[p] + ko);
#pragma unroll
            for (int hf = 0; hf < 2; hf++) {
                float* d = c[p * 2 + hf];
                mma_bf16(d, Ah, Bh[hf * 2], Bh[hf * 2 + 1]);
                mma_bf16(d, Ah, Bl[hf * 2], Bl[hf * 2 + 1]);
                mma_bf16(d, Al, Bh[hf * 2], Bh[hf * 2 + 1]);
            }
        }
    }

    const int r0 = w * 16 + (lane >> 2), r1 = r0 + 8;
    const int aq = (lane & 3) * 2;
    {
        const float* b2r0 = g_bias2 + ((size_t)h * Nn + n0 + r0) * B2P;
        const float* b2r1 = g_bias2 + ((size_t)h * Nn + n0 + r1) * B2P;
#pragma unroll
        for (int j = 0; j < 8; j++) {
            int a0 = j * 8 + aq;
            if (a0 < 48) {
                float2 u0 = *(const float2*)(b2r0 + a0);
                float2 u1 = *(const float2*)(b2r1 + a0);
                c[j][0] += u0.x; c[j][1] += u0.y;
                c[j][2] += u1.x; c[j][3] += u1.y;
            } else if (a0 == 48) {
                c[j][0] += b2r0[48]; c[j][1] = -1e30f;
                c[j][2] += b2r1[48]; c[j][3] = -1e30f;
            } else {
                c[j][0] = c[j][1] = c[j][2] = c[j][3] = -1e30f;
            }
        }
    }

    float m0 = -1e30f, m1 = -1e30f;
#pragma unroll
    for (int j = 0; j < 8; j++) {
        m0 = fmaxf(m0, fmaxf(c[j][0], c[j][1]));
        m1 = fmaxf(m1, fmaxf(c[j][2], c[j][3]));
    }
    m0 = fmaxf(m0, __shfl_xor_sync(0xFFFFFFFFu, m0, 1));
    m0 = fmaxf(m0, __shfl_xor_sync(0xFFFFFFFFu, m0, 2));
    m1 = fmaxf(m1, __shfl_xor_sync(0xFFFFFFFFu, m1, 1));
    m1 = fmaxf(m1, __shfl_xor_sync(0xFFFFFFFFu, m1, 2));
    float l0 = 0.f, l1 = 0.f;
#pragma unroll
    for (int j = 0; j < 8; j++) {
        c[j][0] = __expf(c[j][0] - m0); c[j][1] = __expf(c[j][1] - m0);
        c[j][2] = __expf(c[j][2] - m1); c[j][3] = __expf(c[j][3] - m1);
        l0 += c[j][0] + c[j][1];
        l1 += c[j][2] + c[j][3];
    }
    l0 += __shfl_xor_sync(0xFFFFFFFFu, l0, 1);
    l0 += __shfl_xor_sync(0xFFFFFFFFu, l0, 2);
    l1 += __shfl_xor_sync(0xFFFFFFFFu, l1, 1);
    l1 += __shfl_xor_sync(0xFFFFFFFFu, l1, 2);
    const float rl0 = 1.0f / l0, rl1 = 1.0f / l1;

    float o[4][4];
#pragma unroll
    for (int g = 0; g < 4; g++)
#pragma unroll
        for (int e = 0; e < 4; e++) o[g][e] = 0.f;
#pragma unroll
    for (int kk = 0; kk < 4; kk++) {
        uint32_t ah2[4], al2[4];
        split2(c[2 * kk][0] * rl0, c[2 * kk][1] * rl0, ah2[0], al2[0]);
        split2(c[2 * kk][2] * rl1, c[2 * kk][3] * rl1, ah2[1], al2[1]);
        split2(c[2 * kk + 1][0] * rl0, c[2 * kk + 1][1] * rl0, ah2[2], al2[2]);
        split2(c[2 * kk + 1][2] * rl1, c[2 * kk + 1][3] * rl1, ah2[3], al2[3]);
        uint32_t ko = (uint32_t)(kk * 32);
#pragma unroll
        for (int g = 0; g < 2; g++) {
            uint32_t Bh[4], Bl[4];
            ldm_x4(Bh, uS + OFF_AVH + boffV[g] + ko);
            ldm_x4(Bl, uS + OFF_AVL + boffV[g] + ko);
#pragma unroll
            for (int hf = 0; hf < 2; hf++) {
                float* d = o[g * 2 + hf];
                mma_bf16(d, ah2, Bh[hf * 2], Bh[hf * 2 + 1]);
                mma_bf16(d, ah2, Bl[hf * 2], Bl[hf * 2 + 1]);
                mma_bf16(d, al2, Bh[hf * 2], Bh[hf * 2 + 1]);
            }
        }
    }

    __syncthreads();
    float* stg = (float*)sraw;
#pragma unroll
    for (int g = 0; g < 4; g++) {
        int dcol = g * 8 + aq;
        stg[r0 * 36 + dcol]     = o[g][0];
        stg[r0 * 36 + dcol + 1] = o[g][1];
        stg[r1 * 36 + dcol]     = o[g][2];
        stg[r1 * 36 + dcol + 1] = o[g][3];
    }
    __syncthreads();
#pragma unroll
    for (int it = 0; it < 4; it++) {
        int idx = t + it * 256;
        int m = idx >> 3, d4 = (idx & 7) * 4;
        int n = n0 + m, y = n >> 6, x = n & 63;
        float4 base = *(float4*)&stg[m * 36 + d4];
        float outv[4] = {base.x, base.y, base.z, base.w};
#pragma unroll
        for (int ci = 0; ci < 4; ci++) {
            int cch = d4 + ci;
            float s = bd_s[cch];
#pragma unroll
            for (int dy = -1; dy <= 1; dy++) {
                int yy = y + dy;
                if (yy < 0 || yy > 63) continue;
                int rr = yy - y0 + 1;
#pragma unroll
                for (int dx = -1; dx <= 1; dx++) {
                    int xx = x + dx;
                    if (xx < 0 || xx > 63) continue;
                    s += vh_s[(rr * 64 + xx) * 33 + cch] * wd_s[cch * 9 + (dy + 1) * 3 + (dx + 1)];
                }
            }
            outv[ci] += s;
        }
        uint32_t h0, l0u, h1, l1u;
        split2h(outv[0], outv[1], h0, l0u);
        split2h(outv[2], outv[3], h1, l1u);
        size_t off = ((size_t)b * 4096 + n) * 256 + h * 32 + d4;
        *(uint2*)&g_oh[off] = make_uint2(h0, h1);
        *(uint2*)&g_ol[off] = make_uint2(l0u, l1u);
    }
}

// ---------------- launch ----------------
extern "C" void kernel_launch(void* const* d_in, const int* in_sizes, int n_in,
                              void* d_out, int out_size) {
    const float* x     = (const float*)d_in[0];
    const float* Wq    = (const float*)d_in[1];
    const float* Wkv   = (const float*)d_in[2];
    const float* Wproj = (const float*)d_in[3];
    const float* bproj = (const float*)d_in[4];
    const float* Wdwc  = (const float*)d_in[5];
    const float* bdwc  = (const float*)d_in[6];
    const float* an    = (const float*)d_in[7];
    const float* na    = (const float*)d_in[8];
    const float* ahb   = (const float*)d_in[9];
    const float* awb   = (const float*)d_in[10];
    const float* hab   = (const float*)d_in[11];
    const float* wab   = (const float*)d_in[12];
    float* out = (float*)d_out;

    cudaFuncSetAttribute(k_gemm_mma<0>, cudaFuncAttributeMaxDynamicSharedMemorySize, SMEM_DYN);
    cudaFuncSetAttribute(k_gemm_mma<1>, cudaFuncAttributeMaxDynamicSharedMemorySize, SMEM_DYN);
    cudaFuncSetAttribute(k_st2_tc, cudaFuncAttributeMaxDynamicSharedMemorySize, ST2_DYN);

    k_bias   <<<dim3(Nn / 256, AG, NH), 256>>>(an, na, ahb, awb, hab, wab);
    k_prep_w <<<1024, 256>>>(Wq, Wkv, Wproj);
    k_xsplit <<<dim3(128, 8, Bb), dim3(32, 8)>>>(x);
    k_gemm_mma<0><<<dim3(32, 6, Bb), 256, SMEM_DYN>>>(nullptr, nullptr);
    k_pool   <<<dim3(AG, Bb), 256>>>();
    k_fs1_tc <<<dim3(NSPLIT, NH, Bb), 128>>>();
    k_fs1red <<<Bb * NH, 256>>>();
    k_st2_tc <<<dim3(Nn / 128, NH, Bb), 256, ST2_DYN>>>(Wdwc, bdwc);
    k_gemm_mma<1><<<dim3(32, 2, Bb), 256, SMEM_DYN>>>(bproj, out);
}

// round 17
// speedup vs baseline: 3.2194x; 1.1665x over previous
#include <cuda_runtime.h>
#include <cuda_bf16.h>
#include <cuda_fp16.h>
#include <cstdint>

// ---------------- constants ----------------
namespace {
constexpr int Bb = 16;      // batch
constexpr int Cc = 256;     // channels
constexpr int Nn = 4096;    // H*W
constexpr int NH = 8;       // heads
constexpr int HD = 32;      // head dim
constexpr int AG = 49;      // agent tokens
constexpr int NSPLIT = 8;   // stage-1 n-splits
constexpr int B2P = 52;     // bias2 pitch (floats) for aligned float2 fragment loads
constexpr float SCALE = 0.17677669529663689f;  // 32^-0.5

// GEMM smem: per stage A + B (fp16, 128x32k pitch40 each)
constexpr int KP = 40;                          // k-pitch (80B rows: conflict-free ldmatrix)
constexpr unsigned SA_SZ = 128 * KP * 2;        // 10240 per buffer
constexpr unsigned STAGE_SZ = 2 * SA_SZ;        // 20480
constexpr int SP = 136;                         // epilogue staging pitch (fp32)
constexpr unsigned SMEM_DYN = 128 * SP * 4;     // 69632 >= 2*STAGE_SZ (40960)

// st2 smem offsets (bytes) — dynamic smem
constexpr unsigned OFF_QH  = 0;                 // 128x40 bf16
constexpr unsigned OFF_QL  = 10240;
constexpr unsigned OFF_AHH = 20480;             // 64x40 bf16
constexpr unsigned OFF_AHL = 25600;
constexpr unsigned OFF_AVH = 30720;             // 32x72 bf16 (av^T)
constexpr unsigned OFF_AVL = 35328;
constexpr unsigned OFF_VH  = 39936;             // 4*64 x 33-pitch fp32 v halo = 33792
constexpr unsigned OFF_WD  = 73728;             // 32*9 fp32 = 1152
constexpr unsigned OFF_BD  = 74880;             // 32 fp32 = 128
constexpr unsigned ST2_DYN = 75008;

// fs1_tc smem offsets (bytes) — static smem
constexpr unsigned F_AHH = 0;      // 64x40 bf16
constexpr unsigned F_AHL = 5120;
constexpr unsigned F_KH  = 10240;  // 64x40 bf16
constexpr unsigned F_KL  = 15360;
constexpr unsigned F_VTH = 20480;  // 32x72 bf16 (v^T)
constexpr unsigned F_VTL = 25088;
constexpr unsigned F_SZ  = 29696;
}

// ---------------- scratch (device globals; no allocation allowed) ----------------
__device__ float g_k[Bb * Nn * Cc];
__device__ float g_v[Bb * Nn * Cc];
__device__ float g_bias1[NH * AG * Nn];        // stage-1 bias [h][a][n]
__device__ float g_bias2[NH * Nn * B2P];       // stage-2 bias [h][n][a] pitch 52
__device__ float g_pacc[Bb * NH * NSPLIT * AG * HD];  // stage-1 partial acc
__device__ float g_pm[Bb * NH * NSPLIT * AG];
__device__ float g_pl[Bb * NH * NSPLIT * AG];

// fp16 operands for the two big GEMMs (single fp16 A and B)
__device__ __half g_xf[Bb * Nn * Cc];          // xt row-major [b][n][c]
__device__ __half g_of[Bb * Nn * Cc];          // attention-out + dw (from st2 epilogue)
__device__ __half g_wf[768 * Cc];              // qkv weights combined [q|k|v]
__device__ __half g_pwf[Cc * Cc];              // proj weights

// bf16 hi/lo operands for the attention tensor-core kernels
__device__ __nv_bfloat16 g_qh[Bb * Nn * Cc];   // q hi/lo (from qkv GEMM epilogue)
__device__ __nv_bfloat16 g_ql[Bb * Nn * Cc];
__device__ __nv_bfloat16 g_ahh[Bb * AG * Cc];  // agent*SCALE hi/lo
__device__ __nv_bfloat16 g_ahl[Bb * AG * Cc];
__device__ __nv_bfloat16 g_avh[Bb * NH * AG * HD];  // agent_v hi/lo
__device__ __nv_bfloat16 g_avl[Bb * NH * AG * HD];

// ---------------- PTX helpers (baseline sm_80+ features only) ----------------
__device__ __forceinline__ uint32_t smem_u32(const void* p) {
    uint32_t a;
    asm("{ .reg .u64 t; cvta.to.shared.u64 t, %1; cvt.u32.u64 %0, t; }" : "=r"(a) : "l"(p));
    return a;
}
__device__ __forceinline__ void ldm_x4(uint32_t* r, uint32_t addr) {
    asm volatile("ldmatrix.sync.aligned.m8n8.x4.shared.b16 {%0,%1,%2,%3}, [%4];"
                 : "=r"(r[0]), "=r"(r[1]), "=r"(r[2]), "=r"(r[3]) : "r"(addr));
}
__device__ __forceinline__ void mma_bf16(float* d, const uint32_t* a, uint32_t b0, uint32_t b1) {
    asm volatile(
        "mma.sync.aligned.m16n8k16.row.col.f32.bf16.bf16.f32 "
        "{%0,%1,%2,%3}, {%4,%5,%6,%7}, {%8,%9}, {%0,%1,%2,%3};"
        : "+f"(d[0]), "+f"(d[1]), "+f"(d[2]), "+f"(d[3])
        : "r"(a[0]), "r"(a[1]), "r"(a[2]), "r"(a[3]), "r"(b0), "r"(b1));
}
__device__ __forceinline__ void mma_f16(float* d, const uint32_t* a, uint32_t b0, uint32_t b1) {
    asm volatile(
        "mma.sync.aligned.m16n8k16.row.col.f32.f16.f16.f32 "
        "{%0,%1,%2,%3}, {%4,%5,%6,%7}, {%8,%9}, {%0,%1,%2,%3};"
        : "+f"(d[0]), "+f"(d[1]), "+f"(d[2]), "+f"(d[3])
        : "r"(a[0]), "r"(a[1]), "r"(a[2]), "r"(a[3]), "r"(b0), "r"(b1));
}
__device__ __forceinline__ void cp16(uint32_t dst, const void* src) {
    asm volatile("cp.async.ca.shared.global [%0], [%1], 16;" :: "r"(dst), "l"(src));
}
__device__ __forceinline__ void cp_commit() { asm volatile("cp.async.commit_group;" ::: "memory"); }
template <int N>
__device__ __forceinline__ void cp_wait() { asm volatile("cp.async.wait_group %0;" :: "n"(N) : "memory"); }

// bf16 pair split (attention path)
__device__ __forceinline__ void split2(float x, float y, uint32_t& h, uint32_t& l) {
    __nv_bfloat16 hx = __float2bfloat16(x), hy = __float2bfloat16(y);
    __nv_bfloat162 hv; hv.x = hx; hv.y = hy;
    __nv_bfloat162 lv;
    lv.x = __float2bfloat16(x - __bfloat162float(hx));
    lv.y = __float2bfloat16(y - __bfloat162float(hy));
    h = *reinterpret_cast<uint32_t*>(&hv);
    l = *reinterpret_cast<uint32_t*>(&lv);
}
__device__ __forceinline__ uint32_t pack2h(float x, float y) {
    __half2 hv; hv.x = __float2half(x); hv.y = __float2half(y);
    return *reinterpret_cast<uint32_t*>(&hv);
}

// ---------------- prep: fp16 weights ----------------
__global__ void k_prep_w(const float* __restrict__ Wq, const float* __restrict__ Wkv,
                         const float* __restrict__ Wp) {
    int row = blockIdx.x, t = threadIdx.x;
    if (row < 768) {
        float v = (row < 256) ? Wq[row * 256 + t] : Wkv[(row - 256) * 256 + t];
        g_wf[row * 256 + t] = __float2half(v);
    } else {
        int r = row - 768;
        g_pwf[r * 256 + t] = __float2half(Wp[r * 256 + t]);
    }
}

__global__ void k_xsplit(const float* __restrict__ x) {
    __shared__ float tile[32][33];
    int tx = threadIdx.x, ty = threadIdx.y;  // 32x8
    int n0 = blockIdx.x * 32, c0 = blockIdx.y * 32, b = blockIdx.z;
#pragma unroll
    for (int yy = 0; yy < 32; yy += 8)
        tile[ty + yy][tx] = x[((size_t)b * 256 + c0 + ty + yy) * 4096 + n0 + tx];
    __syncthreads();
#pragma unroll
    for (int yy = 0; yy < 32; yy += 8) {
        int nl = ty + yy;
        g_xf[((size_t)b * 4096 + n0 + nl) * 256 + c0 + tx] = __float2half(tile[tx][nl]);
    }
}

// ---------------- tensor-core GEMM: 128x128 tiles, single fp16 MMA ----------------
// MODE 0: A = g_xf, W = g_wf (6 j-tiles) -> jt<2: q bf16 hi/lo; jt<4: g_k; else g_v
// MODE 1: A = g_of, W = g_pwf (2 j-tiles) -> transposed out + bias
template <int MODE>
__global__ __launch_bounds__(256, 2)
void k_gemm_mma(const float* __restrict__ bias, float* __restrict__ outp) {
    extern __shared__ __align__(16) char dsm[];
    float* stag = (float*)dsm;                 // epilogue staging aliases pipeline smem

    const int t = threadIdx.x;
    const int lane = t & 31, wid = t >> 5;
    const int wm = wid & 3, wn = wid >> 2;     // warp tile: 32(m) x 64(n)
    const int b = blockIdx.z;
    const int n0 = blockIdx.x * 128;
    const int jt = blockIdx.y, j0 = jt * 128;

    const __half* Ag = (MODE == 0 ? g_xf : g_of) + ((size_t)b * 4096 + n0) * 256;
    const __half* Wg = ((MODE == 0) ? g_wf : g_pwf) + (size_t)j0 * 256;

    const uint32_t uS = smem_u32(dsm);

    auto load_stage = [&](int st, int kt) {
        uint32_t base = uS + st * STAGE_SZ;
        int k0 = kt * 32;
#pragma unroll
        for (int it = 0; it < 2; it++) {
            int idx = t + it * 256;
            int r = idx >> 2, ch = idx & 3;
            uint32_t off = (uint32_t)((r * KP + ch * 8) * 2);
            const size_t g = (size_t)r * 256 + k0 + ch * 8;
            cp16(base + off, Ag + g);
            cp16(base + SA_SZ + off, Wg + g);
        }
    };

    const int q8 = lane >> 3, r8 = lane & 7;
    uint32_t aoff[2], boff[4];
#pragma unroll
    for (int mt = 0; mt < 2; mt++) {
        int row = wm * 32 + mt * 16 + (q8 & 1) * 8 + r8;
        aoff[mt] = (uint32_t)((row * KP + (q8 >> 1) * 8) * 2);
    }
#pragma unroll
    for (int p = 0; p < 4; p++) {
        int nrow = wn * 64 + p * 16 + (q8 >> 1) * 8 + r8;
        boff[p] = (uint32_t)((nrow * KP + (q8 & 1) * 8) * 2);
    }

    float acc[2][8][4];
#pragma unroll
    for (int mt = 0; mt < 2; mt++)
#pragma unroll
        for (int nt = 0; nt < 8; nt++)
#pragma unroll
            for (int e = 0; e < 4; e++) acc[mt][nt][e] = 0.f;

    load_stage(0, 0);
    cp_commit();

    for (int kt = 0; kt < 8; kt++) {
        cp_wait<0>();
        __syncthreads();
        if (kt < 7) {
            load_stage((kt + 1) & 1, kt + 1);
            cp_commit();
        }
        const uint32_t base = uS + (kt & 1) * STAGE_SZ;
        const uint32_t uA = base, uB = base + SA_SZ;
#pragma unroll
        for (int kh = 0; kh < 2; kh++) {
            uint32_t ko = (uint32_t)(kh * 32);
            uint32_t A[2][4];
            ldm_x4(A[0], uA + aoff[0] + ko);
            ldm_x4(A[1], uA + aoff[1] + ko);
#pragma unroll
            for (int p = 0; p < 4; p++) {
                uint32_t B[4];
                ldm_x4(B, uB + boff[p] + ko);
#pragma unroll
                for (int mt = 0; mt < 2; mt++) {
#pragma unroll
                    for (int hf = 0; hf < 2; hf++) {
                        mma_f16(acc[mt][p * 2 + hf], A[mt], B[hf * 2], B[hf * 2 + 1]);
                    }
                }
            }
        }
        // next iteration's top sync guards buffer reuse
    }
    __syncthreads();   // all compute done before staging overwrites pipeline smem

    // ---- stage fragments to smem [128][SP] ----
    {
        int r0 = lane >> 2, c0 = (lane & 3) * 2;
#pragma unroll
        for (int mt = 0; mt < 2; mt++) {
#pragma unroll
            for (int nt = 0; nt < 8; nt++) {
                int row = wm * 32 + mt * 16 + r0;
                int col = wn * 64 + nt * 8 + c0;
                stag[row * SP + col]           = acc[mt][nt][0];
                stag[row * SP + col + 1]       = acc[mt][nt][1];
                stag[(row + 8) * SP + col]     = acc[mt][nt][2];
                stag[(row + 8) * SP + col + 1] = acc[mt][nt][3];
            }
        }
    }
    __syncthreads();

    // ---- coalesced stores ----
    if (MODE == 0) {
        int jl = (jt & 1) * 128;
        if (jt < 2) {
#pragma unroll
            for (int it = 0; it < 16; it++) {
                int idx = t + it * 256;
                int m = idx >> 5, j4 = (idx & 31) * 4;
                float4 v = *(float4*)&stag[m * SP + j4];
                uint32_t h0, l0, h1, l1;
                split2(v.x, v.y, h0, l0);
                split2(v.z, v.w, h1, l1);
                size_t off = ((size_t)b * 4096 + n0 + m) * 256 + jl + j4;
                *(uint2*)&g_qh[off] = make_uint2(h0, h1);
                *(uint2*)&g_ql[off] = make_uint2(l0, l1);
            }
        } else {
            float* dst = (jt < 4) ? g_k : g_v;
#pragma unroll
            for (int it = 0; it < 16; it++) {
                int idx = t + it * 256;
                int m = idx >> 5, j4 = (idx & 31) * 4;
                *(float4*)&dst[((size_t)b * 4096 + n0 + m) * 256 + jl + j4] =
                    *(float4*)&stag[m * SP + j4];
            }
        }
    } else {
        int m = t & 127, js = t >> 7;
#pragma unroll 8
        for (int j = js; j < 128; j += 2) {
            float v = stag[m * SP + j] + bias[j0 + j];
            outp[((size_t)b * 256 + j0 + j) * 4096 + n0 + m] = v;
        }
    }
}

// ---------------- bilinear coeffs for 7 -> 64 resize ----------------
__device__ __forceinline__ void lin7(int i, int& j0, int& j1, float& w) {
    float c = (i + 0.5f) * (7.0f / 64.0f) - 0.5f;
    float f = floorf(c);
    w = c - f;
    int j = (int)f;
    j0 = max(0, min(6, j));
    j1 = max(0, min(6, j + 1));
}

__device__ __forceinline__ float bil7(const float* img, int y0, int y1, float wy,
                                      int x0, int x1, float wx) {
    float v0 = img[y0 * 7 + x0] * (1.f - wx) + img[y0 * 7 + x1] * wx;
    float v1 = img[y1 * 7 + x0] * (1.f - wx) + img[y1 * 7 + x1] * wx;
    return v0 * (1.f - wy) + v1 * wy;
}

// ---------------- K1: position biases ----------------
__global__ void k_bias(const float* __restrict__ an, const float* __restrict__ na,
                       const float* __restrict__ ahb, const float* __restrict__ awb,
                       const float* __restrict__ hab, const float* __restrict__ wab) {
    int n = blockIdx.x * 256 + threadIdx.x;
    int a = blockIdx.y, h = blockIdx.z;
    int y = n >> 6, x = n & 63;
    int y0, y1, x0, x1; float wy, wx;
    lin7(y, y0, y1, wy);
    lin7(x, x0, x1, wx);
    const float* i1 = an + (h * AG + a) * 49;
    const float* i2 = na + (h * AG + a) * 49;
    float v1 = bil7(i1, y0, y1, wy, x0, x1, wx);
    float v2 = bil7(i2, y0, y1, wy, x0, x1, wx);
    g_bias1[(h * AG + a) * Nn + n] = v1 + ahb[(h * AG + a) * 64 + y] + awb[(h * AG + a) * 64 + x];
    g_bias2[((size_t)h * Nn + n) * B2P + a] = v2 + hab[(h * 64 + y) * AG + a] + wab[(h * 64 + x) * AG + a];
}

// ---------------- K3: adaptive avg pool q -> agent (scaled bf16 hi/lo split) ----------------
__global__ void k_pool() {
    int c = threadIdx.x;
    int a = blockIdx.x;
    int b = blockIdx.y;
    int p = a / 7, q = a % 7;
    int ys = (p * 64) / 7, ye = ((p + 1) * 64 + 6) / 7;
    int xs = (q * 64) / 7, xe = ((q + 1) * 64 + 6) / 7;
    float s = 0.f;
    for (int y = ys; y < ye; y++)
        for (int x = xs; x < xe; x++) {
            size_t idx = ((size_t)b * Nn + y * 64 + x) * Cc + c;
            s += __bfloat162float(g_qh[idx]) + __bfloat162float(g_ql[idx]);
        }
    float sc = s * (1.0f / ((ye - ys) * (xe - xs))) * SCALE;
    __nv_bfloat16 hi = __float2bfloat16(sc);
    g_ahh[(b * AG + a) * Cc + c] = hi;
    g_ahl[(b * AG + a) * Cc + c] = __float2bfloat16(sc - __bfloat162float(hi));
}

// ---------------- K4: stage-1 on tensor cores (flash, n-split partials) ----------------
__global__ __launch_bounds__(128, 4) void k_fs1_tc() {
    __shared__ __align__(16) char sm[F_SZ];
    const uint32_t uS = smem_u32(sm);
    const int t = threadIdx.x;
    const int lane = t & 31, w = t >> 5;
    const int sp = blockIdx.x, h = blockIdx.y, b = blockIdx.z;
    const int bh = b * NH + h;

#pragma unroll
    for (int i = 0; i < 2; i++) {
        int idx = t + i * 128;
        int r = idx >> 2, ch = idx & 3;
        uint32_t off = (uint32_t)((r * 40 + ch * 8) * 2);
        uint4 z = make_uint4(0, 0, 0, 0);
        uint4 vh = z, vl = z;
        if (r < AG) {
            vh = *(const uint4*)(g_ahh + ((size_t)b * AG + r) * 256 + h * 32 + ch * 8);
            vl = *(const uint4*)(g_ahl + ((size_t)b * AG + r) * 256 + h * 32 + ch * 8);
        }
        *(uint4*)(sm + F_AHH + off) = vh;
        *(uint4*)(sm + F_AHL + off) = vl;
    }

    const int q8 = lane >> 3, r8 = lane & 7;
    const uint32_t aoffA = (uint32_t)(((w * 16 + (q8 & 1) * 8 + r8) * 40 + (q8 >> 1) * 8) * 2);
    uint32_t boffK[4];
#pragma unroll
    for (int p = 0; p < 4; p++)
        boffK[p] = (uint32_t)(((p * 16 + (q8 >> 1) * 8 + r8) * 40 + (q8 & 1) * 8) * 2);
    uint32_t boffV[2];
#pragma unroll
    for (int g = 0; g < 2; g++)
        boffV[g] = (uint32_t)(((g * 16 + (q8 >> 1) * 8 + r8) * 72 + (q8 & 1) * 8) * 2);

    const int r0 = w * 16 + (lane >> 2), r1 = r0 + 8;
    const int aq = (lane & 3) * 2;

    float o[4][4];
#pragma unroll
    for (int g = 0; g < 4; g++)
#pragma unroll
        for (int e = 0; e < 4; e++) o[g][e] = 0.f;
    float m0r = -1e30f, m1r = -1e30f, l0r = 0.f, l1r = 0.f;

    const float* kb = g_k + (size_t)b * Nn * Cc + h * HD;
    const float* vb = g_v + (size_t)b * Nn * Cc + h * HD;
    const float* bias = g_bias1 + (size_t)h * AG * Nn;

    for (int tile = 0; tile < 8; tile++) {
        int n0 = sp * 512 + tile * 64;
        __syncthreads();
        __nv_bfloat16* vth = (__nv_bfloat16*)(sm + F_VTH);
        __nv_bfloat16* vtl = (__nv_bfloat16*)(sm + F_VTL);
#pragma unroll
        for (int i = 0; i < 4; i++) {
            int idx = t + i * 128;
            int r = idx >> 3, c4 = (idx & 7) * 4;
            float4 kk = *(const float4*)(kb + (size_t)(n0 + r) * Cc + c4);
            uint32_t kh0, kl0, kh1, kl1;
            split2(kk.x, kk.y, kh0, kl0);
            split2(kk.z, kk.w, kh1, kl1);
            *(uint2*)(sm + F_KH + (r * 40 + c4) * 2) = make_uint2(kh0, kh1);
            *(uint2*)(sm + F_KL + (r * 40 + c4) * 2) = make_uint2(kl0, kl1);
            float4 vv = *(const float4*)(vb + (size_t)(n0 + r) * Cc + c4);
            float vals[4] = {vv.x, vv.y, vv.z, vv.w};
#pragma unroll
            for (int j = 0; j < 4; j++) {
                __nv_bfloat16 hi = __float2bfloat16(vals[j]);
                vth[(c4 + j) * 72 + r] = hi;
                vtl[(c4 + j) * 72 + r] = __float2bfloat16(vals[j] - __bfloat162float(hi));
            }
        }
        __syncthreads();

        float c[8][4];
#pragma unroll
        for (int j = 0; j < 8; j++)
#pragma unroll
            for (int e = 0; e < 4; e++) c[j][e] = 0.f;
#pragma unroll
        for (int kk = 0; kk < 2; kk++) {
            uint32_t ko = (uint32_t)(kk * 32);
            uint32_t Ah[4], Al[4];
            ldm_x4(Ah, uS + F_AHH + aoffA + ko);
            ldm_x4(Al, uS + F_AHL + aoffA + ko);
#pragma unroll
            for (int p = 0; p < 4; p++) {
                uint32_t Bh[4], Bl[4];
                ldm_x4(Bh, uS + F_KH + boffK[p] + ko);
                ldm_x4(Bl, uS + F_KL + boffK[p] + ko);
#pragma unroll
                for (int hf = 0; hf < 2; hf++) {
                    float* d = c[p * 2 + hf];
                    mma_bf16(d, Ah, Bh[hf * 2], Bh[hf * 2 + 1]);
                    mma_bf16(d, Ah, Bl[hf * 2], Bl[hf * 2 + 1]);
                    mma_bf16(d, Al, Bh[hf * 2], Bh[hf * 2 + 1]);
                }
            }
        }

        if (r0 < AG) {
            const float* br = bias + (size_t)r0 * Nn + n0;
#pragma unroll
            for (int j = 0; j < 8; j++) {
                float2 u = *(const float2*)(br + j * 8 + aq);
                c[j][0] += u.x; c[j][1] += u.y;
            }
        }
        if (r1 < AG) {
            const float* br = bias + (size_t)r1 * Nn + n0;
#pragma unroll
            for (int j = 0; j < 8; j++) {
                float2 u = *(const float2*)(br + j * 8 + aq);
                c[j][2] += u.x; c[j][3] += u.y;
            }
        }

        float tm0 = -1e30f, tm1 = -1e30f;
#pragma unroll
        for (int j = 0; j < 8; j++) {
            tm0 = fmaxf(tm0, fmaxf(c[j][0], c[j][1]));
            tm1 = fmaxf(tm1, fmaxf(c[j][2], c[j][3]));
        }
        tm0 = fmaxf(tm0, __shfl_xor_sync(0xFFFFFFFFu, tm0, 1));
        tm0 = fmaxf(tm0, __shfl_xor_sync(0xFFFFFFFFu, tm0, 2));
        tm1 = fmaxf(tm1, __shfl_xor_sync(0xFFFFFFFFu, tm1, 1));
        tm1 = fmaxf(tm1, __shfl_xor_sync(0xFFFFFFFFu, tm1, 2));
        float mn0 = fmaxf(m0r, tm0), mn1 = fmaxf(m1r, tm1);
        float f0 = __expf(m0r - mn0), f1 = __expf(m1r - mn1);
        float ts0 = 0.f, ts1 = 0.f;
#pragma unroll
        for (int j = 0; j < 8; j++) {
            c[j][0] = __expf(c[j][0] - mn0); c[j][1] = __expf(c[j][1] - mn0);
            c[j][2] = __expf(c[j][2] - mn1); c[j][3] = __expf(c[j][3] - mn1);
            ts0 += c[j][0] + c[j][1];
            ts1 += c[j][2] + c[j][3];
        }
        ts0 += __shfl_xor_sync(0xFFFFFFFFu, ts0, 1);
        ts0 += __shfl_xor_sync(0xFFFFFFFFu, ts0, 2);
        ts1 += __shfl_xor_sync(0xFFFFFFFFu, ts1, 1);
        ts1 += __shfl_xor_sync(0xFFFFFFFFu, ts1, 2);
        l0r = l0r * f0 + ts0;
        l1r = l1r * f1 + ts1;
        m0r = mn0; m1r = mn1;
#pragma unroll
        for (int g = 0; g < 4; g++) {
            o[g][0] *= f0; o[g][1] *= f0;
            o[g][2] *= f1; o[g][3] *= f1;
        }

#pragma unroll
        for (int kk = 0; kk < 4; kk++) {
            uint32_t ah2[4], al2[4];
            split2(c[2 * kk][0], c[2 * kk][1], ah2[0], al2[0]);
            split2(c[2 * kk][2], c[2 * kk][3], ah2[1], al2[1]);
            split2(c[2 * kk + 1][0], c[2 * kk + 1][1], ah2[2], al2[2]);
            split2(c[2 * kk + 1][2], c[2 * kk + 1][3], ah2[3], al2[3]);
            uint32_t ko = (uint32_t)(kk * 32);
#pragma unroll
            for (int g = 0; g < 2; g++) {
                uint32_t Bh[4], Bl[4];
                ldm_x4(Bh, uS + F_VTH + boffV[g] + ko);
                ldm_x4(Bl, uS + F_VTL + boffV[g] + ko);
#pragma unroll
                for (int hf = 0; hf < 2; hf++) {
                    float* d = o[g * 2 + hf];
                    mma_bf16(d, ah2, Bh[hf * 2], Bh[hf * 2 + 1]);
                    mma_bf16(d, ah2, Bl[hf * 2], Bl[hf * 2 + 1]);
                    mma_bf16(d, al2, Bh[hf * 2], Bh[hf * 2 + 1]);
                }
            }
        }
    }

    float* pacc = g_pacc + ((size_t)bh * NSPLIT + sp) * AG * HD;
    if (r0 < AG) {
#pragma unroll
        for (int g = 0; g < 4; g++) {
            pacc[r0 * HD + g * 8 + aq]     = o[g][0];
            pacc[r0 * HD + g * 8 + aq + 1] = o[g][1];
        }
    }
    if (r1 < AG) {
#pragma unroll
        for (int g = 0; g < 4; g++) {
            pacc[r1 * HD + g * 8 + aq]     = o[g][2];
            pacc[r1 * HD + g * 8 + aq + 1] = o[g][3];
        }
    }
    if ((lane & 3) == 0) {
        if (r0 < AG) {
            g_pm[(bh * NSPLIT + sp) * AG + r0] = m0r;
            g_pl[(bh * NSPLIT + sp) * AG + r0] = l0r;
        }
        if (r1 < AG) {
            g_pm[(bh * NSPLIT + sp) * AG + r1] = m1r;
            g_pl[(bh * NSPLIT + sp) * AG + r1] = l1r;
        }
    }
}

// ---------------- K4b: combine stage-1 partials -> agent_v bf16 hi/lo ----------------
__global__ void k_fs1red() {
    int bh = blockIdx.x;
    int t = threadIdx.x;
    for (int idx = t; idx < AG * HD; idx += 256) {
        int a = idx >> 5, d = idx & 31;
        float mmax = -1e30f;
#pragma unroll
        for (int s = 0; s < NSPLIT; s++)
            mmax = fmaxf(mmax, g_pm[(bh * NSPLIT + s) * AG + a]);
        float num = 0.f, den = 0.f;
#pragma unroll
        for (int s = 0; s < NSPLIT; s++) {
            float w = __expf(g_pm[(bh * NSPLIT + s) * AG + a] - mmax);
            num += w * g_pacc[(((size_t)bh * NSPLIT + s) * AG + a) * HD + d];
            den += w * g_pl[(bh * NSPLIT + s) * AG + a];
        }
        float val = num / den;
        __nv_bfloat16 hi = __float2bfloat16(val);
        g_avh[((size_t)bh * AG + a) * HD + d] = hi;
        g_avl[((size_t)bh * AG + a) * HD + d] = __float2bfloat16(val - __bfloat162float(hi));
    }
}

// ---------------- K7: stage-2 on tensor cores + fused depthwise conv epilogue ----------------
__global__ __launch_bounds__(256, 2) void k_st2_tc(const float* __restrict__ Wd,
                                                   const float* __restrict__ bdv) {
    extern __shared__ __align__(16) char sraw[];
    const int t = threadIdx.x;
    const int lane = t & 31, w = t >> 5;
    const int n0 = blockIdx.x * 128, h = blockIdx.y, b = blockIdx.z;
    const int bh = b * NH + h;
    const int y0 = n0 >> 6;
    const uint32_t uS = smem_u32(sraw);
    float* vh_s = (float*)(sraw + OFF_VH);
    float* wd_s = (float*)(sraw + OFF_WD);
    float* bd_s = (float*)(sraw + OFF_BD);

    {
        const __nv_bfloat16* qh = g_qh + ((size_t)b * 4096 + n0) * 256 + h * 32;
        const __nv_bfloat16* ql = g_ql + ((size_t)b * 4096 + n0) * 256 + h * 32;
#pragma unroll
        for (int it = 0; it < 2; it++) {
            int idx = t + it * 256;
            int r = idx >> 2, ch = idx & 3;
            uint32_t off = (uint32_t)((r * 40 + ch * 8) * 2);
            *(uint4*)(sraw + OFF_QH + off) = *(const uint4*)(qh + (size_t)r * 256 + ch * 8);
            *(uint4*)(sraw + OFF_QL + off) = *(const uint4*)(ql + (size_t)r * 256 + ch * 8);
        }
    }
    {
        int r = t >> 2, ch = t & 3;
        uint32_t off = (uint32_t)((r * 40 + ch * 8) * 2);
        uint4 z = make_uint4(0, 0, 0, 0);
        uint4 vh = z, vl = z;
        if (r < AG) {
            vh = *(const uint4*)(g_ahh + ((size_t)b * AG + r) * 256 + h * 32 + ch * 8);
            vl = *(const uint4*)(g_ahl + ((size_t)b * AG + r) * 256 + h * 32 + ch * 8);
        }
        *(uint4*)(sraw + OFF_AHH + off) = vh;
        *(uint4*)(sraw + OFF_AHL + off) = vl;
    }
#pragma unroll
    for (int it = 0; it < 8; it++) {
        int idx = t + it * 256;
        int a = idx >> 5, d = idx & 31;
        __nv_bfloat16 zh = __float2bfloat16(0.f);
        __nv_bfloat16 vh = zh, vl = zh;
        if (a < AG) {
            vh = g_avh[((size_t)bh * AG + a) * HD + d];
            vl = g_avl[((size_t)bh * AG + a) * HD + d];
        }
        ((__nv_bfloat16*)(sraw + OFF_AVH))[d * 72 + a] = vh;
        ((__nv_bfloat16*)(sraw + OFF_AVL))[d * 72 + a] = vl;
    }
#pragma unroll
    for (int it = 0; it < 32; it++) {
        int idx = t + it * 256;
        int rr = idx >> 11;
        int rem = idx & 2047;
        int xx = rem >> 5, c = rem & 31;
        int yy = y0 - 1 + rr;
        float vv = 0.f;
        if (yy >= 0 && yy <= 63)
            vv = g_v[((size_t)b * 4096 + yy * 64 + xx) * 256 + h * 32 + c];
        vh_s[(rr * 64 + xx) * 33 + c] = vv;
    }
    for (int i = t; i < 288; i += 256) wd_s[i] = Wd[h * 288 + i];
    if (t < 32) bd_s[t] = bdv[h * 32 + t];
    __syncthreads();

    const int q8 = lane >> 3, r8 = lane & 7;
    const uint32_t aoffQ = (uint32_t)(((w * 16 + (q8 & 1) * 8 + r8) * 40 + (q8 >> 1) * 8) * 2);
    uint32_t boffA[4];
#pragma unroll
    for (int p = 0; p < 4; p++)
        boffA[p] = (uint32_t)(((p * 16 + (q8 >> 1) * 8 + r8) * 40 + (q8 & 1) * 8) * 2);
    uint32_t boffV[2];
#pragma unroll
    for (int g = 0; g < 2; g++)
        boffV[g] = (uint32_t)(((g * 16 + (q8 >> 1) * 8 + r8) * 72 + (q8 & 1) * 8) * 2);

    float c[8][4];
#pragma unroll
    for (int j = 0; j < 8; j++)
#pragma unroll
        for (int e = 0; e < 4; e++) c[j][e] = 0.f;
#pragma unroll
    for (int kk = 0; kk < 2; kk++) {
        uint32_t ko = (uint32_t)(kk * 32);
        uint32_t Ah[4], Al[4];
        ldm_x4(Ah, uS + OFF_QH + aoffQ + ko);
        ldm_x4(Al, uS + OFF_QL + aoffQ + ko);
#pragma unroll
        for (int p = 0; p < 4; p++) {
            uint32_t Bh[4], Bl[4];
            ldm_x4(Bh, uS + OFF_AHH + boffA[p] + ko);
            ldm_x4(Bl, uS + OFF_AHL + boffA[p] + ko);
#pragma unroll
            for (int hf = 0; hf < 2; hf++) {
                float* d = c[p * 2 + hf];
                mma_bf16(d, Ah, Bh[hf * 2], Bh[hf * 2 + 1]);
                mma_bf16(d, Ah, Bl[hf * 2], Bl[hf * 2 + 1]);
                mma_bf16(d, Al, Bh[hf * 2], Bh[hf * 2 + 1]);
            }
        }
    }

    const int r0 = w * 16 + (lane >> 2), r1 = r0 + 8;
    const int aq = (lane & 3) * 2;
    {
        const float* b2r0 = g_bias2 + ((size_t)h * Nn + n0 + r0) * B2P;
        const float* b2r1 = g_bias2 + ((size_t)h * Nn + n0 + r1) * B2P;
#pragma unroll
        for (int j = 0; j < 8; j++) {
            int a0 = j * 8 + aq;
            if (a0 < 48) {
                float2 u0 = *(const float2*)(b2r0 + a0);
                float2 u1 = *(const float2*)(b2r1 + a0);
                c[j][0] += u0.x; c[j][1] += u0.y;
                c[j][2] += u1.x; c[j][3] += u1.y;
            } else if (a0 == 48) {
                c[j][0] += b2r0[48]; c[j][1] = -1e30f;
                c[j][2] += b2r1[48]; c[j][3] = -1e30f;
            } else {
                c[j][0] = c[j][1] = c[j][2] = c[j][3] = -1e30f;
            }
        }
    }

    float m0 = -1e30f, m1 = -1e30f;
#pragma unroll
    for (int j = 0; j < 8; j++) {
        m0 = fmaxf(m0, fmaxf(c[j][0], c[j][1]));
        m1 = fmaxf(m1, fmaxf(c[j][2], c[j][3]));
    }
    m0 = fmaxf(m0, __shfl_xor_sync(0xFFFFFFFFu, m0, 1));
    m0 = fmaxf(m0, __shfl_xor_sync(0xFFFFFFFFu, m0, 2));
    m1 = fmaxf(m1, __shfl_xor_sync(0xFFFFFFFFu, m1, 1));
    m1 = fmaxf(m1, __shfl_xor_sync(0xFFFFFFFFu, m1, 2));
    float l0 = 0.f, l1 = 0.f;
#pragma unroll
    for (int j = 0; j < 8; j++) {
        c[j][0] = __expf(c[j][0] - m0); c[j][1] = __expf(c[j][1] - m0);
        c[j][2] = __expf(c[j][2] - m1); c[j][3] = __expf(c[j][3] - m1);
        l0 += c[j][0] + c[j][1];
        l1 += c[j][2] + c[j][3];
    }
    l0 += __shfl_xor_sync(0xFFFFFFFFu, l0, 1);
    l0 += __shfl_xor_sync(0xFFFFFFFFu, l0, 2);
    l1 += __shfl_xor_sync(0xFFFFFFFFu, l1, 1);
    l1 += __shfl_xor_sync(0xFFFFFFFFu, l1, 2);
    const float rl0 = 1.0f / l0, rl1 = 1.0f / l1;

    float o[4][4];
#pragma unroll
    for (int g = 0; g < 4; g++)
#pragma unroll
        for (int e = 0; e < 4; e++) o[g][e] = 0.f;
#pragma unroll
    for (int kk = 0; kk < 4; kk++) {
        uint32_t ah2[4], al2[4];
        split2(c[2 * kk][0] * rl0, c[2 * kk][1] * rl0, ah2[0], al2[0]);
        split2(c[2 * kk][2] * rl1, c[2 * kk][3] * rl1, ah2[1], al2[1]);
        split2(c[2 * kk + 1][0] * rl0, c[2 * kk + 1][1] * rl0, ah2[2], al2[2]);
        split2(c[2 * kk + 1][2] * rl1, c[2 * kk + 1][3] * rl1, ah2[3], al2[3]);
        uint32_t ko = (uint32_t)(kk * 32);
#pragma unroll
        for (int g = 0; g < 2; g++) {
            uint32_t Bh[4], Bl[4];
            ldm_x4(Bh, uS + OFF_AVH + boffV[g] + ko);
            ldm_x4(Bl, uS + OFF_AVL + boffV[g] + ko);
#pragma unroll
            for (int hf = 0; hf < 2; hf++) {
                float* d = o[g * 2 + hf];
                mma_bf16(d, ah2, Bh[hf * 2], Bh[hf * 2 + 1]);
                mma_bf16(d, ah2, Bl[hf * 2], Bl[hf * 2 + 1]);
                mma_bf16(d, al2, Bh[hf * 2], Bh[hf * 2 + 1]);
            }
        }
    }

    __syncthreads();
    float* stg = (float*)sraw;
#pragma unroll
    for (int g = 0; g < 4; g++) {
        int dcol = g * 8 + aq;
        stg[r0 * 36 + dcol]     = o[g][0];
        stg[r0 * 36 + dcol + 1] = o[g][1];
        stg[r1 * 36 + dcol]     = o[g][2];
        stg[r1 * 36 + dcol + 1] = o[g][3];
    }
    __syncthreads();
#pragma unroll
    for (int it = 0; it < 4; it++) {
        int idx = t + it * 256;
        int m = idx >> 3, d4 = (idx & 7) * 4;
        int n = n0 + m, y = n >> 6, x = n & 63;
        float4 base = *(float4*)&stg[m * 36 + d4];
        float outv[4] = {base.x, base.y, base.z, base.w};
#pragma unroll
        for (int ci = 0; ci < 4; ci++) {
            int cch = d4 + ci;
            float s = bd_s[cch];
#pragma unroll
            for (int dy = -1; dy <= 1; dy++) {
                int yy = y + dy;
                if (yy < 0 || yy > 63) continue;
                int rr = yy - y0 + 1;
#pragma unroll
                for (int dx = -1; dx <= 1; dx++) {
                    int xx = x + dx;
                    if (xx < 0 || xx > 63) continue;
                    s += vh_s[(rr * 64 + xx) * 33 + cch] * wd_s[cch * 9 + (dy + 1) * 3 + (dx + 1)];
                }
            }
            outv[ci] += s;
        }
        size_t off = ((size_t)b * 4096 + n) * 256 + h * 32 + d4;
        *(uint2*)&g_of[off] = make_uint2(pack2h(outv[0], outv[1]), pack2h(outv[2], outv[3]));
    }
}

// ---------------- launch ----------------
extern "C" void kernel_launch(void* const* d_in, const int* in_sizes, int n_in,
                              void* d_out, int out_size) {
    const float* x     = (const float*)d_in[0];
    const float* Wq    = (const float*)d_in[1];
    const float* Wkv   = (const float*)d_in[2];
    const float* Wproj = (const float*)d_in[3];
    const float* bproj = (const float*)d_in[4];
    const float* Wdwc  = (const float*)d_in[5];
    const float* bdwc  = (const float*)d_in[6];
    const float* an    = (const float*)d_in[7];
    const float* na    = (const float*)d_in[8];
    const float* ahb   = (const float*)d_in[9];
    const float* awb   = (const float*)d_in[10];
    const float* hab   = (const float*)d_in[11];
    const float* wab   = (const float*)d_in[12];
    float* out = (float*)d_out;

    cudaFuncSetAttribute(k_gemm_mma<0>, cudaFuncAttributeMaxDynamicSharedMemorySize, SMEM_DYN);
    cudaFuncSetAttribute(k_gemm_mma<1>, cudaFuncAttributeMaxDynamicSharedMemorySize, SMEM_DYN);
    cudaFuncSetAttribute(k_st2_tc, cudaFuncAttributeMaxDynamicSharedMemorySize, ST2_DYN);

    k_bias   <<<dim3(Nn / 256, AG, NH), 256>>>(an, na, ahb, awb, hab, wab);
    k_prep_w <<<1024, 256>>>(Wq, Wkv, Wproj);
    k_xsplit <<<dim3(128, 8, Bb), dim3(32, 8)>>>(x);
    k_gemm_mma<0><<<dim3(32, 6, Bb), 256, SMEM_DYN>>>(nullptr, nullptr);
    k_pool   <<<dim3(AG, Bb), 256>>>();
    k_fs1_tc <<<dim3(NSPLIT, NH, Bb), 128>>>();
    k_fs1red <<<Bb * NH, 256>>>();
    k_st2_tc <<<dim3(Nn / 128, NH, Bb), 256, ST2_DYN>>>(Wdwc, bdwc);
    k_gemm_mma<1><<<dim3(32, 2, Bb), 256, SMEM_DYN>>>(bproj, out);
}